// round 9
// baseline (speedup 1.0000x reference)
#include <cuda_runtime.h>
#include <cuda_fp16.h>
#include <math.h>
#include <stdint.h>

// Problem constants
#define BATCH   64
#define PIX     196
#define ENC     2048
#define DEC     512
#define ATT     512
#define EMBD    512
#define VOC     10000
#define MAXLEN  52
#define TSTEPS  51
#define HCAT2   2560     // 512 dec_att | 2048 fbeta
#define XDIM2   3072     // emb 512 | awe 2048 | h 512
#define GDIM    2048     // 4*DEC

// Output layout (flattened tuple, float32)
#define PRED_OFF   0
#define CAP_OFF    32640000
#define LEN_OFF    32643328
#define ALPHA_OFF  32643392

#define HSPLIT 4         // hproj split-K
#define GSPLITB 8        // gates part-B split-K
#define ISPLIT 8         // h0c0 split-K

#define MTOT  (TSTEPS * BATCH)   // 3264
#define NPAD  10112              // 79*128 >= VOC
#define NBLK  148                // persistent grid

// ---------------- scratch ----------------
__device__ __align__(16) __half g_WhcatT[HCAT2 * DEC];    // [n][k]
__device__ __align__(16) __half g_WihT[GDIM * XDIM2];     // [n][k] (W_ih|W_hh)
__device__ __align__(16) __half g_WencT[ATT * ENC];       // [n][k]
__device__ __align__(16) __half g_WfcT[NPAD * DEC];       // [n][k]
__device__ __align__(16) __half g_WinitT[1024 * ENC];     // [n][k] (h0|c0)
__device__ __align__(16) __half g_enc_h[(BATCH * PIX + 8) * ENC]; // padded
__device__ __align__(16) __half g_mean16[BATCH * ENC];
__device__ __align__(16) __half g_h16cur[BATCH * DEC];
__device__ __align__(16) __half g_h16[MTOT * DEC];
__device__ __align__(16) __half g_x16[BATCH * XDIM2];
__device__ float  g_mask[TSTEPS * BATCH];
__device__ float  g_c[BATCH * DEC];
__device__ float  g_att_enc[BATCH * PIX * ATT];
__device__ float  g_hpart[HSPLIT * BATCH * HCAT2];
__device__ float  g_gpartA[2 * BATCH * GDIM];
__device__ float  g_gpartB[GSPLITB * BATCH * GDIM];
__device__ float  g_ipart[ISPLIT * BATCH * 1024];
__device__ float  g_e[BATCH * PIX];

// grid barrier state
__device__ unsigned g_barcnt = 0;
__device__ unsigned g_bargen = 0;

__device__ __forceinline__ float sigmoidf_(float x) { return 1.f / (1.f + __expf(-x)); }

// FMA-pipe-only tanh (NO MUFU): Eigen/XLA Pade(13,6) + bit-trick reciprocal
// + 2 Newton steps. Max err ~1e-4 rel; clamped |x|<=7.99.
__device__ __forceinline__ float tanh_fma(float x) {
    float cx = fminf(fmaxf(x, -7.99f), 7.99f);
    float y = cx * cx;
    float np = fmaf(y, -2.76076847742355e-16f, 2.00018790482477e-13f);
    np = fmaf(y, np, -8.60467152213735e-11f);
    np = fmaf(y, np, 5.12229709037114e-08f);
    np = fmaf(y, np, 1.48572235717979e-05f);
    np = fmaf(y, np, 6.37261928875436e-04f);
    np = fmaf(y, np, 4.89352455891786e-03f);
    np = np * cx;
    float dp = fmaf(y, 1.19825839466702e-06f, 1.18534705686654e-04f);
    dp = fmaf(y, dp, 2.26843463243900e-03f);
    dp = fmaf(y, dp, 4.89352518554385e-03f);
    // reciprocal of dp (positive, normal): bit trick + 2 Newton iterations
    float r = __uint_as_float(0x7EF311C3u - __float_as_uint(dp));
    r = r * (2.0f - dp * r);
    r = r * (2.0f - dp * r);
    return np * r;
}

__device__ __forceinline__ unsigned ld_acq(const unsigned* p) {
    unsigned v;
    asm volatile("ld.acquire.gpu.u32 %0, [%1];" : "=r"(v) : "l"(p) : "memory");
    return v;
}
__device__ __forceinline__ void gbar(unsigned& gen) {
    __syncthreads();
    if (threadIdx.x == 0) {
        __threadfence();
        unsigned arrived = atomicAdd(&g_barcnt, 1u);
        if (arrived == NBLK - 1) {
            g_barcnt = 0;
            __threadfence();
            atomicAdd(&g_bargen, 1u);
        } else {
            while (ld_acq(&g_bargen) == gen) { __nanosleep(16); }
        }
    }
    gen++;
    __syncthreads();
}

// ---------------- HMMA 64x128 tile (fp16 in, fp32 acc) ----------------
__device__ __forceinline__ void hmma_tile(
    const __half* __restrict__ Ag, int lda,
    const __half* __restrict__ Bg, int ldb,
    float* __restrict__ Cg, int ldc,
    int n0, int koff, int nsteps,
    const float* __restrict__ bias,
    __half* sAh, __half* sBh, int tid)
{
    const int wid  = tid >> 5;
    const int lane = tid & 31;
    const int grp  = lane >> 2;
    const int tg   = lane & 3;
    const int wm   = wid >> 2;
    const int wn   = wid & 3;

    const int arow = tid >> 2;            // 0..63
    const int aseg = (tid & 3) * 8;

    const __half* Ap = Ag + (size_t)arow * lda + koff + aseg;
    const __half* Bp = Bg + (size_t)(n0 + arow) * ldb + koff + aseg;

    float c[2][4][4];
#pragma unroll
    for (int i = 0; i < 2; i++)
#pragma unroll
        for (int j = 0; j < 4; j++)
#pragma unroll
            for (int q = 0; q < 4; q++) c[i][j][q] = 0.f;

    for (int kt = 0; kt < nsteps; kt++) {
        const int kb = kt * 32;
        __syncthreads();
        *(uint4*)&sAh[arow * 40 + aseg]        = *(const uint4*)(Ap + kb);
        *(uint4*)&sBh[arow * 40 + aseg]        = *(const uint4*)(Bp + kb);
        *(uint4*)&sBh[(arow + 64) * 40 + aseg] = *(const uint4*)(Bp + (size_t)64 * ldb + kb);
        __syncthreads();

#pragma unroll
        for (int ks = 0; ks < 2; ks++) {
            const int k0 = ks * 16;
            uint32_t a[2][4];
#pragma unroll
            for (int mi = 0; mi < 2; mi++) {
                const int r = wm * 32 + mi * 16 + grp;
                a[mi][0] = *(const uint32_t*)&sAh[(r    ) * 40 + k0 + tg * 2];
                a[mi][1] = *(const uint32_t*)&sAh[(r + 8) * 40 + k0 + tg * 2];
                a[mi][2] = *(const uint32_t*)&sAh[(r    ) * 40 + k0 + tg * 2 + 8];
                a[mi][3] = *(const uint32_t*)&sAh[(r + 8) * 40 + k0 + tg * 2 + 8];
            }
#pragma unroll
            for (int ni = 0; ni < 4; ni++) {
                const int nr = wn * 32 + ni * 8 + grp;
                uint32_t b0 = *(const uint32_t*)&sBh[nr * 40 + k0 + tg * 2];
                uint32_t b1 = *(const uint32_t*)&sBh[nr * 40 + k0 + tg * 2 + 8];
#pragma unroll
                for (int mi = 0; mi < 2; mi++) {
                    asm volatile(
                        "mma.sync.aligned.m16n8k16.row.col.f32.f16.f16.f32 "
                        "{%0,%1,%2,%3}, {%4,%5,%6,%7}, {%8,%9}, {%0,%1,%2,%3};"
                        : "+f"(c[mi][ni][0]), "+f"(c[mi][ni][1]),
                          "+f"(c[mi][ni][2]), "+f"(c[mi][ni][3])
                        : "r"(a[mi][0]), "r"(a[mi][1]), "r"(a[mi][2]), "r"(a[mi][3]),
                          "r"(b0), "r"(b1));
                }
            }
        }
    }

#pragma unroll
    for (int mi = 0; mi < 2; mi++) {
#pragma unroll
        for (int hh = 0; hh < 2; hh++) {
            const int row = wm * 32 + mi * 16 + grp + hh * 8;
            float* crow = Cg + (size_t)row * ldc;
#pragma unroll
            for (int ni = 0; ni < 4; ni++) {
                const int col = n0 + wn * 32 + ni * 8 + tg * 2;
                float v0 = c[mi][ni][hh * 2];
                float v1 = c[mi][ni][hh * 2 + 1];
                if (bias) { v0 += bias[col]; v1 += bias[col + 1]; }
                crow[col]     = v0;
                crow[col + 1] = v1;
            }
        }
    }
}

// ============ persistent decode-loop kernel ============
__global__ void __launch_bounds__(256, 1)
decode_loop_kernel(const float* __restrict__ b_dec_att, const float* __restrict__ Wf,
                   const float* __restrict__ bf, const float* __restrict__ b_fbeta,
                   const float* __restrict__ emb, const int* __restrict__ captions,
                   const int* __restrict__ cap_len,
                   const float* __restrict__ b_ih, const float* __restrict__ b_hh,
                   const float* __restrict__ b_init_h, const float* __restrict__ b_init_c,
                   float* __restrict__ out)
{
    __shared__ __half sAh[64 * 40];
    __shared__ __half sBh[128 * 40];
    __shared__ float sdec[ATT];
    __shared__ float swf[ATT];
    __shared__ float sred[256];
    __shared__ float salpha[256];

    const int bid = blockIdx.x;
    const int tid = threadIdx.x;
    unsigned gen = ld_acq(&g_bargen);

    // ---- pre-phase A: h0/c0 partials via HMMA (64 blocks) ----
    if (bid < 64) {
        const int nt = bid & 7, z = bid >> 3;
        hmma_tile(g_mean16, ENC, g_WinitT, ENC,
                  g_ipart + (size_t)z * 64 * 1024, 1024,
                  nt * 128, z * 256, 8, nullptr, sAh, sBh, tid);
    }
    gbar(gen);
    // ---- pre-phase B: reduce -> h0 (h16cur + x slot), c0; prefetch emb for t=0 ----
    if (bid < 64) {
        const int b = bid;
#pragma unroll
        for (int jj = 0; jj < 4; jj++) {
            const int col = tid + jj * 256;
            float v = 0.f;
#pragma unroll
            for (int z = 0; z < ISPLIT; z++) v += g_ipart[(size_t)(z * BATCH + b) * 1024 + col];
            if (col < DEC) {
                __half hv = __float2half_rn(v + b_init_h[col]);
                g_h16cur[b * DEC + col] = hv;
                g_x16[b * XDIM2 + EMBD + ENC + col] = hv;
            } else {
                g_c[b * DEC + (col - DEC)] = v + b_init_c[col - DEC];
            }
        }
        const int tok = captions[b * MAXLEN + 0];
        if (tid < 256) {
            float2 v = *(const float2*)&emb[(size_t)tok * EMBD + tid * 2];
            __half2 h2 = __floats2half2_rn(v.x, v.y);
            *(__half2*)&g_x16[b * XDIM2 + tid * 2] = h2;
        }
    }
    gbar(gen);

    for (int t = 0; t < TSTEPS; t++) {
        // ---- phase 1: hproj partials (80 blocks) + gates part-A over emb|h (32 blocks) ----
        if (bid < 80) {
            const int nt = bid / HSPLIT;          // 0..19
            const int z  = bid - nt * HSPLIT;     // 0..3
            hmma_tile(g_h16cur, DEC, g_WhcatT, DEC,
                      g_hpart + (size_t)z * 64 * HCAT2, HCAT2,
                      nt * 128, z * 128, 4, nullptr, sAh, sBh, tid);
        } else if (bid < 112) {
            const int idx = bid - 80;
            const int nt  = idx & 15;             // 0..15
            const int seg = idx >> 4;             // 0: emb K[0,512), 1: h K[2560,3072)
            hmma_tile(g_x16, XDIM2, g_WihT, XDIM2,
                      g_gpartA + (size_t)seg * 64 * GDIM, GDIM,
                      nt * 128, seg ? (EMBD + ENC) : 0, 16, nullptr, sAh, sBh, tid);
        }
        gbar(gen);

        // ---- phase 2: attention scores e[b,p] (128 blocks, FMA-only tanh) ----
        if (bid < 128) {
            const int b = bid >> 1, ph = bid & 1;
            for (int k = tid; k < ATT; k += 256) {
                float s = b_dec_att[k];
#pragma unroll
                for (int z = 0; z < HSPLIT; z++)
                    s += g_hpart[(size_t)(z * BATCH + b) * HCAT2 + k];
                sdec[k] = s;
                swf[k] = Wf[k];
            }
            __syncthreads();
            const int warp = tid >> 5, lane = tid & 31;
            const float bf0 = bf[0];
            const int pbase = ph * 98;
            for (int p = pbase + warp; p < pbase + 98; p += 8) {
                const float* ae = g_att_enc + ((size_t)(b * PIX + p)) * ATT;
                float acc = 0.f;
#pragma unroll
                for (int kk = 0; kk < 16; kk++) {
                    const int k = lane + kk * 32;
                    acc += tanh_fma(ae[k] + sdec[k]) * swf[k];
                }
#pragma unroll
                for (int o = 16; o; o >>= 1) acc += __shfl_down_sync(0xffffffffu, acc, o);
                if (lane == 0) g_e[b * PIX + p] = acc + bf0;
            }
        }
        gbar(gen);

        // ---- phase 3: softmax + awe + x16 awe-slot + alphas out (128 blocks) ----
        if (bid < 128) {
            const int b = bid >> 1, chunk = bid & 1;
            float v = (tid < PIX) ? g_e[b * PIX + tid] : -1e30f;
            sred[tid] = v; __syncthreads();
            for (int s = 128; s; s >>= 1) { if (tid < s) sred[tid] = fmaxf(sred[tid], sred[tid+s]); __syncthreads(); }
            const float mx = sred[0]; __syncthreads();
            const float ex = (tid < PIX) ? __expf(v - mx) : 0.f;
            sred[tid] = ex; __syncthreads();
            for (int s = 128; s; s >>= 1) { if (tid < s) sred[tid] += sred[tid+s]; __syncthreads(); }
            const float inv = 1.f / sred[0];
            const float a = ex * inv;            // 0 for tid >= PIX
            salpha[tid] = a;
            if (chunk == 0 && tid < PIX) {
                const float m = (t < cap_len[b] - 1) ? 1.f : 0.f;
                out[ALPHA_OFF + (size_t)b * TSTEPS * PIX + (size_t)t * PIX + tid] = a * m;
            }
            __syncthreads();

            const int d = chunk * 1024 + tid * 4;
            float4 acc = make_float4(0,0,0,0);
            const __half* ep = g_enc_h + (size_t)b * PIX * ENC + d;
#pragma unroll 8
            for (int p = 0; p < 200; p++) {       // padded; alpha[196..200)=0
                const float al = salpha[p];
                uint2 r = *(const uint2*)(ep + (size_t)p * ENC);
                __half2 h0 = *(const __half2*)&r.x;
                __half2 h1 = *(const __half2*)&r.y;
                acc.x = fmaf(al, __low2float(h0),  acc.x);
                acc.y = fmaf(al, __high2float(h0), acc.y);
                acc.z = fmaf(al, __low2float(h1),  acc.z);
                acc.w = fmaf(al, __high2float(h1), acc.w);
            }
            float4 g = make_float4(b_fbeta[d], b_fbeta[d+1], b_fbeta[d+2], b_fbeta[d+3]);
#pragma unroll
            for (int z = 0; z < HSPLIT; z++) {
                float4 p4 = *(const float4*)&g_hpart[(size_t)(z * BATCH + b) * HCAT2 + DEC + d];
                g.x += p4.x; g.y += p4.y; g.z += p4.z; g.w += p4.w;
            }
            g.x = sigmoidf_(g.x); g.y = sigmoidf_(g.y); g.z = sigmoidf_(g.z); g.w = sigmoidf_(g.w);
            __half2 o0 = __floats2half2_rn(acc.x * g.x, acc.y * g.y);
            __half2 o1 = __floats2half2_rn(acc.z * g.z, acc.w * g.w);
            uint2 u; u.x = *(uint32_t*)&o0; u.y = *(uint32_t*)&o1;
            *(uint2*)&g_x16[b * XDIM2 + EMBD + d] = u;
        }
        gbar(gen);

        // ---- phase 4: gates part-B over awe K[512,2560) (128 blocks, split-K 8) ----
        if (bid < 128) {
            const int nt = bid & 15;
            const int z  = bid >> 4;
            hmma_tile(g_x16, XDIM2, g_WihT, XDIM2,
                      g_gpartB + (size_t)z * 64 * GDIM, GDIM,
                      nt * 128, EMBD + z * 256, 8, nullptr, sAh, sBh, tid);
        }
        gbar(gen);

        // ---- phase 5: LSTM update + history + x h-slot + emb prefetch t+1 (64 blocks) ----
        if (bid < 64) {
            const int b = bid;
#pragma unroll
            for (int jj = 0; jj < 2; jj++) {
                const int j = tid + jj * 256;
                float gv[4];
#pragma unroll
                for (int s = 0; s < 4; s++) {
                    const int col = s * DEC + j;
                    float v = b_ih[col] + b_hh[col]
                            + g_gpartA[(size_t)b * GDIM + col]
                            + g_gpartA[(size_t)(BATCH + b) * GDIM + col];
#pragma unroll
                    for (int z = 0; z < GSPLITB; z++)
                        v += g_gpartB[(size_t)(z * BATCH + b) * GDIM + col];
                    gv[s] = v;
                }
                float h = __half2float(g_h16cur[b * DEC + j]);
                if (t < cap_len[b] - 1) {
                    const float c_old = g_c[b * DEC + j];
                    const float cn = sigmoidf_(gv[1]) * c_old + sigmoidf_(gv[0]) * tanhf(gv[2]);
                    g_c[b * DEC + j] = cn;
                    h = sigmoidf_(gv[3]) * tanhf(cn);
                }
                __half hv = __float2half_rn(h);
                g_h16cur[b * DEC + j] = hv;
                g_x16[b * XDIM2 + EMBD + ENC + j] = hv;
                g_h16[((size_t)t * BATCH + b) * DEC + j] = hv;
            }
            if (t + 1 < TSTEPS) {
                const int tok = captions[b * MAXLEN + t + 1];
                float2 v = *(const float2*)&emb[(size_t)tok * EMBD + tid * 2];
                __half2 h2 = __floats2half2_rn(v.x, v.y);
                *(__half2*)&g_x16[b * XDIM2 + tid * 2] = h2;
            }
        }
        gbar(gen);
    }
}

// ============ prologue att_enc GEMM via HMMA ============
__global__ void __launch_bounds__(256)
attenc_mma_kernel(const float* __restrict__ b_enc_att)
{
    __shared__ __half sAh[64 * 40];
    __shared__ __half sBh[128 * 40];
    const int m0 = blockIdx.y * 64;
    const int n0 = blockIdx.x * 128;
    hmma_tile(g_enc_h + (size_t)m0 * ENC, ENC, g_WencT, ENC,
              g_att_enc + (size_t)m0 * ATT, ATT,
              n0, 0, ENC / 32, b_enc_att, sAh, sBh, threadIdx.x);
}

// ============ batched predictions via HMMA ============
__global__ void __launch_bounds__(256)
preds_mma_kernel(const float* __restrict__ b_fc, const float* __restrict__ mask,
                 float* __restrict__ out)
{
    __shared__ __half sAh[64 * 40];
    __shared__ __half sBh[128 * 40];

    const int tid  = threadIdx.x;
    const int wid  = tid >> 5;
    const int lane = tid & 31;
    const int grp  = lane >> 2;
    const int tg   = lane & 3;
    const int wm   = wid >> 2;
    const int wn   = wid & 3;

    const int m0 = blockIdx.y * 64;
    const int n0 = blockIdx.x * 128;

    const int arow = tid >> 2;
    const int aseg = (tid & 3) * 8;

    const __half* Ap = g_h16  + (size_t)(m0 + arow) * DEC + aseg;
    const __half* Bp = g_WfcT + (size_t)(n0 + arow) * DEC + aseg;

    float c[2][4][4];
#pragma unroll
    for (int i = 0; i < 2; i++)
#pragma unroll
        for (int j = 0; j < 4; j++)
#pragma unroll
            for (int q = 0; q < 4; q++) c[i][j][q] = 0.f;

    for (int kt = 0; kt < DEC / 32; kt++) {
        const int kb = kt * 32;
        __syncthreads();
        *(uint4*)&sAh[arow * 40 + aseg]        = *(const uint4*)(Ap + kb);
        *(uint4*)&sBh[arow * 40 + aseg]        = *(const uint4*)(Bp + kb);
        *(uint4*)&sBh[(arow + 64) * 40 + aseg] = *(const uint4*)(Bp + (size_t)64 * DEC + kb);
        __syncthreads();

#pragma unroll
        for (int ks = 0; ks < 2; ks++) {
            const int k0 = ks * 16;
            uint32_t a[2][4];
#pragma unroll
            for (int mi = 0; mi < 2; mi++) {
                const int r = wm * 32 + mi * 16 + grp;
                a[mi][0] = *(const uint32_t*)&sAh[(r    ) * 40 + k0 + tg * 2];
                a[mi][1] = *(const uint32_t*)&sAh[(r + 8) * 40 + k0 + tg * 2];
                a[mi][2] = *(const uint32_t*)&sAh[(r    ) * 40 + k0 + tg * 2 + 8];
                a[mi][3] = *(const uint32_t*)&sAh[(r + 8) * 40 + k0 + tg * 2 + 8];
            }
#pragma unroll
            for (int ni = 0; ni < 4; ni++) {
                const int nr = wn * 32 + ni * 8 + grp;
                uint32_t b0 = *(const uint32_t*)&sBh[nr * 40 + k0 + tg * 2];
                uint32_t b1 = *(const uint32_t*)&sBh[nr * 40 + k0 + tg * 2 + 8];
#pragma unroll
                for (int mi = 0; mi < 2; mi++) {
                    asm volatile(
                        "mma.sync.aligned.m16n8k16.row.col.f32.f16.f16.f32 "
                        "{%0,%1,%2,%3}, {%4,%5,%6,%7}, {%8,%9}, {%0,%1,%2,%3};"
                        : "+f"(c[mi][ni][0]), "+f"(c[mi][ni][1]),
                          "+f"(c[mi][ni][2]), "+f"(c[mi][ni][3])
                        : "r"(a[mi][0]), "r"(a[mi][1]), "r"(a[mi][2]), "r"(a[mi][3]),
                          "r"(b0), "r"(b1));
                }
            }
        }
    }

#pragma unroll
    for (int mi = 0; mi < 2; mi++) {
#pragma unroll
        for (int hh = 0; hh < 2; hh++) {
            const int m = m0 + wm * 32 + mi * 16 + grp + hh * 8;
            const int tt = m >> 6, bb = m & 63;
            const float ms = mask[tt * BATCH + bb];
            float* orow = out + PRED_OFF + ((size_t)bb * TSTEPS + tt) * VOC;
#pragma unroll
            for (int ni = 0; ni < 4; ni++) {
                const int n = n0 + wn * 32 + ni * 8 + tg * 2;
                if (n + 1 < VOC) {
                    orow[n]     = (c[mi][ni][hh * 2]     + b_fc[n])     * ms;
                    orow[n + 1] = (c[mi][ni][hh * 2 + 1] + b_fc[n + 1]) * ms;
                } else if (n < VOC) {
                    orow[n] = (c[mi][ni][hh * 2] + b_fc[n]) * ms;
                }
            }
        }
    }
}

// ---------------- init ----------------
__global__ void init_kernel(const float* __restrict__ Wdec, const float* __restrict__ Wfbeta,
                            const float* __restrict__ Whh, const float* __restrict__ Wih,
                            const float* __restrict__ Wenc,
                            const float* __restrict__ Winith, const float* __restrict__ Winitc,
                            const float* __restrict__ Wfc, const float* __restrict__ enc,
                            const int* __restrict__ captions, const int* __restrict__ cap_len,
                            float* __restrict__ out)
{
    int idx = blockIdx.x * blockDim.x + threadIdx.x;
    int stride = gridDim.x * blockDim.x;
    for (int i = idx; i < HCAT2 * DEC; i += stride) {
        int n = i >> 9, k = i & 511;
        float v = (n < DEC) ? Wdec[k * DEC + n] : Wfbeta[k * ENC + (n - DEC)];
        g_WhcatT[i] = __float2half_rn(v);
    }
    for (int i = idx; i < GDIM * XDIM2; i += stride) {
        int n = i / XDIM2, k = i - n * XDIM2;
        float v = (k < EMBD + ENC) ? Wih[(size_t)k * GDIM + n]
                                   : Whh[(size_t)(k - EMBD - ENC) * GDIM + n];
        g_WihT[i] = __float2half_rn(v);
    }
    for (int i = idx; i < ATT * ENC; i += stride) {
        int n = i >> 11, k = i & 2047;
        g_WencT[i] = __float2half_rn(Wenc[(size_t)k * ATT + n]);
    }
    for (int i = idx; i < NPAD * DEC; i += stride) {
        int n = i >> 9, k = i & 511;
        g_WfcT[i] = (n < VOC) ? __float2half_rn(Wfc[(size_t)k * VOC + n]) : __ushort_as_half(0);
    }
    for (int i = idx; i < 1024 * ENC; i += stride) {
        int n = i >> 11, k = i & 2047;
        float v = (n < DEC) ? Winith[k * DEC + n] : Winitc[k * DEC + (n - DEC)];
        g_WinitT[i] = __float2half_rn(v);
    }
    for (int i = idx; i < BATCH * PIX * ENC; i += stride)
        g_enc_h[i] = __float2half_rn(enc[i]);
    for (int i = idx; i < 8 * ENC; i += stride)
        g_enc_h[BATCH * PIX * ENC + i] = __ushort_as_half(0);
    if (idx < TSTEPS * BATCH) {
        int t = idx / BATCH, b = idx - t * BATCH;
        g_mask[idx] = (t < cap_len[b] - 1) ? 1.f : 0.f;
    }
    if (idx < BATCH * MAXLEN) out[CAP_OFF + idx] = (float)captions[idx];
    if (idx < BATCH)          out[LEN_OFF + idx] = (float)(cap_len[idx] - 1);
}

__global__ void mean_kernel(const float* __restrict__ enc)
{
    int b = blockIdx.y;
    int d = blockIdx.x * 256 + threadIdx.x;
    const float* ep = enc + (size_t)b * PIX * ENC + d;
    float s = 0.f;
    for (int p = 0; p < PIX; p++) s += ep[(size_t)p * ENC];
    g_mean16[b * ENC + d] = __float2half_rn(s * (1.f / (float)PIX));
}

// ---------------- host launcher ----------------
extern "C" void kernel_launch(void* const* d_in, const int* in_sizes, int n_in,
                              void* d_out, int out_size)
{
    const float* enc        = (const float*)d_in[0];
    const int*   captions   = (const int*)  d_in[1];
    const int*   cap_len    = (const int*)  d_in[2];
    const float* emb        = (const float*)d_in[3];
    const float* W_enc_att  = (const float*)d_in[4];
    const float* b_enc_att  = (const float*)d_in[5];
    const float* W_dec_att  = (const float*)d_in[6];
    const float* b_dec_att  = (const float*)d_in[7];
    const float* W_full_att = (const float*)d_in[8];
    const float* b_full_att = (const float*)d_in[9];
    const float* W_init_h   = (const float*)d_in[10];
    const float* b_init_h   = (const float*)d_in[11];
    const float* W_init_c   = (const float*)d_in[12];
    const float* b_init_c   = (const float*)d_in[13];
    const float* W_fbeta    = (const float*)d_in[14];
    const float* b_fbeta    = (const float*)d_in[15];
    const float* W_ih       = (const float*)d_in[16];
    const float* W_hh       = (const float*)d_in[17];
    const float* b_ih       = (const float*)d_in[18];
    const float* b_hh       = (const float*)d_in[19];
    const float* W_fc       = (const float*)d_in[20];
    const float* b_fc       = (const float*)d_in[21];
    float* out = (float*)d_out;
    (void)in_sizes; (void)n_in; (void)out_size;

    float* pmask;
    cudaGetSymbolAddress((void**)&pmask, g_mask);

    // 1: init (concat/transpose/fp16)
    init_kernel<<<4096, 256>>>(W_dec_att, W_fbeta, W_hh, W_ih, W_enc_att,
                               W_init_h, W_init_c, W_fc, enc, captions, cap_len, out);
    // 2: mean over pixels (fp16 out)
    mean_kernel<<<dim3(ENC / 256, BATCH), 256>>>(enc);
    // 3: att_enc = enc @ W_enc_att + b (HMMA)
    attenc_mma_kernel<<<dim3(ATT / 128, (BATCH * PIX) / 64), 256>>>(b_enc_att);
    // 4: entire decode loop (persistent)
    decode_loop_kernel<<<NBLK, 256>>>(b_dec_att, W_full_att, b_full_att, b_fbeta,
                                      emb, captions, cap_len,
                                      b_ih, b_hh, b_init_h, b_init_c, out);
    // 5: all predictions (HMMA)
    preds_mma_kernel<<<dim3(NPAD / 128, MTOT / 64), 256>>>(b_fc, pmask, out);
}

// round 10
// speedup vs baseline: 1.1993x; 1.1993x over previous
#include <cuda_runtime.h>
#include <cuda_fp16.h>
#include <math.h>
#include <stdint.h>

// Problem constants
#define BATCH   64
#define PIX     196
#define ENC     2048
#define DEC     512
#define ATT     512
#define EMBD    512
#define VOC     10000
#define MAXLEN  52
#define TSTEPS  51
#define HCAT2   2560     // 512 dec_att | 2048 fbeta
#define XDIM2   3072     // emb 512 | awe 2048 | h 512
#define GDIM    2048     // 4*DEC

// Output layout (flattened tuple, float32)
#define PRED_OFF   0
#define CAP_OFF    32640000
#define LEN_OFF    32643328
#define ALPHA_OFF  32643392

#define HSPLIT  4        // hproj split-K
#define GSPLITA 8        // gates part-A split-K (emb|h, K=1024)
#define GSPLITB 16       // gates part-B split-K (awe, K=2048)
#define ISPLIT  8        // h0c0 split-K

#define MTOT  (TSTEPS * BATCH)   // 3264
#define NPAD  10112              // 79*128 >= VOC
#define NBLK  296                // persistent grid: 2 blocks/SM

// ---------------- scratch ----------------
__device__ __align__(16) __half g_WhcatT[HCAT2 * DEC];    // [n][k]
__device__ __align__(16) __half g_WihT[GDIM * XDIM2];     // [n][k] (W_ih|W_hh)
__device__ __align__(16) __half g_WencT[ATT * ENC];       // [n][k]
__device__ __align__(16) __half g_WfcT[NPAD * DEC];       // [n][k]
__device__ __align__(16) __half g_WinitT[1024 * ENC];     // [n][k] (h0|c0)
__device__ __align__(16) __half g_enc_h[(BATCH * PIX + 8) * ENC]; // padded
__device__ __align__(16) __half g_mean16[BATCH * ENC];
__device__ __align__(16) __half g_h16cur[BATCH * DEC];
__device__ __align__(16) __half g_h16[MTOT * DEC];
__device__ __align__(16) __half g_x16[BATCH * XDIM2];
__device__ float  g_mask[TSTEPS * BATCH];
__device__ float  g_c[BATCH * DEC];
__device__ float  g_att_enc[BATCH * PIX * ATT];
__device__ float  g_hpart[HSPLIT * BATCH * HCAT2];
__device__ float  g_gpartA[GSPLITA * BATCH * GDIM];
__device__ float  g_gpartB[GSPLITB * BATCH * GDIM];
__device__ float  g_ipart[ISPLIT * BATCH * 1024];
__device__ float  g_e[BATCH * PIX];

// grid barrier: monotonic counter (reset by host memset each launch)
__device__ unsigned g_barcnt;

__device__ __forceinline__ float sigmoidf_(float x) { return 1.f / (1.f + __expf(-x)); }

// FMA-pipe-only tanh (no MUFU): Pade(13,6) + bit-trick reciprocal + 2 Newton
__device__ __forceinline__ float tanh_fma(float x) {
    float cx = fminf(fmaxf(x, -7.99f), 7.99f);
    float y = cx * cx;
    float np = fmaf(y, -2.76076847742355e-16f, 2.00018790482477e-13f);
    np = fmaf(y, np, -8.60467152213735e-11f);
    np = fmaf(y, np, 5.12229709037114e-08f);
    np = fmaf(y, np, 1.48572235717979e-05f);
    np = fmaf(y, np, 6.37261928875436e-04f);
    np = fmaf(y, np, 4.89352455891786e-03f);
    np = np * cx;
    float dp = fmaf(y, 1.19825839466702e-06f, 1.18534705686654e-04f);
    dp = fmaf(y, dp, 2.26843463243900e-03f);
    dp = fmaf(y, dp, 4.89352518554385e-03f);
    float r = __uint_as_float(0x7EF311C3u - __float_as_uint(dp));
    r = r * (2.0f - dp * r);
    r = r * (2.0f - dp * r);
    return np * r;
}

// monotonic grid barrier: arrival = red.add; wait = poll counter >= nbar
__device__ __forceinline__ void gbar(unsigned& nbar) {
    nbar += NBLK;
    __syncthreads();
    if (threadIdx.x == 0) {
        __threadfence();
        asm volatile("red.relaxed.gpu.global.add.u32 [%0], 1;" :: "l"(&g_barcnt) : "memory");
        unsigned v;
        do {
            asm volatile("ld.acquire.gpu.u32 %0, [%1];" : "=r"(v) : "l"(&g_barcnt) : "memory");
        } while ((int)(v - nbar) < 0);
    }
    __syncthreads();
}

// ---------------- HMMA 64x128 tile (fp16 in, fp32 acc) ----------------
__device__ __forceinline__ void hmma_tile(
    const __half* __restrict__ Ag, int lda,
    const __half* __restrict__ Bg, int ldb,
    float* __restrict__ Cg, int ldc,
    int n0, int koff, int nsteps,
    const float* __restrict__ bias,
    __half* sAh, __half* sBh, int tid)
{
    const int wid  = tid >> 5;
    const int lane = tid & 31;
    const int grp  = lane >> 2;
    const int tg   = lane & 3;
    const int wm   = wid >> 2;
    const int wn   = wid & 3;

    const int arow = tid >> 2;            // 0..63
    const int aseg = (tid & 3) * 8;

    const __half* Ap = Ag + (size_t)arow * lda + koff + aseg;
    const __half* Bp = Bg + (size_t)(n0 + arow) * ldb + koff + aseg;

    float c[2][4][4];
#pragma unroll
    for (int i = 0; i < 2; i++)
#pragma unroll
        for (int j = 0; j < 4; j++)
#pragma unroll
            for (int q = 0; q < 4; q++) c[i][j][q] = 0.f;

    for (int kt = 0; kt < nsteps; kt++) {
        const int kb = kt * 32;
        __syncthreads();
        *(uint4*)&sAh[arow * 40 + aseg]        = *(const uint4*)(Ap + kb);
        *(uint4*)&sBh[arow * 40 + aseg]        = *(const uint4*)(Bp + kb);
        *(uint4*)&sBh[(arow + 64) * 40 + aseg] = *(const uint4*)(Bp + (size_t)64 * ldb + kb);
        __syncthreads();

#pragma unroll
        for (int ks = 0; ks < 2; ks++) {
            const int k0 = ks * 16;
            uint32_t a[2][4];
#pragma unroll
            for (int mi = 0; mi < 2; mi++) {
                const int r = wm * 32 + mi * 16 + grp;
                a[mi][0] = *(const uint32_t*)&sAh[(r    ) * 40 + k0 + tg * 2];
                a[mi][1] = *(const uint32_t*)&sAh[(r + 8) * 40 + k0 + tg * 2];
                a[mi][2] = *(const uint32_t*)&sAh[(r    ) * 40 + k0 + tg * 2 + 8];
                a[mi][3] = *(const uint32_t*)&sAh[(r + 8) * 40 + k0 + tg * 2 + 8];
            }
#pragma unroll
            for (int ni = 0; ni < 4; ni++) {
                const int nr = wn * 32 + ni * 8 + grp;
                uint32_t b0 = *(const uint32_t*)&sBh[nr * 40 + k0 + tg * 2];
                uint32_t b1 = *(const uint32_t*)&sBh[nr * 40 + k0 + tg * 2 + 8];
#pragma unroll
                for (int mi = 0; mi < 2; mi++) {
                    asm volatile(
                        "mma.sync.aligned.m16n8k16.row.col.f32.f16.f16.f32 "
                        "{%0,%1,%2,%3}, {%4,%5,%6,%7}, {%8,%9}, {%0,%1,%2,%3};"
                        : "+f"(c[mi][ni][0]), "+f"(c[mi][ni][1]),
                          "+f"(c[mi][ni][2]), "+f"(c[mi][ni][3])
                        : "r"(a[mi][0]), "r"(a[mi][1]), "r"(a[mi][2]), "r"(a[mi][3]),
                          "r"(b0), "r"(b1));
                }
            }
        }
    }

#pragma unroll
    for (int mi = 0; mi < 2; mi++) {
#pragma unroll
        for (int hh = 0; hh < 2; hh++) {
            const int row = wm * 32 + mi * 16 + grp + hh * 8;
            float* crow = Cg + (size_t)row * ldc;
#pragma unroll
            for (int ni = 0; ni < 4; ni++) {
                const int col = n0 + wn * 32 + ni * 8 + tg * 2;
                float v0 = c[mi][ni][hh * 2];
                float v1 = c[mi][ni][hh * 2 + 1];
                if (bias) { v0 += bias[col]; v1 += bias[col + 1]; }
                crow[col]     = v0;
                crow[col + 1] = v1;
            }
        }
    }
}

// ============ persistent decode-loop kernel (296 blocks, 2/SM) ============
__global__ void __launch_bounds__(256, 2)
decode_loop_kernel(const float* __restrict__ b_dec_att, const float* __restrict__ Wf,
                   const float* __restrict__ bf, const float* __restrict__ b_fbeta,
                   const float* __restrict__ emb, const int* __restrict__ captions,
                   const int* __restrict__ cap_len,
                   const float* __restrict__ b_ih, const float* __restrict__ b_hh,
                   const float* __restrict__ b_init_h, const float* __restrict__ b_init_c,
                   float* __restrict__ out)
{
    __shared__ __half sAh[64 * 40];
    __shared__ __half sBh[128 * 40];
    __shared__ float sdec[ATT];
    __shared__ float swf[ATT];
    __shared__ float sred[256];
    __shared__ float salpha[256];

    const int bid = blockIdx.x;
    const int tid = threadIdx.x;
    unsigned nbar = 0;

    // ---- pre-phase A: h0/c0 partials via HMMA (64 blocks) ----
    if (bid < 64) {
        const int nt = bid & 7, z = bid >> 3;
        hmma_tile(g_mean16, ENC, g_WinitT, ENC,
                  g_ipart + (size_t)z * 64 * 1024, 1024,
                  nt * 128, z * 256, 8, nullptr, sAh, sBh, tid);
    }
    gbar(nbar);
    // ---- pre-phase B: reduce -> h0 (h16cur + x slot), c0; emb prefetch t=0 ----
    if (bid < 64) {
        const int b = bid;
#pragma unroll
        for (int jj = 0; jj < 4; jj++) {
            const int col = tid + jj * 256;
            float v = 0.f;
#pragma unroll
            for (int z = 0; z < ISPLIT; z++) v += g_ipart[(size_t)(z * BATCH + b) * 1024 + col];
            if (col < DEC) {
                __half hv = __float2half_rn(v + b_init_h[col]);
                g_h16cur[b * DEC + col] = hv;
                g_x16[b * XDIM2 + EMBD + ENC + col] = hv;
            } else {
                g_c[b * DEC + (col - DEC)] = v + b_init_c[col - DEC];
            }
        }
        const int tok = captions[b * MAXLEN + 0];
        float2 v = *(const float2*)&emb[(size_t)tok * EMBD + tid * 2];
        *(__half2*)&g_x16[b * XDIM2 + tid * 2] = __floats2half2_rn(v.x, v.y);
    }
    gbar(nbar);

    for (int t = 0; t < TSTEPS; t++) {
        // ---- phase 1: hproj (80 blocks) + gates part-A (128 blocks, K=1024 split 8) ----
        if (bid < 80) {
            const int nt = bid / HSPLIT;          // 0..19
            const int z  = bid - nt * HSPLIT;     // 0..3
            hmma_tile(g_h16cur, DEC, g_WhcatT, DEC,
                      g_hpart + (size_t)z * 64 * HCAT2, HCAT2,
                      nt * 128, z * 128, 4, nullptr, sAh, sBh, tid);
        } else if (bid < 208) {
            const int idx = bid - 80;
            const int nt  = idx & 15;             // 0..15
            const int c   = idx >> 4;             // 0..7
            const int koff = (c < 4) ? c * 128 : (EMBD + ENC) + (c - 4) * 128;
            hmma_tile(g_x16, XDIM2, g_WihT, XDIM2,
                      g_gpartA + (size_t)c * 64 * GDIM, GDIM,
                      nt * 128, koff, 4, nullptr, sAh, sBh, tid);
        }
        gbar(nbar);

        // ---- phase 2: attention scores (256 blocks; 4 per b, 49 pixels) ----
        if (bid < 256) {
            const int b = bid >> 2, q = bid & 3;
            for (int k = tid; k < ATT; k += 256) {
                float s = b_dec_att[k];
#pragma unroll
                for (int z = 0; z < HSPLIT; z++)
                    s += g_hpart[(size_t)(z * BATCH + b) * HCAT2 + k];
                sdec[k] = s;
                swf[k] = Wf[k];
            }
            __syncthreads();
            const int warp = tid >> 5, lane = tid & 31;
            const float bf0 = bf[0];
            const int pbase = q * 49;
            for (int p = pbase + warp; p < pbase + 49; p += 8) {
                const float* ae = g_att_enc + ((size_t)(b * PIX + p)) * ATT;
                float acc = 0.f;
#pragma unroll
                for (int kk = 0; kk < 16; kk++) {
                    const int k = lane + kk * 32;
                    acc += tanh_fma(ae[k] + sdec[k]) * swf[k];
                }
#pragma unroll
                for (int o = 16; o; o >>= 1) acc += __shfl_down_sync(0xffffffffu, acc, o);
                if (lane == 0) g_e[b * PIX + p] = acc + bf0;
            }
        }
        gbar(nbar);

        // ---- phase 3: softmax + awe + x16 awe-slot (256 blocks; 4 per b, 512 dims) ----
        if (bid < 256) {
            const int b = bid >> 2, chunk = bid & 3;
            float v = (tid < PIX) ? g_e[b * PIX + tid] : -1e30f;
            sred[tid] = v; __syncthreads();
            for (int s = 128; s; s >>= 1) { if (tid < s) sred[tid] = fmaxf(sred[tid], sred[tid+s]); __syncthreads(); }
            const float mx = sred[0]; __syncthreads();
            const float ex = (tid < PIX) ? __expf(v - mx) : 0.f;
            sred[tid] = ex; __syncthreads();
            for (int s = 128; s; s >>= 1) { if (tid < s) sred[tid] += sred[tid+s]; __syncthreads(); }
            const float inv = 1.f / sred[0];
            const float a = ex * inv;            // 0 for tid >= PIX
            salpha[tid] = a;
            if (chunk == 0 && tid < PIX) {
                const float m = (t < cap_len[b] - 1) ? 1.f : 0.f;
                out[ALPHA_OFF + (size_t)b * TSTEPS * PIX + (size_t)t * PIX + tid] = a * m;
            }
            __syncthreads();

            const int d = chunk * 512 + tid * 2;
            float ax = 0.f, ay = 0.f;
            const __half* ep = g_enc_h + (size_t)b * PIX * ENC + d;
#pragma unroll 8
            for (int p = 0; p < 200; p++) {       // padded; alpha[196..200)=0
                const float al = salpha[p];
                __half2 h2 = *(const __half2*)(ep + (size_t)p * ENC);
                ax = fmaf(al, __low2float(h2),  ax);
                ay = fmaf(al, __high2float(h2), ay);
            }
            float gx = b_fbeta[d], gy = b_fbeta[d + 1];
#pragma unroll
            for (int z = 0; z < HSPLIT; z++) {
                float2 p2 = *(const float2*)&g_hpart[(size_t)(z * BATCH + b) * HCAT2 + DEC + d];
                gx += p2.x; gy += p2.y;
            }
            gx = sigmoidf_(gx); gy = sigmoidf_(gy);
            *(__half2*)&g_x16[b * XDIM2 + EMBD + d] = __floats2half2_rn(ax * gx, ay * gy);
        }
        gbar(nbar);

        // ---- phase 4: gates part-B over awe K[512,2560) (256 blocks, split-K 16) ----
        if (bid < 256) {
            const int nt = bid & 15;
            const int z  = bid >> 4;              // 0..15
            hmma_tile(g_x16, XDIM2, g_WihT, XDIM2,
                      g_gpartB + (size_t)z * 64 * GDIM, GDIM,
                      nt * 128, EMBD + z * 128, 4, nullptr, sAh, sBh, tid);
        }
        gbar(nbar);

        // ---- phase 5: LSTM update (128 blocks; 2 per b) + emb prefetch t+1 ----
        if (bid < 128) {
            const int b = bid >> 1, half = bid & 1;
            const int j = half * 256 + tid;
            float gv[4];
#pragma unroll
            for (int s = 0; s < 4; s++) {
                const int col = s * DEC + j;
                float v = b_ih[col] + b_hh[col];
#pragma unroll
                for (int z = 0; z < GSPLITA; z++)
                    v += g_gpartA[(size_t)(z * BATCH + b) * GDIM + col];
#pragma unroll
                for (int z = 0; z < GSPLITB; z++)
                    v += g_gpartB[(size_t)(z * BATCH + b) * GDIM + col];
                gv[s] = v;
            }
            float h = __half2float(g_h16cur[b * DEC + j]);
            if (t < cap_len[b] - 1) {
                const float c_old = g_c[b * DEC + j];
                const float cn = sigmoidf_(gv[1]) * c_old + sigmoidf_(gv[0]) * tanhf(gv[2]);
                g_c[b * DEC + j] = cn;
                h = sigmoidf_(gv[3]) * tanhf(cn);
            }
            __half hv = __float2half_rn(h);
            g_h16cur[b * DEC + j] = hv;
            g_x16[b * XDIM2 + EMBD + ENC + j] = hv;
            g_h16[((size_t)t * BATCH + b) * DEC + j] = hv;

            if (half == 1 && t + 1 < TSTEPS) {
                const int tok = captions[b * MAXLEN + t + 1];
                float2 v = *(const float2*)&emb[(size_t)tok * EMBD + tid * 2];
                *(__half2*)&g_x16[b * XDIM2 + tid * 2] = __floats2half2_rn(v.x, v.y);
            }
        }
        gbar(nbar);
    }
}

// ============ prologue att_enc GEMM via HMMA ============
__global__ void __launch_bounds__(256)
attenc_mma_kernel(const float* __restrict__ b_enc_att)
{
    __shared__ __half sAh[64 * 40];
    __shared__ __half sBh[128 * 40];
    const int m0 = blockIdx.y * 64;
    const int n0 = blockIdx.x * 128;
    hmma_tile(g_enc_h + (size_t)m0 * ENC, ENC, g_WencT, ENC,
              g_att_enc + (size_t)m0 * ATT, ATT,
              n0, 0, ENC / 32, b_enc_att, sAh, sBh, threadIdx.x);
}

// ============ batched predictions via HMMA ============
__global__ void __launch_bounds__(256)
preds_mma_kernel(const float* __restrict__ b_fc, const float* __restrict__ mask,
                 float* __restrict__ out)
{
    __shared__ __half sAh[64 * 40];
    __shared__ __half sBh[128 * 40];

    const int tid  = threadIdx.x;
    const int wid  = tid >> 5;
    const int lane = tid & 31;
    const int grp  = lane >> 2;
    const int tg   = lane & 3;
    const int wm   = wid >> 2;
    const int wn   = wid & 3;

    const int m0 = blockIdx.y * 64;
    const int n0 = blockIdx.x * 128;

    const int arow = tid >> 2;
    const int aseg = (tid & 3) * 8;

    const __half* Ap = g_h16  + (size_t)(m0 + arow) * DEC + aseg;
    const __half* Bp = g_WfcT + (size_t)(n0 + arow) * DEC + aseg;

    float c[2][4][4];
#pragma unroll
    for (int i = 0; i < 2; i++)
#pragma unroll
        for (int j = 0; j < 4; j++)
#pragma unroll
            for (int q = 0; q < 4; q++) c[i][j][q] = 0.f;

    for (int kt = 0; kt < DEC / 32; kt++) {
        const int kb = kt * 32;
        __syncthreads();
        *(uint4*)&sAh[arow * 40 + aseg]        = *(const uint4*)(Ap + kb);
        *(uint4*)&sBh[arow * 40 + aseg]        = *(const uint4*)(Bp + kb);
        *(uint4*)&sBh[(arow + 64) * 40 + aseg] = *(const uint4*)(Bp + (size_t)64 * DEC + kb);
        __syncthreads();

#pragma unroll
        for (int ks = 0; ks < 2; ks++) {
            const int k0 = ks * 16;
            uint32_t a[2][4];
#pragma unroll
            for (int mi = 0; mi < 2; mi++) {
                const int r = wm * 32 + mi * 16 + grp;
                a[mi][0] = *(const uint32_t*)&sAh[(r    ) * 40 + k0 + tg * 2];
                a[mi][1] = *(const uint32_t*)&sAh[(r + 8) * 40 + k0 + tg * 2];
                a[mi][2] = *(const uint32_t*)&sAh[(r    ) * 40 + k0 + tg * 2 + 8];
                a[mi][3] = *(const uint32_t*)&sAh[(r + 8) * 40 + k0 + tg * 2 + 8];
            }
#pragma unroll
            for (int ni = 0; ni < 4; ni++) {
                const int nr = wn * 32 + ni * 8 + grp;
                uint32_t b0 = *(const uint32_t*)&sBh[nr * 40 + k0 + tg * 2];
                uint32_t b1 = *(const uint32_t*)&sBh[nr * 40 + k0 + tg * 2 + 8];
#pragma unroll
                for (int mi = 0; mi < 2; mi++) {
                    asm volatile(
                        "mma.sync.aligned.m16n8k16.row.col.f32.f16.f16.f32 "
                        "{%0,%1,%2,%3}, {%4,%5,%6,%7}, {%8,%9}, {%0,%1,%2,%3};"
                        : "+f"(c[mi][ni][0]), "+f"(c[mi][ni][1]),
                          "+f"(c[mi][ni][2]), "+f"(c[mi][ni][3])
                        : "r"(a[mi][0]), "r"(a[mi][1]), "r"(a[mi][2]), "r"(a[mi][3]),
                          "r"(b0), "r"(b1));
                }
            }
        }
    }

#pragma unroll
    for (int mi = 0; mi < 2; mi++) {
#pragma unroll
        for (int hh = 0; hh < 2; hh++) {
            const int m = m0 + wm * 32 + mi * 16 + grp + hh * 8;
            const int tt = m >> 6, bb = m & 63;
            const float ms = mask[tt * BATCH + bb];
            float* orow = out + PRED_OFF + ((size_t)bb * TSTEPS + tt) * VOC;
#pragma unroll
            for (int ni = 0; ni < 4; ni++) {
                const int n = n0 + wn * 32 + ni * 8 + tg * 2;
                if (n + 1 < VOC) {
                    orow[n]     = (c[mi][ni][hh * 2]     + b_fc[n])     * ms;
                    orow[n + 1] = (c[mi][ni][hh * 2 + 1] + b_fc[n + 1]) * ms;
                } else if (n < VOC) {
                    orow[n] = (c[mi][ni][hh * 2] + b_fc[n]) * ms;
                }
            }
        }
    }
}

// ---------------- init ----------------
__global__ void init_kernel(const float* __restrict__ Wdec, const float* __restrict__ Wfbeta,
                            const float* __restrict__ Whh, const float* __restrict__ Wih,
                            const float* __restrict__ Wenc,
                            const float* __restrict__ Winith, const float* __restrict__ Winitc,
                            const float* __restrict__ Wfc, const float* __restrict__ enc,
                            const int* __restrict__ captions, const int* __restrict__ cap_len,
                            float* __restrict__ out)
{
    int idx = blockIdx.x * blockDim.x + threadIdx.x;
    int stride = gridDim.x * blockDim.x;
    for (int i = idx; i < HCAT2 * DEC; i += stride) {
        int n = i >> 9, k = i & 511;
        float v = (n < DEC) ? Wdec[k * DEC + n] : Wfbeta[k * ENC + (n - DEC)];
        g_WhcatT[i] = __float2half_rn(v);
    }
    for (int i = idx; i < GDIM * XDIM2; i += stride) {
        int n = i / XDIM2, k = i - n * XDIM2;
        float v = (k < EMBD + ENC) ? Wih[(size_t)k * GDIM + n]
                                   : Whh[(size_t)(k - EMBD - ENC) * GDIM + n];
        g_WihT[i] = __float2half_rn(v);
    }
    for (int i = idx; i < ATT * ENC; i += stride) {
        int n = i >> 11, k = i & 2047;
        g_WencT[i] = __float2half_rn(Wenc[(size_t)k * ATT + n]);
    }
    for (int i = idx; i < NPAD * DEC; i += stride) {
        int n = i >> 9, k = i & 511;
        g_WfcT[i] = (n < VOC) ? __float2half_rn(Wfc[(size_t)k * VOC + n]) : __ushort_as_half(0);
    }
    for (int i = idx; i < 1024 * ENC; i += stride) {
        int n = i >> 11, k = i & 2047;
        float v = (n < DEC) ? Winith[k * DEC + n] : Winitc[k * DEC + (n - DEC)];
        g_WinitT[i] = __float2half_rn(v);
    }
    for (int i = idx; i < BATCH * PIX * ENC; i += stride)
        g_enc_h[i] = __float2half_rn(enc[i]);
    for (int i = idx; i < 8 * ENC; i += stride)
        g_enc_h[BATCH * PIX * ENC + i] = __ushort_as_half(0);
    if (idx < TSTEPS * BATCH) {
        int t = idx / BATCH, b = idx - t * BATCH;
        g_mask[idx] = (t < cap_len[b] - 1) ? 1.f : 0.f;
    }
    if (idx < BATCH * MAXLEN) out[CAP_OFF + idx] = (float)captions[idx];
    if (idx < BATCH)          out[LEN_OFF + idx] = (float)(cap_len[idx] - 1);
}

__global__ void mean_kernel(const float* __restrict__ enc)
{
    int b = blockIdx.y;
    int d = blockIdx.x * 256 + threadIdx.x;
    const float* ep = enc + (size_t)b * PIX * ENC + d;
    float s = 0.f;
    for (int p = 0; p < PIX; p++) s += ep[(size_t)p * ENC];
    g_mean16[b * ENC + d] = __float2half_rn(s * (1.f / (float)PIX));
}

// ---------------- host launcher ----------------
extern "C" void kernel_launch(void* const* d_in, const int* in_sizes, int n_in,
                              void* d_out, int out_size)
{
    const float* enc        = (const float*)d_in[0];
    const int*   captions   = (const int*)  d_in[1];
    const int*   cap_len    = (const int*)  d_in[2];
    const float* emb        = (const float*)d_in[3];
    const float* W_enc_att  = (const float*)d_in[4];
    const float* b_enc_att  = (const float*)d_in[5];
    const float* W_dec_att  = (const float*)d_in[6];
    const float* b_dec_att  = (const float*)d_in[7];
    const float* W_full_att = (const float*)d_in[8];
    const float* b_full_att = (const float*)d_in[9];
    const float* W_init_h   = (const float*)d_in[10];
    const float* b_init_h   = (const float*)d_in[11];
    const float* W_init_c   = (const float*)d_in[12];
    const float* b_init_c   = (const float*)d_in[13];
    const float* W_fbeta    = (const float*)d_in[14];
    const float* b_fbeta    = (const float*)d_in[15];
    const float* W_ih       = (const float*)d_in[16];
    const float* W_hh       = (const float*)d_in[17];
    const float* b_ih       = (const float*)d_in[18];
    const float* b_hh       = (const float*)d_in[19];
    const float* W_fc       = (const float*)d_in[20];
    const float* b_fc       = (const float*)d_in[21];
    float* out = (float*)d_out;
    (void)in_sizes; (void)n_in; (void)out_size;

    float* pmask;
    unsigned* pbar;
    cudaGetSymbolAddress((void**)&pmask, g_mask);
    cudaGetSymbolAddress((void**)&pbar,  g_barcnt);

    // reset barrier counter (graph-capturable memset)
    cudaMemsetAsync(pbar, 0, sizeof(unsigned));

    // 1: init (concat/transpose/fp16)
    init_kernel<<<4096, 256>>>(W_dec_att, W_fbeta, W_hh, W_ih, W_enc_att,
                               W_init_h, W_init_c, W_fc, enc, captions, cap_len, out);
    // 2: mean over pixels (fp16 out)
    mean_kernel<<<dim3(ENC / 256, BATCH), 256>>>(enc);
    // 3: att_enc = enc @ W_enc_att + b (HMMA)
    attenc_mma_kernel<<<dim3(ATT / 128, (BATCH * PIX) / 64), 256>>>(b_enc_att);
    // 4: entire decode loop (persistent, 296 blocks = 2/SM)
    decode_loop_kernel<<<NBLK, 256>>>(b_dec_att, W_full_att, b_full_att, b_fbeta,
                                      emb, captions, cap_len,
                                      b_ih, b_hh, b_init_h, b_init_c, out);
    // 5: all predictions (HMMA)
    preds_mma_kernel<<<dim3(NPAD / 128, MTOT / 64), 256>>>(b_fc, pmask, out);
}

// round 11
// speedup vs baseline: 1.2986x; 1.0828x over previous
#include <cuda_runtime.h>
#include <cuda_fp16.h>
#include <math.h>
#include <stdint.h>

// Problem constants
#define BATCH   64
#define PIX     196
#define ENC     2048
#define DEC     512
#define ATT     512
#define EMBD    512
#define VOC     10000
#define MAXLEN  52
#define TSTEPS  51
#define HCAT2   2560     // 512 dec_att | 2048 fbeta
#define XDIM2   3072     // emb 512 | awe 2048 | h 512
#define GDIM    2048     // 4*DEC

// Output layout (flattened tuple, float32)
#define PRED_OFF   0
#define CAP_OFF    32640000
#define LEN_OFF    32643328
#define ALPHA_OFF  32643392

#define HSPLIT  4        // hproj split-K
#define GSPLITA 8        // gates part-A split-K (emb|h, K=1024)
#define GSPLITB 16       // gates part-B split-K (awe, K=2048)
#define ISPLIT  8        // h0c0 split-K

#define MTOT  (TSTEPS * BATCH)   // 3264
#define NPAD  10112              // 79*128 >= VOC
#define NBLK  296                // persistent grid: 2 blocks/SM

// ---------------- scratch ----------------
__device__ __align__(16) __half g_WhcatT[HCAT2 * DEC];    // [n][k]
__device__ __align__(16) __half g_WihT[GDIM * XDIM2];     // [n][k] (W_ih|W_hh)
__device__ __align__(16) __half g_WencT[ATT * ENC];       // [n][k]
__device__ __align__(16) __half g_WfcT[NPAD * DEC];       // [n][k]
__device__ __align__(16) __half g_WinitT[1024 * ENC];     // [n][k] (h0|c0)
__device__ __align__(16) __half g_enc_h[(BATCH * PIX + 8) * ENC]; // padded
__device__ __align__(16) __half g_mean16[BATCH * ENC];
__device__ __align__(16) __half g_h16cur[BATCH * DEC];
__device__ __align__(16) __half g_h16[MTOT * DEC];
__device__ __align__(16) __half g_x16[BATCH * XDIM2];
__device__ float  g_mask[TSTEPS * BATCH];
__device__ float  g_c[BATCH * DEC];
__device__ float  g_att_enc[BATCH * PIX * ATT];
__device__ float  g_hpart[HSPLIT * BATCH * HCAT2];
__device__ float  g_gpartA[GSPLITA * BATCH * GDIM];
__device__ float  g_gpartB[GSPLITB * BATCH * GDIM];
__device__ float  g_ipart[ISPLIT * BATCH * 1024];
__device__ float  g_e[BATCH * PIX];

// grid barrier: monotonic counter (reset by host memset each launch)
__device__ unsigned g_barcnt;

__device__ __forceinline__ float sigmoidf_(float x) { return 1.f / (1.f + __expf(-x)); }
// MUFU tanh: rt_SMSP=8 per WARP-instruction -> ~1.5us/step chip-wide for 6.4M tanh
__device__ __forceinline__ float tanh_fast(float x) {
    float y; asm("tanh.approx.f32 %0, %1;" : "=f"(y) : "f"(x)); return y;
}

// monotonic grid barrier: arrival = red.add; wait = poll counter >= nbar
__device__ __forceinline__ void gbar(unsigned& nbar) {
    nbar += NBLK;
    __syncthreads();
    if (threadIdx.x == 0) {
        __threadfence();
        asm volatile("red.relaxed.gpu.global.add.u32 [%0], 1;" :: "l"(&g_barcnt) : "memory");
        unsigned v;
        do {
            asm volatile("ld.acquire.gpu.u32 %0, [%1];" : "=r"(v) : "l"(&g_barcnt) : "memory");
        } while ((int)(v - nbar) < 0);
    }
    __syncthreads();
}

// ---------------- HMMA 64x128 core (fp16 in, fp32 acc), double-buffered smem ------
// sAh: 2*64*40 halfs, sBh: 2*128*40 halfs.
__device__ __forceinline__ void hmma_core(
    const __half* __restrict__ Ag, int lda,
    const __half* __restrict__ Bg, int ldb,
    int n0, int koff, int nsteps,
    __half* sAh, __half* sBh, int tid,
    float (&c)[2][4][4])
{
    const int wid  = tid >> 5;
    const int lane = tid & 31;
    const int grp  = lane >> 2;
    const int tg   = lane & 3;
    const int wm   = wid >> 2;
    const int wn   = wid & 3;

    const int arow = tid >> 2;            // 0..63
    const int aseg = (tid & 3) * 8;

    const __half* Ap = Ag + (size_t)arow * lda + koff + aseg;
    const __half* Bp = Bg + (size_t)(n0 + arow) * ldb + koff + aseg;
    const size_t boff = (size_t)64 * ldb;

#pragma unroll
    for (int i = 0; i < 2; i++)
#pragma unroll
        for (int j = 0; j < 4; j++)
#pragma unroll
            for (int q = 0; q < 4; q++) c[i][j][q] = 0.f;

    // prologue: load k-chunk 0 into buffer 0
    uint4 ra  = *(const uint4*)Ap;
    uint4 rb0 = *(const uint4*)Bp;
    uint4 rb1 = *(const uint4*)(Bp + boff);
    *(uint4*)&sAh[arow * 40 + aseg]        = ra;
    *(uint4*)&sBh[arow * 40 + aseg]        = rb0;
    *(uint4*)&sBh[(arow + 64) * 40 + aseg] = rb1;
    __syncthreads();

    for (int kt = 0; kt < nsteps; kt++) {
        const int cur = kt & 1;
        const __half* cA = sAh + cur * (64 * 40);
        const __half* cB = sBh + cur * (128 * 40);

        if (kt + 1 < nsteps) {
            const int kb = (kt + 1) * 32;
            ra  = *(const uint4*)(Ap + kb);
            rb0 = *(const uint4*)(Bp + kb);
            rb1 = *(const uint4*)(Bp + boff + kb);
        }

#pragma unroll
        for (int ks = 0; ks < 2; ks++) {
            const int k0 = ks * 16;
            uint32_t a[2][4];
#pragma unroll
            for (int mi = 0; mi < 2; mi++) {
                const int r = wm * 32 + mi * 16 + grp;
                a[mi][0] = *(const uint32_t*)&cA[(r    ) * 40 + k0 + tg * 2];
                a[mi][1] = *(const uint32_t*)&cA[(r + 8) * 40 + k0 + tg * 2];
                a[mi][2] = *(const uint32_t*)&cA[(r    ) * 40 + k0 + tg * 2 + 8];
                a[mi][3] = *(const uint32_t*)&cA[(r + 8) * 40 + k0 + tg * 2 + 8];
            }
#pragma unroll
            for (int ni = 0; ni < 4; ni++) {
                const int nr = wn * 32 + ni * 8 + grp;
                uint32_t b0 = *(const uint32_t*)&cB[nr * 40 + k0 + tg * 2];
                uint32_t b1 = *(const uint32_t*)&cB[nr * 40 + k0 + tg * 2 + 8];
#pragma unroll
                for (int mi = 0; mi < 2; mi++) {
                    asm volatile(
                        "mma.sync.aligned.m16n8k16.row.col.f32.f16.f16.f32 "
                        "{%0,%1,%2,%3}, {%4,%5,%6,%7}, {%8,%9}, {%0,%1,%2,%3};"
                        : "+f"(c[mi][ni][0]), "+f"(c[mi][ni][1]),
                          "+f"(c[mi][ni][2]), "+f"(c[mi][ni][3])
                        : "r"(a[mi][0]), "r"(a[mi][1]), "r"(a[mi][2]), "r"(a[mi][3]),
                          "r"(b0), "r"(b1));
                }
            }
        }

        if (kt + 1 < nsteps) {
            const int nxt = cur ^ 1;
            __half* nA = sAh + nxt * (64 * 40);
            __half* nB = sBh + nxt * (128 * 40);
            *(uint4*)&nA[arow * 40 + aseg]        = ra;
            *(uint4*)&nB[arow * 40 + aseg]        = rb0;
            *(uint4*)&nB[(arow + 64) * 40 + aseg] = rb1;
            __syncthreads();
        }
    }
}

// standard epilogue: raw/biased dense store
__device__ __forceinline__ void hmma_tile(
    const __half* __restrict__ Ag, int lda,
    const __half* __restrict__ Bg, int ldb,
    float* __restrict__ Cg, int ldc,
    int n0, int koff, int nsteps,
    const float* __restrict__ bias,
    __half* sAh, __half* sBh, int tid)
{
    float c[2][4][4];
    hmma_core(Ag, lda, Bg, ldb, n0, koff, nsteps, sAh, sBh, tid, c);

    const int wid  = tid >> 5;
    const int lane = tid & 31;
    const int grp  = lane >> 2;
    const int tg   = lane & 3;
    const int wm   = wid >> 2;
    const int wn   = wid & 3;

#pragma unroll
    for (int mi = 0; mi < 2; mi++) {
#pragma unroll
        for (int hh = 0; hh < 2; hh++) {
            const int row = wm * 32 + mi * 16 + grp + hh * 8;
            float* crow = Cg + (size_t)row * ldc;
#pragma unroll
            for (int ni = 0; ni < 4; ni++) {
                const int col = n0 + wn * 32 + ni * 8 + tg * 2;
                float v0 = c[mi][ni][hh * 2];
                float v1 = c[mi][ni][hh * 2 + 1];
                if (bias) { v0 += bias[col]; v1 += bias[col + 1]; }
                crow[col]     = v0;
                crow[col + 1] = v1;
            }
        }
    }
}

// ============ persistent decode-loop kernel (296 blocks, 2/SM) ============
__global__ void __launch_bounds__(256, 2)
decode_loop_kernel(const float* __restrict__ b_dec_att, const float* __restrict__ Wf,
                   const float* __restrict__ bf, const float* __restrict__ b_fbeta,
                   const float* __restrict__ emb, const int* __restrict__ captions,
                   const int* __restrict__ cap_len,
                   const float* __restrict__ b_ih, const float* __restrict__ b_hh,
                   const float* __restrict__ b_init_h, const float* __restrict__ b_init_c,
                   float* __restrict__ out)
{
    __shared__ __half sAh[2 * 64 * 40];
    __shared__ __half sBh[2 * 128 * 40];
    __shared__ float sdec[ATT];
    __shared__ float swf[ATT];
    __shared__ float sred[256];
    __shared__ float salpha[256];

    const int bid = blockIdx.x;
    const int tid = threadIdx.x;
    unsigned nbar = 0;

    // ---- pre-phase A: h0/c0 partials via HMMA (64 blocks) ----
    if (bid < 64) {
        const int nt = bid & 7, z = bid >> 3;
        hmma_tile(g_mean16, ENC, g_WinitT, ENC,
                  g_ipart + (size_t)z * 64 * 1024, 1024,
                  nt * 128, z * 256, 8, nullptr, sAh, sBh, tid);
    }
    gbar(nbar);
    // ---- pre-phase B: reduce -> h0 (h16cur + x slot), c0; emb prefetch t=0 ----
    if (bid < 64) {
        const int b = bid;
#pragma unroll
        for (int jj = 0; jj < 4; jj++) {
            const int col = tid + jj * 256;
            float v = 0.f;
#pragma unroll
            for (int z = 0; z < ISPLIT; z++) v += g_ipart[(size_t)(z * BATCH + b) * 1024 + col];
            if (col < DEC) {
                __half hv = __float2half_rn(v + b_init_h[col]);
                g_h16cur[b * DEC + col] = hv;
                g_x16[b * XDIM2 + EMBD + ENC + col] = hv;
            } else {
                g_c[b * DEC + (col - DEC)] = v + b_init_c[col - DEC];
            }
        }
        const int tok = captions[b * MAXLEN + 0];
        float2 v = *(const float2*)&emb[(size_t)tok * EMBD + tid * 2];
        *(__half2*)&g_x16[b * XDIM2 + tid * 2] = __floats2half2_rn(v.x, v.y);
    }
    gbar(nbar);

    for (int t = 0; t < TSTEPS; t++) {
        // ---- phase 1: hproj (80 blocks) + gates part-A (128 blocks, K=1024 split 8) ----
        if (bid < 80) {
            const int nt = bid / HSPLIT;          // 0..19
            const int z  = bid - nt * HSPLIT;     // 0..3
            hmma_tile(g_h16cur, DEC, g_WhcatT, DEC,
                      g_hpart + (size_t)z * 64 * HCAT2, HCAT2,
                      nt * 128, z * 128, 4, nullptr, sAh, sBh, tid);
        } else if (bid < 208) {
            const int idx = bid - 80;
            const int nt  = idx & 15;             // 0..15
            const int c   = idx >> 4;             // 0..7
            const int koff = (c < 4) ? c * 128 : (EMBD + ENC) + (c - 4) * 128;
            hmma_tile(g_x16, XDIM2, g_WihT, XDIM2,
                      g_gpartA + (size_t)c * 64 * GDIM, GDIM,
                      nt * 128, koff, 4, nullptr, sAh, sBh, tid);
        }
        gbar(nbar);

        // ---- phase 2: attention scores (256 blocks; 4 per b, 49 pixels) ----
        if (bid < 256) {
            const int b = bid >> 2, q = bid & 3;
            for (int k = tid; k < ATT; k += 256) {
                float s = b_dec_att[k];
#pragma unroll
                for (int z = 0; z < HSPLIT; z++)
                    s += g_hpart[(size_t)(z * BATCH + b) * HCAT2 + k];
                sdec[k] = s;
                swf[k] = Wf[k];
            }
            __syncthreads();
            const int warp = tid >> 5, lane = tid & 31;
            const float bf0 = bf[0];
            const int pbase = q * 49;
            for (int p = pbase + warp; p < pbase + 49; p += 8) {
                const float* ae = g_att_enc + ((size_t)(b * PIX + p)) * ATT;
                float acc = 0.f;
#pragma unroll
                for (int kk = 0; kk < 16; kk++) {
                    const int k = lane + kk * 32;
                    acc += tanh_fast(ae[k] + sdec[k]) * swf[k];
                }
#pragma unroll
                for (int o = 16; o; o >>= 1) acc += __shfl_down_sync(0xffffffffu, acc, o);
                if (lane == 0) g_e[b * PIX + p] = acc + bf0;
            }
        }
        gbar(nbar);

        // ---- phase 3: softmax + awe + x16 awe-slot (256 blocks; 4 per b, 512 dims) ----
        if (bid < 256) {
            const int b = bid >> 2, chunk = bid & 3;
            float v = (tid < PIX) ? g_e[b * PIX + tid] : -1e30f;
            sred[tid] = v; __syncthreads();
            for (int s = 128; s; s >>= 1) { if (tid < s) sred[tid] = fmaxf(sred[tid], sred[tid+s]); __syncthreads(); }
            const float mx = sred[0]; __syncthreads();
            const float ex = (tid < PIX) ? __expf(v - mx) : 0.f;
            sred[tid] = ex; __syncthreads();
            for (int s = 128; s; s >>= 1) { if (tid < s) sred[tid] += sred[tid+s]; __syncthreads(); }
            const float inv = 1.f / sred[0];
            const float a = ex * inv;            // 0 for tid >= PIX
            salpha[tid] = a;
            if (chunk == 0 && tid < PIX) {
                const float m = (t < cap_len[b] - 1) ? 1.f : 0.f;
                out[ALPHA_OFF + (size_t)b * TSTEPS * PIX + (size_t)t * PIX + tid] = a * m;
            }
            __syncthreads();

            const int d = chunk * 512 + tid * 2;
            float ax = 0.f, ay = 0.f;
            const __half* ep = g_enc_h + (size_t)b * PIX * ENC + d;
#pragma unroll 8
            for (int p = 0; p < 200; p++) {       // padded; alpha[196..200)=0
                const float al = salpha[p];
                __half2 h2 = *(const __half2*)(ep + (size_t)p * ENC);
                ax = fmaf(al, __low2float(h2),  ax);
                ay = fmaf(al, __high2float(h2), ay);
            }
            float gx = b_fbeta[d], gy = b_fbeta[d + 1];
#pragma unroll
            for (int z = 0; z < HSPLIT; z++) {
                float2 p2 = *(const float2*)&g_hpart[(size_t)(z * BATCH + b) * HCAT2 + DEC + d];
                gx += p2.x; gy += p2.y;
            }
            gx = sigmoidf_(gx); gy = sigmoidf_(gy);
            *(__half2*)&g_x16[b * XDIM2 + EMBD + d] = __floats2half2_rn(ax * gx, ay * gy);
        }
        gbar(nbar);

        // ---- phase 4: gates part-B over awe K[512,2560) (256 blocks, split-K 16) ----
        if (bid < 256) {
            const int nt = bid & 15;
            const int z  = bid >> 4;              // 0..15
            hmma_tile(g_x16, XDIM2, g_WihT, XDIM2,
                      g_gpartB + (size_t)z * 64 * GDIM, GDIM,
                      nt * 128, EMBD + z * 128, 4, nullptr, sAh, sBh, tid);
        }
        gbar(nbar);

        // ---- phase 5: LSTM update (128 blocks; 2 per b) + emb prefetch t+1 ----
        if (bid < 128) {
            const int b = bid >> 1, half = bid & 1;
            const int j = half * 256 + tid;
            float gv[4];
#pragma unroll
            for (int s = 0; s < 4; s++) {
                const int col = s * DEC + j;
                float v = b_ih[col] + b_hh[col];
#pragma unroll
                for (int z = 0; z < GSPLITA; z++)
                    v += g_gpartA[(size_t)(z * BATCH + b) * GDIM + col];
#pragma unroll
                for (int z = 0; z < GSPLITB; z++)
                    v += g_gpartB[(size_t)(z * BATCH + b) * GDIM + col];
                gv[s] = v;
            }
            float h = __half2float(g_h16cur[b * DEC + j]);
            if (t < cap_len[b] - 1) {
                const float c_old = g_c[b * DEC + j];
                const float cn = sigmoidf_(gv[1]) * c_old + sigmoidf_(gv[0]) * tanhf(gv[2]);
                g_c[b * DEC + j] = cn;
                h = sigmoidf_(gv[3]) * tanhf(cn);
            }
            __half hv = __float2half_rn(h);
            g_h16cur[b * DEC + j] = hv;
            g_x16[b * XDIM2 + EMBD + ENC + j] = hv;
            g_h16[((size_t)t * BATCH + b) * DEC + j] = hv;

            if (half == 1 && t + 1 < TSTEPS) {
                const int tok = captions[b * MAXLEN + t + 1];
                float2 v = *(const float2*)&emb[(size_t)tok * EMBD + tid * 2];
                *(__half2*)&g_x16[b * XDIM2 + tid * 2] = __floats2half2_rn(v.x, v.y);
            }
        }
        gbar(nbar);
    }
}

// ============ prologue att_enc GEMM via HMMA ============
__global__ void __launch_bounds__(256)
attenc_mma_kernel(const float* __restrict__ b_enc_att)
{
    __shared__ __half sAh[2 * 64 * 40];
    __shared__ __half sBh[2 * 128 * 40];
    const int m0 = blockIdx.y * 64;
    const int n0 = blockIdx.x * 128;
    hmma_tile(g_enc_h + (size_t)m0 * ENC, ENC, g_WencT, ENC,
              g_att_enc + (size_t)m0 * ATT, ATT,
              n0, 0, ENC / 32, b_enc_att, sAh, sBh, threadIdx.x);
}

// ============ batched predictions via HMMA (custom bias+mask epilogue) ============
__global__ void __launch_bounds__(256)
preds_mma_kernel(const float* __restrict__ b_fc, const float* __restrict__ mask,
                 float* __restrict__ out)
{
    __shared__ __half sAh[2 * 64 * 40];
    __shared__ __half sBh[2 * 128 * 40];

    const int tid  = threadIdx.x;
    const int m0 = blockIdx.y * 64;
    const int n0 = blockIdx.x * 128;

    float c[2][4][4];
    hmma_core(g_h16 + (size_t)m0 * DEC, DEC, g_WfcT, DEC,
              n0, 0, DEC / 32, sAh, sBh, tid, c);

    const int wid  = tid >> 5;
    const int lane = tid & 31;
    const int grp  = lane >> 2;
    const int tg   = lane & 3;
    const int wm   = wid >> 2;
    const int wn   = wid & 3;

#pragma unroll
    for (int mi = 0; mi < 2; mi++) {
#pragma unroll
        for (int hh = 0; hh < 2; hh++) {
            const int m = m0 + wm * 32 + mi * 16 + grp + hh * 8;
            const int tt = m >> 6, bb = m & 63;
            const float ms = mask[tt * BATCH + bb];
            float* orow = out + PRED_OFF + ((size_t)bb * TSTEPS + tt) * VOC;
#pragma unroll
            for (int ni = 0; ni < 4; ni++) {
                const int n = n0 + wn * 32 + ni * 8 + tg * 2;
                if (n + 1 < VOC) {
                    orow[n]     = (c[mi][ni][hh * 2]     + b_fc[n])     * ms;
                    orow[n + 1] = (c[mi][ni][hh * 2 + 1] + b_fc[n + 1]) * ms;
                } else if (n < VOC) {
                    orow[n] = (c[mi][ni][hh * 2] + b_fc[n]) * ms;
                }
            }
        }
    }
}

// ---------------- init ----------------
__global__ void init_kernel(const float* __restrict__ Wdec, const float* __restrict__ Wfbeta,
                            const float* __restrict__ Whh, const float* __restrict__ Wih,
                            const float* __restrict__ Wenc,
                            const float* __restrict__ Winith, const float* __restrict__ Winitc,
                            const float* __restrict__ Wfc, const float* __restrict__ enc,
                            const int* __restrict__ captions, const int* __restrict__ cap_len,
                            float* __restrict__ out)
{
    int idx = blockIdx.x * blockDim.x + threadIdx.x;
    int stride = gridDim.x * blockDim.x;
    for (int i = idx; i < HCAT2 * DEC; i += stride) {
        int n = i >> 9, k = i & 511;
        float v = (n < DEC) ? Wdec[k * DEC + n] : Wfbeta[k * ENC + (n - DEC)];
        g_WhcatT[i] = __float2half_rn(v);
    }
    for (int i = idx; i < GDIM * XDIM2; i += stride) {
        int n = i / XDIM2, k = i - n * XDIM2;
        float v = (k < EMBD + ENC) ? Wih[(size_t)k * GDIM + n]
                                   : Whh[(size_t)(k - EMBD - ENC) * GDIM + n];
        g_WihT[i] = __float2half_rn(v);
    }
    for (int i = idx; i < ATT * ENC; i += stride) {
        int n = i >> 11, k = i & 2047;
        g_WencT[i] = __float2half_rn(Wenc[(size_t)k * ATT + n]);
    }
    for (int i = idx; i < NPAD * DEC; i += stride) {
        int n = i >> 9, k = i & 511;
        g_WfcT[i] = (n < VOC) ? __float2half_rn(Wfc[(size_t)k * VOC + n]) : __ushort_as_half(0);
    }
    for (int i = idx; i < 1024 * ENC; i += stride) {
        int n = i >> 11, k = i & 2047;
        float v = (n < DEC) ? Winith[k * DEC + n] : Winitc[k * DEC + (n - DEC)];
        g_WinitT[i] = __float2half_rn(v);
    }
    for (int i = idx; i < BATCH * PIX * ENC; i += stride)
        g_enc_h[i] = __float2half_rn(enc[i]);
    for (int i = idx; i < 8 * ENC; i += stride)
        g_enc_h[BATCH * PIX * ENC + i] = __ushort_as_half(0);
    if (idx < TSTEPS * BATCH) {
        int t = idx / BATCH, b = idx - t * BATCH;
        g_mask[idx] = (t < cap_len[b] - 1) ? 1.f : 0.f;
    }
    if (idx < BATCH * MAXLEN) out[CAP_OFF + idx] = (float)captions[idx];
    if (idx < BATCH)          out[LEN_OFF + idx] = (float)(cap_len[idx] - 1);
}

__global__ void mean_kernel(const float* __restrict__ enc)
{
    int b = blockIdx.y;
    int d = blockIdx.x * 256 + threadIdx.x;
    const float* ep = enc + (size_t)b * PIX * ENC + d;
    float s = 0.f;
    for (int p = 0; p < PIX; p++) s += ep[(size_t)p * ENC];
    g_mean16[b * ENC + d] = __float2half_rn(s * (1.f / (float)PIX));
}

// ---------------- host launcher ----------------
extern "C" void kernel_launch(void* const* d_in, const int* in_sizes, int n_in,
                              void* d_out, int out_size)
{
    const float* enc        = (const float*)d_in[0];
    const int*   captions   = (const int*)  d_in[1];
    const int*   cap_len    = (const int*)  d_in[2];
    const float* emb        = (const float*)d_in[3];
    const float* W_enc_att  = (const float*)d_in[4];
    const float* b_enc_att  = (const float*)d_in[5];
    const float* W_dec_att  = (const float*)d_in[6];
    const float* b_dec_att  = (const float*)d_in[7];
    const float* W_full_att = (const float*)d_in[8];
    const float* b_full_att = (const float*)d_in[9];
    const float* W_init_h   = (const float*)d_in[10];
    const float* b_init_h   = (const float*)d_in[11];
    const float* W_init_c   = (const float*)d_in[12];
    const float* b_init_c   = (const float*)d_in[13];
    const float* W_fbeta    = (const float*)d_in[14];
    const float* b_fbeta    = (const float*)d_in[15];
    const float* W_ih       = (const float*)d_in[16];
    const float* W_hh       = (const float*)d_in[17];
    const float* b_ih       = (const float*)d_in[18];
    const float* b_hh       = (const float*)d_in[19];
    const float* W_fc       = (const float*)d_in[20];
    const float* b_fc       = (const float*)d_in[21];
    float* out = (float*)d_out;
    (void)in_sizes; (void)n_in; (void)out_size;

    float* pmask;
    unsigned* pbar;
    cudaGetSymbolAddress((void**)&pmask, g_mask);
    cudaGetSymbolAddress((void**)&pbar,  g_barcnt);

    // reset barrier counter (graph-capturable memset)
    cudaMemsetAsync(pbar, 0, sizeof(unsigned));

    // 1: init (concat/transpose/fp16)
    init_kernel<<<4096, 256>>>(W_dec_att, W_fbeta, W_hh, W_ih, W_enc_att,
                               W_init_h, W_init_c, W_fc, enc, captions, cap_len, out);
    // 2: mean over pixels (fp16 out)
    mean_kernel<<<dim3(ENC / 256, BATCH), 256>>>(enc);
    // 3: att_enc = enc @ W_enc_att + b (HMMA)
    attenc_mma_kernel<<<dim3(ATT / 128, (BATCH * PIX) / 64), 256>>>(b_enc_att);
    // 4: entire decode loop (persistent, 296 blocks = 2/SM)
    decode_loop_kernel<<<NBLK, 256>>>(b_dec_att, W_full_att, b_full_att, b_fbeta,
                                      emb, captions, cap_len,
                                      b_ih, b_hh, b_init_h, b_init_c, out);
    // 5: all predictions (HMMA)
    preds_mma_kernel<<<dim3(NPAD / 128, MTOT / 64), 256>>>(b_fc, pmask, out);
}

// round 12
// speedup vs baseline: 1.3932x; 1.0729x over previous
#include <cuda_runtime.h>
#include <cuda_fp16.h>
#include <math.h>
#include <stdint.h>

// Problem constants
#define BATCH   64
#define PIX     196
#define ENC     2048
#define DEC     512
#define ATT     512
#define EMBD    512
#define VOC     10000
#define MAXLEN  52
#define TSTEPS  51
#define HCAT2   2560     // 512 dec_att | 2048 fbeta
#define XDIM2   3072     // emb 512 | awe 2048 | h 512
#define GDIM    2048     // 4*DEC

// Output layout (flattened tuple, float32)
#define PRED_OFF   0
#define CAP_OFF    32640000
#define LEN_OFF    32643328
#define ALPHA_OFF  32643392

#define HSPLIT  4        // hproj split-K
#define GSPLITA 8        // gates part-A split-K (emb|h, K=1024)
#define GSPLITB 16       // gates part-B split-K (awe, K=2048)
#define ISPLIT  8        // h0c0 split-K

#define MTOT  (TSTEPS * BATCH)   // 3264
#define NPAD  10112              // 79*128 >= VOC
#define NBLK  296                // persistent grid: 2 blocks/SM

// ---------------- scratch ----------------
__device__ __align__(16) __half g_WhcatT[HCAT2 * DEC];    // [n][k]
__device__ __align__(16) __half g_WihT[GDIM * XDIM2];     // [n][k] (W_ih|W_hh)
__device__ __align__(16) __half g_WencT[ATT * ENC];       // [n][k]
__device__ __align__(16) __half g_WfcT[NPAD * DEC];       // [n][k]
__device__ __align__(16) __half g_WinitT[1024 * ENC];     // [n][k] (h0|c0)
__device__ __align__(16) __half g_enc_h[(BATCH * PIX + 8) * ENC]; // padded
__device__ __align__(16) __half g_mean16[BATCH * ENC];
__device__ __align__(16) __half g_h16cur[BATCH * DEC];
__device__ __align__(16) __half g_h16[MTOT * DEC];
__device__ __align__(16) __half g_x16[BATCH * XDIM2];
__device__ __align__(16) __half g_att_enc16[BATCH * PIX * ATT];  // fp16 att_enc
__device__ float  g_mask[TSTEPS * BATCH];
__device__ float  g_c[BATCH * DEC];
__device__ float  g_hpart[HSPLIT * BATCH * HCAT2];
__device__ float  g_gpartA[GSPLITA * BATCH * GDIM];
__device__ float  g_gpartB[GSPLITB * BATCH * GDIM];
__device__ float  g_ipart[ISPLIT * BATCH * 1024];
__device__ float  g_e[BATCH * PIX];

// grid barrier: monotonic counter (reset by host memset each launch)
__device__ unsigned g_barcnt;

__device__ __forceinline__ float sigmoidf_(float x) { return 1.f / (1.f + __expf(-x)); }
__device__ __forceinline__ float tanh_fast(float x) {
    float y; asm("tanh.approx.f32 %0, %1;" : "=f"(y) : "f"(x)); return y;
}

// monotonic grid barrier: arrival = red.add; wait = poll counter >= nbar
__device__ __forceinline__ void gbar(unsigned& nbar) {
    nbar += NBLK;
    __syncthreads();
    if (threadIdx.x == 0) {
        __threadfence();
        asm volatile("red.relaxed.gpu.global.add.u32 [%0], 1;" :: "l"(&g_barcnt) : "memory");
        unsigned v;
        do {
            asm volatile("ld.acquire.gpu.u32 %0, [%1];" : "=r"(v) : "l"(&g_barcnt) : "memory");
        } while ((int)(v - nbar) < 0);
    }
    __syncthreads();
}

// ---------------- HMMA 64x128 core (fp16 in, fp32 acc), double-buffered smem ------
__device__ __forceinline__ void hmma_core(
    const __half* __restrict__ Ag, int lda,
    const __half* __restrict__ Bg, int ldb,
    int n0, int koff, int nsteps,
    __half* sAh, __half* sBh, int tid,
    float (&c)[2][4][4])
{
    const int wid  = tid >> 5;
    const int lane = tid & 31;
    const int grp  = lane >> 2;
    const int tg   = lane & 3;
    const int wm   = wid >> 2;
    const int wn   = wid & 3;

    const int arow = tid >> 2;            // 0..63
    const int aseg = (tid & 3) * 8;

    const __half* Ap = Ag + (size_t)arow * lda + koff + aseg;
    const __half* Bp = Bg + (size_t)(n0 + arow) * ldb + koff + aseg;
    const size_t boff = (size_t)64 * ldb;

#pragma unroll
    for (int i = 0; i < 2; i++)
#pragma unroll
        for (int j = 0; j < 4; j++)
#pragma unroll
            for (int q = 0; q < 4; q++) c[i][j][q] = 0.f;

    uint4 ra  = *(const uint4*)Ap;
    uint4 rb0 = *(const uint4*)Bp;
    uint4 rb1 = *(const uint4*)(Bp + boff);
    *(uint4*)&sAh[arow * 40 + aseg]        = ra;
    *(uint4*)&sBh[arow * 40 + aseg]        = rb0;
    *(uint4*)&sBh[(arow + 64) * 40 + aseg] = rb1;
    __syncthreads();

    for (int kt = 0; kt < nsteps; kt++) {
        const int cur = kt & 1;
        const __half* cA = sAh + cur * (64 * 40);
        const __half* cB = sBh + cur * (128 * 40);

        if (kt + 1 < nsteps) {
            const int kb = (kt + 1) * 32;
            ra  = *(const uint4*)(Ap + kb);
            rb0 = *(const uint4*)(Bp + kb);
            rb1 = *(const uint4*)(Bp + boff + kb);
        }

#pragma unroll
        for (int ks = 0; ks < 2; ks++) {
            const int k0 = ks * 16;
            uint32_t a[2][4];
#pragma unroll
            for (int mi = 0; mi < 2; mi++) {
                const int r = wm * 32 + mi * 16 + grp;
                a[mi][0] = *(const uint32_t*)&cA[(r    ) * 40 + k0 + tg * 2];
                a[mi][1] = *(const uint32_t*)&cA[(r + 8) * 40 + k0 + tg * 2];
                a[mi][2] = *(const uint32_t*)&cA[(r    ) * 40 + k0 + tg * 2 + 8];
                a[mi][3] = *(const uint32_t*)&cA[(r + 8) * 40 + k0 + tg * 2 + 8];
            }
#pragma unroll
            for (int ni = 0; ni < 4; ni++) {
                const int nr = wn * 32 + ni * 8 + grp;
                uint32_t b0 = *(const uint32_t*)&cB[nr * 40 + k0 + tg * 2];
                uint32_t b1 = *(const uint32_t*)&cB[nr * 40 + k0 + tg * 2 + 8];
#pragma unroll
                for (int mi = 0; mi < 2; mi++) {
                    asm volatile(
                        "mma.sync.aligned.m16n8k16.row.col.f32.f16.f16.f32 "
                        "{%0,%1,%2,%3}, {%4,%5,%6,%7}, {%8,%9}, {%0,%1,%2,%3};"
                        : "+f"(c[mi][ni][0]), "+f"(c[mi][ni][1]),
                          "+f"(c[mi][ni][2]), "+f"(c[mi][ni][3])
                        : "r"(a[mi][0]), "r"(a[mi][1]), "r"(a[mi][2]), "r"(a[mi][3]),
                          "r"(b0), "r"(b1));
                }
            }
        }

        if (kt + 1 < nsteps) {
            const int nxt = cur ^ 1;
            __half* nA = sAh + nxt * (64 * 40);
            __half* nB = sBh + nxt * (128 * 40);
            *(uint4*)&nA[arow * 40 + aseg]        = ra;
            *(uint4*)&nB[arow * 40 + aseg]        = rb0;
            *(uint4*)&nB[(arow + 64) * 40 + aseg] = rb1;
            __syncthreads();
        }
    }
}

// standard epilogue: raw/biased dense fp32 store
__device__ __forceinline__ void hmma_tile(
    const __half* __restrict__ Ag, int lda,
    const __half* __restrict__ Bg, int ldb,
    float* __restrict__ Cg, int ldc,
    int n0, int koff, int nsteps,
    const float* __restrict__ bias,
    __half* sAh, __half* sBh, int tid)
{
    float c[2][4][4];
    hmma_core(Ag, lda, Bg, ldb, n0, koff, nsteps, sAh, sBh, tid, c);

    const int wid  = tid >> 5;
    const int lane = tid & 31;
    const int grp  = lane >> 2;
    const int tg   = lane & 3;
    const int wm   = wid >> 2;
    const int wn   = wid & 3;

#pragma unroll
    for (int mi = 0; mi < 2; mi++) {
#pragma unroll
        for (int hh = 0; hh < 2; hh++) {
            const int row = wm * 32 + mi * 16 + grp + hh * 8;
            float* crow = Cg + (size_t)row * ldc;
#pragma unroll
            for (int ni = 0; ni < 4; ni++) {
                const int col = n0 + wn * 32 + ni * 8 + tg * 2;
                float v0 = c[mi][ni][hh * 2];
                float v1 = c[mi][ni][hh * 2 + 1];
                if (bias) { v0 += bias[col]; v1 += bias[col + 1]; }
                crow[col]     = v0;
                crow[col + 1] = v1;
            }
        }
    }
}

// ============ persistent decode-loop kernel (296 blocks, 2/SM) ============
__global__ void __launch_bounds__(256, 2)
decode_loop_kernel(const float* __restrict__ b_dec_att, const float* __restrict__ Wf,
                   const float* __restrict__ bf, const float* __restrict__ b_fbeta,
                   const float* __restrict__ emb, const int* __restrict__ captions,
                   const int* __restrict__ cap_len,
                   const float* __restrict__ b_ih, const float* __restrict__ b_hh,
                   const float* __restrict__ b_init_h, const float* __restrict__ b_init_c,
                   float* __restrict__ out)
{
    __shared__ __half sAh[2 * 64 * 40];
    __shared__ __half sBh[2 * 128 * 40];
    __shared__ float sdec[ATT];
    __shared__ float swf[ATT];
    __shared__ float sred[256];
    __shared__ float salpha[256];

    const int bid = blockIdx.x;
    const int tid = threadIdx.x;
    unsigned nbar = 0;

    // ---- pre-phase A: h0/c0 partials via HMMA (64 blocks) ----
    if (bid < 64) {
        const int nt = bid & 7, z = bid >> 3;
        hmma_tile(g_mean16, ENC, g_WinitT, ENC,
                  g_ipart + (size_t)z * 64 * 1024, 1024,
                  nt * 128, z * 256, 8, nullptr, sAh, sBh, tid);
    }
    gbar(nbar);
    // ---- pre-phase B: reduce -> h0 (h16cur + x slot), c0; emb prefetch t=0 ----
    if (bid < 64) {
        const int b = bid;
#pragma unroll
        for (int jj = 0; jj < 4; jj++) {
            const int col = tid + jj * 256;
            float v = 0.f;
#pragma unroll
            for (int z = 0; z < ISPLIT; z++) v += g_ipart[(size_t)(z * BATCH + b) * 1024 + col];
            if (col < DEC) {
                __half hv = __float2half_rn(v + b_init_h[col]);
                g_h16cur[b * DEC + col] = hv;
                g_x16[b * XDIM2 + EMBD + ENC + col] = hv;
            } else {
                g_c[b * DEC + (col - DEC)] = v + b_init_c[col - DEC];
            }
        }
        const int tok = captions[b * MAXLEN + 0];
        float2 v = *(const float2*)&emb[(size_t)tok * EMBD + tid * 2];
        *(__half2*)&g_x16[b * XDIM2 + tid * 2] = __floats2half2_rn(v.x, v.y);
    }
    gbar(nbar);

    for (int t = 0; t < TSTEPS; t++) {
        // ---- phase 1: hproj (80 blocks) + gates part-A (128 blocks) ----
        if (bid < 80) {
            const int nt = bid / HSPLIT;
            const int z  = bid - nt * HSPLIT;
            hmma_tile(g_h16cur, DEC, g_WhcatT, DEC,
                      g_hpart + (size_t)z * 64 * HCAT2, HCAT2,
                      nt * 128, z * 128, 4, nullptr, sAh, sBh, tid);
        } else if (bid < 208) {
            const int idx = bid - 80;
            const int nt  = idx & 15;
            const int c   = idx >> 4;
            const int koff = (c < 4) ? c * 128 : (EMBD + ENC) + (c - 4) * 128;
            hmma_tile(g_x16, XDIM2, g_WihT, XDIM2,
                      g_gpartA + (size_t)c * 64 * GDIM, GDIM,
                      nt * 128, koff, 4, nullptr, sAh, sBh, tid);
        }
        gbar(nbar);

        // ---- phase 2: attention scores (256 blocks; 4 per b, 49 pixels; fp16 att_enc) --
        if (bid < 256) {
            const int b = bid >> 2, q = bid & 3;
            for (int k = tid; k < ATT; k += 256) {
                float s = b_dec_att[k];
#pragma unroll
                for (int z = 0; z < HSPLIT; z++)
                    s += g_hpart[(size_t)(z * BATCH + b) * HCAT2 + k];
                sdec[k] = s;
                swf[k] = Wf[k];
            }
            __syncthreads();
            const int warp = tid >> 5, lane = tid & 31;
            const float bf0 = bf[0];
            const int pbase = q * 49;
            for (int p = pbase + warp; p < pbase + 49; p += 8) {
                const __half2* ae = (const __half2*)(g_att_enc16 + (size_t)(b * PIX + p) * ATT);
                float acc = 0.f;
#pragma unroll
                for (int kk = 0; kk < 8; kk++) {
                    const int idx = lane + kk * 32;
                    __half2 a2 = ae[idx];
                    const int k0 = idx * 2;
                    acc += tanh_fast(__low2float(a2)  + sdec[k0])     * swf[k0];
                    acc += tanh_fast(__high2float(a2) + sdec[k0 + 1]) * swf[k0 + 1];
                }
#pragma unroll
                for (int o = 16; o; o >>= 1) acc += __shfl_down_sync(0xffffffffu, acc, o);
                if (lane == 0) g_e[b * PIX + p] = acc + bf0;
            }
        }
        gbar(nbar);

        // ---- phase 3: softmax + awe + x16 awe-slot (256 blocks; 4 per b) ----
        if (bid < 256) {
            const int b = bid >> 2, chunk = bid & 3;
            float v = (tid < PIX) ? g_e[b * PIX + tid] : -1e30f;
            sred[tid] = v; __syncthreads();
            for (int s = 128; s; s >>= 1) { if (tid < s) sred[tid] = fmaxf(sred[tid], sred[tid+s]); __syncthreads(); }
            const float mx = sred[0]; __syncthreads();
            const float ex = (tid < PIX) ? __expf(v - mx) : 0.f;
            sred[tid] = ex; __syncthreads();
            for (int s = 128; s; s >>= 1) { if (tid < s) sred[tid] += sred[tid+s]; __syncthreads(); }
            const float inv = 1.f / sred[0];
            const float a = ex * inv;
            salpha[tid] = a;
            if (chunk == 0 && tid < PIX) {
                const float m = (t < cap_len[b] - 1) ? 1.f : 0.f;
                out[ALPHA_OFF + (size_t)b * TSTEPS * PIX + (size_t)t * PIX + tid] = a * m;
            }
            __syncthreads();

            const int d = chunk * 512 + tid * 2;
            float ax = 0.f, ay = 0.f;
            const __half* ep = g_enc_h + (size_t)b * PIX * ENC + d;
#pragma unroll 8
            for (int p = 0; p < 200; p++) {
                const float al = salpha[p];
                __half2 h2 = *(const __half2*)(ep + (size_t)p * ENC);
                ax = fmaf(al, __low2float(h2),  ax);
                ay = fmaf(al, __high2float(h2), ay);
            }
            float gx = b_fbeta[d], gy = b_fbeta[d + 1];
#pragma unroll
            for (int z = 0; z < HSPLIT; z++) {
                float2 p2 = *(const float2*)&g_hpart[(size_t)(z * BATCH + b) * HCAT2 + DEC + d];
                gx += p2.x; gy += p2.y;
            }
            gx = sigmoidf_(gx); gy = sigmoidf_(gy);
            *(__half2*)&g_x16[b * XDIM2 + EMBD + d] = __floats2half2_rn(ax * gx, ay * gy);
        }
        gbar(nbar);

        // ---- phase 4: gates part-B over awe K[512,2560) (256 blocks, split-K 16) ----
        if (bid < 256) {
            const int nt = bid & 15;
            const int z  = bid >> 4;
            hmma_tile(g_x16, XDIM2, g_WihT, XDIM2,
                      g_gpartB + (size_t)z * 64 * GDIM, GDIM,
                      nt * 128, EMBD + z * 128, 4, nullptr, sAh, sBh, tid);
        }
        gbar(nbar);

        // ---- phase 5: LSTM update (128 blocks; 2 per b) + emb prefetch t+1 ----
        if (bid < 128) {
            const int b = bid >> 1, half = bid & 1;
            const int j = half * 256 + tid;
            float gv[4];
#pragma unroll
            for (int s = 0; s < 4; s++) {
                const int col = s * DEC + j;
                float v = b_ih[col] + b_hh[col];
#pragma unroll
                for (int z = 0; z < GSPLITA; z++)
                    v += g_gpartA[(size_t)(z * BATCH + b) * GDIM + col];
#pragma unroll
                for (int z = 0; z < GSPLITB; z++)
                    v += g_gpartB[(size_t)(z * BATCH + b) * GDIM + col];
                gv[s] = v;
            }
            float h = __half2float(g_h16cur[b * DEC + j]);
            if (t < cap_len[b] - 1) {
                const float c_old = g_c[b * DEC + j];
                const float cn = sigmoidf_(gv[1]) * c_old + sigmoidf_(gv[0]) * tanhf(gv[2]);
                g_c[b * DEC + j] = cn;
                h = sigmoidf_(gv[3]) * tanhf(cn);
            }
            __half hv = __float2half_rn(h);
            g_h16cur[b * DEC + j] = hv;
            g_x16[b * XDIM2 + EMBD + ENC + j] = hv;
            g_h16[((size_t)t * BATCH + b) * DEC + j] = hv;

            if (half == 1 && t + 1 < TSTEPS) {
                const int tok = captions[b * MAXLEN + t + 1];
                float2 v = *(const float2*)&emb[(size_t)tok * EMBD + tid * 2];
                *(__half2*)&g_x16[b * XDIM2 + tid * 2] = __floats2half2_rn(v.x, v.y);
            }
        }
        gbar(nbar);
    }
}

// ============ prologue att_enc GEMM via HMMA -> fp16 output ============
__global__ void __launch_bounds__(256)
attenc_mma_kernel(const float* __restrict__ b_enc_att)
{
    __shared__ __half sAh[2 * 64 * 40];
    __shared__ __half sBh[2 * 128 * 40];
    const int tid = threadIdx.x;
    const int m0 = blockIdx.y * 64;
    const int n0 = blockIdx.x * 128;

    float c[2][4][4];
    hmma_core(g_enc_h + (size_t)m0 * ENC, ENC, g_WencT, ENC,
              n0, 0, ENC / 32, sAh, sBh, tid, c);

    const int wid  = tid >> 5;
    const int lane = tid & 31;
    const int grp  = lane >> 2;
    const int tg   = lane & 3;
    const int wm   = wid >> 2;
    const int wn   = wid & 3;

#pragma unroll
    for (int mi = 0; mi < 2; mi++) {
#pragma unroll
        for (int hh = 0; hh < 2; hh++) {
            const int row = wm * 32 + mi * 16 + grp + hh * 8;
            __half* crow = g_att_enc16 + (size_t)(m0 + row) * ATT;
#pragma unroll
            for (int ni = 0; ni < 4; ni++) {
                const int col = n0 + wn * 32 + ni * 8 + tg * 2;
                float v0 = c[mi][ni][hh * 2]     + b_enc_att[col];
                float v1 = c[mi][ni][hh * 2 + 1] + b_enc_att[col + 1];
                *(__half2*)&crow[col] = __floats2half2_rn(v0, v1);
            }
        }
    }
}

// ============ batched predictions via HMMA (bias+mask epilogue) ============
__global__ void __launch_bounds__(256)
preds_mma_kernel(const float* __restrict__ b_fc, const float* __restrict__ mask,
                 float* __restrict__ out)
{
    __shared__ __half sAh[2 * 64 * 40];
    __shared__ __half sBh[2 * 128 * 40];

    const int tid = threadIdx.x;
    const int m0 = blockIdx.y * 64;
    const int n0 = blockIdx.x * 128;

    float c[2][4][4];
    hmma_core(g_h16 + (size_t)m0 * DEC, DEC, g_WfcT, DEC,
              n0, 0, DEC / 32, sAh, sBh, tid, c);

    const int wid  = tid >> 5;
    const int lane = tid & 31;
    const int grp  = lane >> 2;
    const int tg   = lane & 3;
    const int wm   = wid >> 2;
    const int wn   = wid & 3;

#pragma unroll
    for (int mi = 0; mi < 2; mi++) {
#pragma unroll
        for (int hh = 0; hh < 2; hh++) {
            const int m = m0 + wm * 32 + mi * 16 + grp + hh * 8;
            const int tt = m >> 6, bb = m & 63;
            const float ms = mask[tt * BATCH + bb];
            float* orow = out + PRED_OFF + ((size_t)bb * TSTEPS + tt) * VOC;
#pragma unroll
            for (int ni = 0; ni < 4; ni++) {
                const int n = n0 + wn * 32 + ni * 8 + tg * 2;
                if (n + 1 < VOC) {
                    orow[n]     = (c[mi][ni][hh * 2]     + b_fc[n])     * ms;
                    orow[n + 1] = (c[mi][ni][hh * 2 + 1] + b_fc[n + 1]) * ms;
                } else if (n < VOC) {
                    orow[n] = (c[mi][ni][hh * 2] + b_fc[n]) * ms;
                }
            }
        }
    }
}

// ---------------- tiled transpose: src fp32 [K][N] -> dst fp16 [N][ldd] ----------
__global__ void transpose_f2h_kernel(const float* __restrict__ src, __half* __restrict__ dst,
                                     int K, int N, int ldd)
{
    __shared__ float tile[32][33];
    const int kb = blockIdx.y * 32, nb = blockIdx.x * 32;
    const int tx = threadIdx.x & 31, ty = threadIdx.x >> 5;   // 32x8
#pragma unroll
    for (int i = 0; i < 32; i += 8) {
        const int k = kb + ty + i, n = nb + tx;
        tile[ty + i][tx] = (k < K && n < N) ? src[(size_t)k * N + n] : 0.f;
    }
    __syncthreads();
#pragma unroll
    for (int i = 0; i < 32; i += 8) {
        const int n = nb + ty + i, k = kb + tx;
        if (n < N && k < K)
            dst[(size_t)n * ldd + k] = __float2half_rn(tile[tx][ty + i]);
    }
}

// ---------------- init: enc fp16, pads, mask, int outputs ----------------
__global__ void init_kernel(const float* __restrict__ enc,
                            const int* __restrict__ captions, const int* __restrict__ cap_len,
                            float* __restrict__ out)
{
    int idx = blockIdx.x * blockDim.x + threadIdx.x;
    int stride = gridDim.x * blockDim.x;
    for (int i = idx; i < BATCH * PIX * ENC; i += stride)
        g_enc_h[i] = __float2half_rn(enc[i]);
    for (int i = idx; i < 8 * ENC; i += stride)
        g_enc_h[BATCH * PIX * ENC + i] = __ushort_as_half(0);
    // WfcT pad rows [VOC, NPAD)
    for (int i = idx; i < (NPAD - VOC) * DEC; i += stride)
        g_WfcT[(size_t)VOC * DEC + i] = __ushort_as_half(0);
    if (idx < TSTEPS * BATCH) {
        int t = idx / BATCH, b = idx - t * BATCH;
        g_mask[idx] = (t < cap_len[b] - 1) ? 1.f : 0.f;
    }
    if (idx < BATCH * MAXLEN) out[CAP_OFF + idx] = (float)captions[idx];
    if (idx < BATCH)          out[LEN_OFF + idx] = (float)(cap_len[idx] - 1);
}

__global__ void mean_kernel(const float* __restrict__ enc)
{
    int b = blockIdx.y;
    int d = blockIdx.x * 256 + threadIdx.x;
    const float* ep = enc + (size_t)b * PIX * ENC + d;
    float s = 0.f;
    for (int p = 0; p < PIX; p++) s += ep[(size_t)p * ENC];
    g_mean16[b * ENC + d] = __float2half_rn(s * (1.f / (float)PIX));
}

// ---------------- host launcher ----------------
extern "C" void kernel_launch(void* const* d_in, const int* in_sizes, int n_in,
                              void* d_out, int out_size)
{
    const float* enc        = (const float*)d_in[0];
    const int*   captions   = (const int*)  d_in[1];
    const int*   cap_len    = (const int*)  d_in[2];
    const float* emb        = (const float*)d_in[3];
    const float* W_enc_att  = (const float*)d_in[4];
    const float* b_enc_att  = (const float*)d_in[5];
    const float* W_dec_att  = (const float*)d_in[6];
    const float* b_dec_att  = (const float*)d_in[7];
    const float* W_full_att = (const float*)d_in[8];
    const float* b_full_att = (const float*)d_in[9];
    const float* W_init_h   = (const float*)d_in[10];
    const float* b_init_h   = (const float*)d_in[11];
    const float* W_init_c   = (const float*)d_in[12];
    const float* b_init_c   = (const float*)d_in[13];
    const float* W_fbeta    = (const float*)d_in[14];
    const float* b_fbeta    = (const float*)d_in[15];
    const float* W_ih       = (const float*)d_in[16];
    const float* W_hh       = (const float*)d_in[17];
    const float* b_ih       = (const float*)d_in[18];
    const float* b_hh       = (const float*)d_in[19];
    const float* W_fc       = (const float*)d_in[20];
    const float* b_fc       = (const float*)d_in[21];
    float* out = (float*)d_out;
    (void)in_sizes; (void)n_in; (void)out_size;

    float* pmask;
    unsigned* pbar;
    __half *pWhcatT, *pWihT, *pWencT, *pWfcT, *pWinitT;
    cudaGetSymbolAddress((void**)&pmask,   g_mask);
    cudaGetSymbolAddress((void**)&pbar,    g_barcnt);
    cudaGetSymbolAddress((void**)&pWhcatT, g_WhcatT);
    cudaGetSymbolAddress((void**)&pWihT,   g_WihT);
    cudaGetSymbolAddress((void**)&pWencT,  g_WencT);
    cudaGetSymbolAddress((void**)&pWfcT,   g_WfcT);
    cudaGetSymbolAddress((void**)&pWinitT, g_WinitT);

    cudaMemsetAsync(pbar, 0, sizeof(unsigned));

    // coalesced tiled transposes (fp32 -> fp16, [K][N] -> [N][ldd])
    transpose_f2h_kernel<<<dim3(512 / 32, 512 / 32), 256>>>(W_dec_att, pWhcatT, 512, 512, 512);
    transpose_f2h_kernel<<<dim3(2048 / 32, 512 / 32), 256>>>(W_fbeta, pWhcatT + 512 * 512, 512, 2048, 512);
    transpose_f2h_kernel<<<dim3(2048 / 32, 2560 / 32), 256>>>(W_ih, pWihT, 2560, 2048, XDIM2);
    transpose_f2h_kernel<<<dim3(2048 / 32, 512 / 32), 256>>>(W_hh, pWihT + 2560, 512, 2048, XDIM2);
    transpose_f2h_kernel<<<dim3(512 / 32, 2048 / 32), 256>>>(W_enc_att, pWencT, 2048, 512, 2048);
    transpose_f2h_kernel<<<dim3((VOC + 31) / 32, 512 / 32), 256>>>(W_fc, pWfcT, 512, VOC, 512);
    transpose_f2h_kernel<<<dim3(512 / 32, 2048 / 32), 256>>>(W_init_h, pWinitT, 2048, 512, 2048);
    transpose_f2h_kernel<<<dim3(512 / 32, 2048 / 32), 256>>>(W_init_c, pWinitT + 512 * 2048, 2048, 512, 2048);

    // init (enc fp16, pads, mask, int outputs)
    init_kernel<<<4096, 256>>>(enc, captions, cap_len, out);
    // mean over pixels (fp16 out)
    mean_kernel<<<dim3(ENC / 256, BATCH), 256>>>(enc);
    // att_enc = enc @ W_enc_att + b (HMMA, fp16 out)
    attenc_mma_kernel<<<dim3(ATT / 128, (BATCH * PIX) / 64), 256>>>(b_enc_att);
    // entire decode loop (persistent, 296 blocks = 2/SM)
    decode_loop_kernel<<<NBLK, 256>>>(b_dec_att, W_full_att, b_full_att, b_fbeta,
                                      emb, captions, cap_len,
                                      b_ih, b_hh, b_init_h, b_init_c, out);
    // all predictions (HMMA)
    preds_mma_kernel<<<dim3(NPAD / 128, MTOT / 64), 256>>>(b_fc, pmask, out);
}

// round 13
// speedup vs baseline: 1.8813x; 1.3504x over previous
#include <cuda_runtime.h>
#include <cuda_fp16.h>
#include <math.h>
#include <stdint.h>

// Problem constants
#define BATCH   64
#define PIX     196
#define ENC     2048
#define DEC     512
#define ATT     512
#define EMBD    512
#define VOC     10000
#define MAXLEN  52
#define TSTEPS  51
#define HCAT2   2560     // 512 dec_att | 2048 fbeta
#define XDIM2   3072     // emb 512 | awe 2048 | h 512
#define GDIM    2048     // 4*DEC

// Output layout (flattened tuple, float32)
#define PRED_OFF   0
#define CAP_OFF    32640000
#define LEN_OFF    32643328
#define ALPHA_OFF  32643392

#define HSPLIT  4
#define GSPLITA 8
#define GSPLITB 16
#define ISPLIT  8

#define MTOT  (TSTEPS * BATCH)   // 3264
#define NPAD  10112              // 79*128 >= VOC
#define NBLK  296                // persistent grid: 2 blocks/SM

#define SWS   136                // persistent weight tile row stride (halfs)
#define SWT   (128 * SWS)        // 17408 halfs per 128x128 tile

// ---------------- scratch ----------------
__device__ __align__(16) __half g_WhcatT[HCAT2 * DEC];    // [n][k]
__device__ __align__(16) __half g_WihT[GDIM * XDIM2];     // [n][k] (W_ih|W_hh)
__device__ __align__(16) __half g_WencT[ATT * ENC];       // [n][k]
__device__ __align__(16) __half g_WfcT[NPAD * DEC];       // [n][k]
__device__ __align__(16) __half g_WinitT[1024 * ENC];     // [n][k] (h0|c0)
__device__ __align__(16) __half g_enc_h[(BATCH * PIX + 8) * ENC];
__device__ __align__(16) __half g_mean16[BATCH * ENC];
__device__ __align__(16) __half g_h16cur[BATCH * DEC];
__device__ __align__(16) __half g_h16[MTOT * DEC];
__device__ __align__(16) __half g_x16[BATCH * XDIM2];
__device__ __align__(16) __half g_att_enc16[BATCH * PIX * ATT];
__device__ float  g_mask[TSTEPS * BATCH];
__device__ float  g_c[BATCH * DEC];
__device__ float  g_hpart[HSPLIT * BATCH * HCAT2];
__device__ float  g_gpartA[GSPLITA * BATCH * GDIM];
__device__ float  g_gpartB[GSPLITB * BATCH * GDIM];
__device__ float  g_ipart[ISPLIT * BATCH * 1024];
__device__ float  g_e[BATCH * PIX];

__device__ unsigned g_barcnt;

__device__ __forceinline__ float sigmoidf_(float x) { return 1.f / (1.f + __expf(-x)); }
__device__ __forceinline__ float tanh_fast(float x) {
    float y; asm("tanh.approx.f32 %0, %1;" : "=f"(y) : "f"(x)); return y;
}

// monotonic grid barrier: release-arrival, acquire-poll
__device__ __forceinline__ void gbar(unsigned& nbar) {
    nbar += NBLK;
    __syncthreads();
    if (threadIdx.x == 0) {
        asm volatile("red.release.gpu.global.add.u32 [%0], 1;" :: "l"(&g_barcnt) : "memory");
        unsigned v;
        do {
            asm volatile("ld.acquire.gpu.u32 %0, [%1];" : "=r"(v) : "l"(&g_barcnt) : "memory");
        } while ((int)(v - nbar) < 0);
    }
    __syncthreads();
}

#define MMA_OP(c, a, b0, b1) \
    asm volatile("mma.sync.aligned.m16n8k16.row.col.f32.f16.f16.f32 " \
        "{%0,%1,%2,%3}, {%4,%5,%6,%7}, {%8,%9}, {%0,%1,%2,%3};" \
        : "+f"((c)[0]), "+f"((c)[1]), "+f"((c)[2]), "+f"((c)[3]) \
        : "r"((a)[0]), "r"((a)[1]), "r"((a)[2]), "r"((a)[3]), "r"(b0), "r"(b1))

// ---------------- HMMA 64x128 core: A+B streamed from global (prologue kernels) ----
__device__ __forceinline__ void hmma_core(
    const __half* __restrict__ Ag, int lda,
    const __half* __restrict__ Bg, int ldb,
    int n0, int koff, int nsteps,
    __half* sAh, __half* sBh, int tid,
    float (&c)[2][4][4])
{
    const int wid  = tid >> 5;
    const int lane = tid & 31;
    const int grp  = lane >> 2;
    const int tg   = lane & 3;
    const int wm   = wid >> 2;
    const int wn   = wid & 3;
    const int arow = tid >> 2;
    const int aseg = (tid & 3) * 8;

    const __half* Ap = Ag + (size_t)arow * lda + koff + aseg;
    const __half* Bp = Bg + (size_t)(n0 + arow) * ldb + koff + aseg;
    const size_t boff = (size_t)64 * ldb;

#pragma unroll
    for (int i = 0; i < 2; i++)
#pragma unroll
        for (int j = 0; j < 4; j++)
#pragma unroll
            for (int q = 0; q < 4; q++) c[i][j][q] = 0.f;

    uint4 ra  = *(const uint4*)Ap;
    uint4 rb0 = *(const uint4*)Bp;
    uint4 rb1 = *(const uint4*)(Bp + boff);
    *(uint4*)&sAh[arow * 40 + aseg]        = ra;
    *(uint4*)&sBh[arow * 40 + aseg]        = rb0;
    *(uint4*)&sBh[(arow + 64) * 40 + aseg] = rb1;
    __syncthreads();

    for (int kt = 0; kt < nsteps; kt++) {
        const int cur = kt & 1;
        const __half* cA = sAh + cur * (64 * 40);
        const __half* cB = sBh + cur * (128 * 40);

        if (kt + 1 < nsteps) {
            const int kb = (kt + 1) * 32;
            ra  = *(const uint4*)(Ap + kb);
            rb0 = *(const uint4*)(Bp + kb);
            rb1 = *(const uint4*)(Bp + boff + kb);
        }

#pragma unroll
        for (int ks = 0; ks < 2; ks++) {
            const int k0 = ks * 16;
            uint32_t a[2][4];
#pragma unroll
            for (int mi = 0; mi < 2; mi++) {
                const int r = wm * 32 + mi * 16 + grp;
                a[mi][0] = *(const uint32_t*)&cA[(r    ) * 40 + k0 + tg * 2];
                a[mi][1] = *(const uint32_t*)&cA[(r + 8) * 40 + k0 + tg * 2];
                a[mi][2] = *(const uint32_t*)&cA[(r    ) * 40 + k0 + tg * 2 + 8];
                a[mi][3] = *(const uint32_t*)&cA[(r + 8) * 40 + k0 + tg * 2 + 8];
            }
#pragma unroll
            for (int ni = 0; ni < 4; ni++) {
                const int nr = wn * 32 + ni * 8 + grp;
                uint32_t b0 = *(const uint32_t*)&cB[nr * 40 + k0 + tg * 2];
                uint32_t b1 = *(const uint32_t*)&cB[nr * 40 + k0 + tg * 2 + 8];
#pragma unroll
                for (int mi = 0; mi < 2; mi++) MMA_OP(c[mi][ni], a[mi], b0, b1);
            }
        }

        if (kt + 1 < nsteps) {
            const int nxt = cur ^ 1;
            __half* nA = sAh + nxt * (64 * 40);
            __half* nB = sBh + nxt * (128 * 40);
            *(uint4*)&nA[arow * 40 + aseg]        = ra;
            *(uint4*)&nB[arow * 40 + aseg]        = rb0;
            *(uint4*)&nB[(arow + 64) * 40 + aseg] = rb1;
            __syncthreads();
        }
    }
}

__device__ __forceinline__ void hmma_store(
    float (&c)[2][4][4], float* __restrict__ Cg, int ldc, int n0,
    const float* __restrict__ bias, int tid)
{
    const int wid  = tid >> 5;
    const int lane = tid & 31;
    const int grp  = lane >> 2;
    const int tg   = lane & 3;
    const int wm   = wid >> 2;
    const int wn   = wid & 3;
#pragma unroll
    for (int mi = 0; mi < 2; mi++) {
#pragma unroll
        for (int hh = 0; hh < 2; hh++) {
            const int row = wm * 32 + mi * 16 + grp + hh * 8;
            float* crow = Cg + (size_t)row * ldc;
#pragma unroll
            for (int ni = 0; ni < 4; ni++) {
                const int col = n0 + wn * 32 + ni * 8 + tg * 2;
                float v0 = c[mi][ni][hh * 2];
                float v1 = c[mi][ni][hh * 2 + 1];
                if (bias) { v0 += bias[col]; v1 += bias[col + 1]; }
                crow[col]     = v0;
                crow[col + 1] = v1;
            }
        }
    }
}

__device__ __forceinline__ void hmma_tile(
    const __half* __restrict__ Ag, int lda,
    const __half* __restrict__ Bg, int ldb,
    float* __restrict__ Cg, int ldc,
    int n0, int koff, int nsteps,
    const float* __restrict__ bias,
    __half* sAh, __half* sBh, int tid)
{
    float c[2][4][4];
    hmma_core(Ag, lda, Bg, ldb, n0, koff, nsteps, sAh, sBh, tid, c);
    hmma_store(c, Cg, ldc, n0, bias, tid);
}

// ---------------- HMMA 64x128, B resident in smem (128x128 tile, K=128 fixed) ------
__device__ __forceinline__ void hmma_smemB(
    const __half* __restrict__ Ag, int lda, int koff,
    const __half* __restrict__ sW,     // 128 x SWS
    float* __restrict__ Cg, int ldc, int n0,
    __half* sAh, int tid)
{
    const int wid  = tid >> 5;
    const int lane = tid & 31;
    const int grp  = lane >> 2;
    const int tg   = lane & 3;
    const int wm   = wid >> 2;
    const int wn   = wid & 3;
    const int arow = tid >> 2;
    const int aseg = (tid & 3) * 8;

    const __half* Ap = Ag + (size_t)arow * lda + koff + aseg;

    float c[2][4][4];
#pragma unroll
    for (int i = 0; i < 2; i++)
#pragma unroll
        for (int j = 0; j < 4; j++)
#pragma unroll
            for (int q = 0; q < 4; q++) c[i][j][q] = 0.f;

    uint4 ra = *(const uint4*)Ap;
    *(uint4*)&sAh[arow * 40 + aseg] = ra;
    __syncthreads();

#pragma unroll
    for (int kt = 0; kt < 4; kt++) {
        const int cur = kt & 1;
        const __half* cA = sAh + cur * (64 * 40);
        if (kt < 3) ra = *(const uint4*)(Ap + (kt + 1) * 32);

#pragma unroll
        for (int ks = 0; ks < 2; ks++) {
            const int k0 = ks * 16;          // within A chunk
            const int kW = kt * 32 + k0;     // within 128-wide B tile
            uint32_t a[2][4];
#pragma unroll
            for (int mi = 0; mi < 2; mi++) {
                const int r = wm * 32 + mi * 16 + grp;
                a[mi][0] = *(const uint32_t*)&cA[(r    ) * 40 + k0 + tg * 2];
                a[mi][1] = *(const uint32_t*)&cA[(r + 8) * 40 + k0 + tg * 2];
                a[mi][2] = *(const uint32_t*)&cA[(r    ) * 40 + k0 + tg * 2 + 8];
                a[mi][3] = *(const uint32_t*)&cA[(r + 8) * 40 + k0 + tg * 2 + 8];
            }
#pragma unroll
            for (int ni = 0; ni < 4; ni++) {
                const int nr = wn * 32 + ni * 8 + grp;
                uint32_t b0 = *(const uint32_t*)&sW[nr * SWS + kW + tg * 2];
                uint32_t b1 = *(const uint32_t*)&sW[nr * SWS + kW + tg * 2 + 8];
#pragma unroll
                for (int mi = 0; mi < 2; mi++) MMA_OP(c[mi][ni], a[mi], b0, b1);
            }
        }

        if (kt < 3) {
            const int nxt = cur ^ 1;
            *(uint4*)&sAh[nxt * (64 * 40) + arow * 40 + aseg] = ra;
            __syncthreads();
        }
    }

    hmma_store(c, Cg, ldc, n0, nullptr, tid);
}

// load a 128x128 weight tile into persistent smem (stride SWS)
__device__ __forceinline__ void load_wtile(const __half* __restrict__ src, int lds,
                                           __half* dst, int tid)
{
#pragma unroll
    for (int j = 0; j < 8; j++) {
        const int u = tid + j * 256;
        const int r = u >> 4, seg = (u & 15) * 8;
        *(uint4*)&dst[r * SWS + seg] = *(const uint4*)&src[(size_t)r * lds + seg];
    }
}

// ============ persistent decode-loop kernel (296 blocks, 2/SM, dynamic smem) ========
__global__ void __launch_bounds__(256, 2)
decode_loop_kernel(const float* __restrict__ b_dec_att, const float* __restrict__ Wf,
                   const float* __restrict__ bf, const float* __restrict__ b_fbeta,
                   const float* __restrict__ emb, const int* __restrict__ captions,
                   const int* __restrict__ cap_len,
                   const float* __restrict__ b_ih, const float* __restrict__ b_hh,
                   const float* __restrict__ b_init_h, const float* __restrict__ b_init_c,
                   float* __restrict__ out)
{
    extern __shared__ __half dyn[];
    __half* sAh  = dyn;                  // 2*64*40 = 5120 halfs
    __half* sWp1 = dyn + 5120;           // SWT halfs
    __half* sWp4 = sWp1 + SWT;           // SWT halfs
    __shared__ float sdec[ATT];
    __shared__ float swf[ATT];
    __shared__ float sred[256];
    __shared__ float salpha[256];

    const int bid = blockIdx.x;
    const int tid = threadIdx.x;
    unsigned nbar = 0;

    // ---- pre-phase A: h0/c0 partials (64 blocks); sWp1 used as B scratch ----
    if (bid < 64) {
        const int nt = bid & 7, z = bid >> 3;
        hmma_tile(g_mean16, ENC, g_WinitT, ENC,
                  g_ipart + (size_t)z * 64 * 1024, 1024,
                  nt * 128, z * 256, 8, nullptr, sAh, sWp1, tid);
    }
    gbar(nbar);

    // ---- pre-phase B: load persistent weight tiles; reduce h0/c0; emb t=0 ----
    if (bid < 80) {
        const int nt = bid / HSPLIT, z = bid - (bid / HSPLIT) * HSPLIT;
        load_wtile(g_WhcatT + (size_t)(nt * 128) * DEC + z * 128, DEC, sWp1, tid);
    } else if (bid < 208) {
        const int idx = bid - 80, nt = idx & 15, cc = idx >> 4;
        const int koff = (cc < 4) ? cc * 128 : (EMBD + ENC) + (cc - 4) * 128;
        load_wtile(g_WihT + (size_t)(nt * 128) * XDIM2 + koff, XDIM2, sWp1, tid);
    }
    if (bid < 256) {
        const int nt = bid & 15, z = bid >> 4;
        load_wtile(g_WihT + (size_t)(nt * 128) * XDIM2 + EMBD + z * 128, XDIM2, sWp4, tid);
    }
    if (bid < 64) {
        const int b = bid;
#pragma unroll
        for (int jj = 0; jj < 4; jj++) {
            const int col = tid + jj * 256;
            float v = 0.f;
#pragma unroll
            for (int z = 0; z < ISPLIT; z++) v += g_ipart[(size_t)(z * BATCH + b) * 1024 + col];
            if (col < DEC) {
                __half hv = __float2half_rn(v + b_init_h[col]);
                g_h16cur[b * DEC + col] = hv;
                g_x16[b * XDIM2 + EMBD + ENC + col] = hv;
            } else {
                g_c[b * DEC + (col - DEC)] = v + b_init_c[col - DEC];
            }
        }
        const int tok = captions[b * MAXLEN + 0];
        float2 v = *(const float2*)&emb[(size_t)tok * EMBD + tid * 2];
        *(__half2*)&g_x16[b * XDIM2 + tid * 2] = __floats2half2_rn(v.x, v.y);
    }
    gbar(nbar);

    for (int t = 0; t < TSTEPS; t++) {
        // ---- phase 1: hproj (80 blocks) + gates part-A (128 blocks); B in smem ----
        if (bid < 80) {
            const int nt = bid / HSPLIT, z = bid - nt * HSPLIT;
            hmma_smemB(g_h16cur, DEC, z * 128, sWp1,
                       g_hpart + (size_t)z * 64 * HCAT2, HCAT2, nt * 128, sAh, tid);
        } else if (bid < 208) {
            const int idx = bid - 80, nt = idx & 15, cc = idx >> 4;
            const int koff = (cc < 4) ? cc * 128 : (EMBD + ENC) + (cc - 4) * 128;
            hmma_smemB(g_x16, XDIM2, koff, sWp1,
                       g_gpartA + (size_t)cc * 64 * GDIM, GDIM, nt * 128, sAh, tid);
        }
        gbar(nbar);

        // ---- phase 2: attention scores (256 blocks; 4 per b, 49 pixels) ----
        if (bid < 256) {
            const int b = bid >> 2, q = bid & 3;
            for (int k = tid; k < ATT; k += 256) {
                float s = b_dec_att[k];
#pragma unroll
                for (int z = 0; z < HSPLIT; z++)
                    s += g_hpart[(size_t)(z * BATCH + b) * HCAT2 + k];
                sdec[k] = s;
                swf[k] = Wf[k];
            }
            __syncthreads();
            const int warp = tid >> 5, lane = tid & 31;
            const float bf0 = bf[0];
            const int pbase = q * 49;
            for (int p = pbase + warp; p < pbase + 49; p += 8) {
                const __half2* ae = (const __half2*)(g_att_enc16 + (size_t)(b * PIX + p) * ATT);
                float acc = 0.f;
#pragma unroll
                for (int kk = 0; kk < 8; kk++) {
                    const int idx = lane + kk * 32;
                    __half2 a2 = ae[idx];
                    const int k0 = idx * 2;
                    acc += tanh_fast(__low2float(a2)  + sdec[k0])     * swf[k0];
                    acc += tanh_fast(__high2float(a2) + sdec[k0 + 1]) * swf[k0 + 1];
                }
#pragma unroll
                for (int o = 16; o; o >>= 1) acc += __shfl_down_sync(0xffffffffu, acc, o);
                if (lane == 0) g_e[b * PIX + p] = acc + bf0;
            }
        }
        gbar(nbar);

        // ---- phase 3: softmax + awe + x16 awe-slot (256 blocks; 4 per b) ----
        if (bid < 256) {
            const int b = bid >> 2, chunk = bid & 3;
            float v = (tid < PIX) ? g_e[b * PIX + tid] : -1e30f;
            sred[tid] = v; __syncthreads();
            for (int s = 128; s; s >>= 1) { if (tid < s) sred[tid] = fmaxf(sred[tid], sred[tid+s]); __syncthreads(); }
            const float mx = sred[0]; __syncthreads();
            const float ex = (tid < PIX) ? __expf(v - mx) : 0.f;
            sred[tid] = ex; __syncthreads();
            for (int s = 128; s; s >>= 1) { if (tid < s) sred[tid] += sred[tid+s]; __syncthreads(); }
            const float inv = 1.f / sred[0];
            const float a = ex * inv;
            salpha[tid] = a;
            if (chunk == 0 && tid < PIX) {
                const float m = (t < cap_len[b] - 1) ? 1.f : 0.f;
                out[ALPHA_OFF + (size_t)b * TSTEPS * PIX + (size_t)t * PIX + tid] = a * m;
            }
            __syncthreads();

            const int d = chunk * 512 + tid * 2;
            float ax = 0.f, ay = 0.f;
            const __half* ep = g_enc_h + (size_t)b * PIX * ENC + d;
#pragma unroll 16
            for (int p = 0; p < 200; p++) {
                const float al = salpha[p];
                __half2 h2 = *(const __half2*)(ep + (size_t)p * ENC);
                ax = fmaf(al, __low2float(h2),  ax);
                ay = fmaf(al, __high2float(h2), ay);
            }
            float gx = b_fbeta[d], gy = b_fbeta[d + 1];
#pragma unroll
            for (int z = 0; z < HSPLIT; z++) {
                float2 p2 = *(const float2*)&g_hpart[(size_t)(z * BATCH + b) * HCAT2 + DEC + d];
                gx += p2.x; gy += p2.y;
            }
            gx = sigmoidf_(gx); gy = sigmoidf_(gy);
            *(__half2*)&g_x16[b * XDIM2 + EMBD + d] = __floats2half2_rn(ax * gx, ay * gy);
        }
        gbar(nbar);

        // ---- phase 4: gates part-B over awe (256 blocks, split-K 16; B in smem) ----
        if (bid < 256) {
            const int nt = bid & 15, z = bid >> 4;
            hmma_smemB(g_x16, XDIM2, EMBD + z * 128, sWp4,
                       g_gpartB + (size_t)z * 64 * GDIM, GDIM, nt * 128, sAh, tid);
        }
        gbar(nbar);

        // ---- phase 5: LSTM update (128 blocks; 2 per b) + emb prefetch t+1 ----
        if (bid < 128) {
            const int b = bid >> 1, half = bid & 1;
            const int j = half * 256 + tid;
            float gv[4];
#pragma unroll
            for (int s = 0; s < 4; s++) {
                const int col = s * DEC + j;
                float v = b_ih[col] + b_hh[col];
#pragma unroll
                for (int z = 0; z < GSPLITA; z++)
                    v += g_gpartA[(size_t)(z * BATCH + b) * GDIM + col];
#pragma unroll
                for (int z = 0; z < GSPLITB; z++)
                    v += g_gpartB[(size_t)(z * BATCH + b) * GDIM + col];
                gv[s] = v;
            }
            float h = __half2float(g_h16cur[b * DEC + j]);
            if (t < cap_len[b] - 1) {
                const float c_old = g_c[b * DEC + j];
                const float cn = sigmoidf_(gv[1]) * c_old + sigmoidf_(gv[0]) * tanhf(gv[2]);
                g_c[b * DEC + j] = cn;
                h = sigmoidf_(gv[3]) * tanhf(cn);
            }
            __half hv = __float2half_rn(h);
            g_h16cur[b * DEC + j] = hv;
            g_x16[b * XDIM2 + EMBD + ENC + j] = hv;
            g_h16[((size_t)t * BATCH + b) * DEC + j] = hv;

            if (half == 1 && t + 1 < TSTEPS) {
                const int tok = captions[b * MAXLEN + t + 1];
                float2 v = *(const float2*)&emb[(size_t)tok * EMBD + tid * 2];
                *(__half2*)&g_x16[b * XDIM2 + tid * 2] = __floats2half2_rn(v.x, v.y);
            }
        }
        gbar(nbar);
    }
}

// ============ prologue att_enc GEMM via HMMA -> fp16 output ============
__global__ void __launch_bounds__(256)
attenc_mma_kernel(const float* __restrict__ b_enc_att)
{
    __shared__ __half sAh[2 * 64 * 40];
    __shared__ __half sBh[2 * 128 * 40];
    const int tid = threadIdx.x;
    const int m0 = blockIdx.y * 64;
    const int n0 = blockIdx.x * 128;

    float c[2][4][4];
    hmma_core(g_enc_h + (size_t)m0 * ENC, ENC, g_WencT, ENC,
              n0, 0, ENC / 32, sAh, sBh, tid, c);

    const int wid  = tid >> 5;
    const int lane = tid & 31;
    const int grp  = lane >> 2;
    const int tg   = lane & 3;
    const int wm   = wid >> 2;
    const int wn   = wid & 3;

#pragma unroll
    for (int mi = 0; mi < 2; mi++) {
#pragma unroll
        for (int hh = 0; hh < 2; hh++) {
            const int row = wm * 32 + mi * 16 + grp + hh * 8;
            __half* crow = g_att_enc16 + (size_t)(m0 + row) * ATT;
#pragma unroll
            for (int ni = 0; ni < 4; ni++) {
                const int col = n0 + wn * 32 + ni * 8 + tg * 2;
                float v0 = c[mi][ni][hh * 2]     + b_enc_att[col];
                float v1 = c[mi][ni][hh * 2 + 1] + b_enc_att[col + 1];
                *(__half2*)&crow[col] = __floats2half2_rn(v0, v1);
            }
        }
    }
}

// ============ batched predictions via HMMA (bias+mask epilogue) ============
__global__ void __launch_bounds__(256)
preds_mma_kernel(const float* __restrict__ b_fc, const float* __restrict__ mask,
                 float* __restrict__ out)
{
    __shared__ __half sAh[2 * 64 * 40];
    __shared__ __half sBh[2 * 128 * 40];

    const int tid = threadIdx.x;
    const int m0 = blockIdx.y * 64;
    const int n0 = blockIdx.x * 128;

    float c[2][4][4];
    hmma_core(g_h16 + (size_t)m0 * DEC, DEC, g_WfcT, DEC,
              n0, 0, DEC / 32, sAh, sBh, tid, c);

    const int wid  = tid >> 5;
    const int lane = tid & 31;
    const int grp  = lane >> 2;
    const int tg   = lane & 3;
    const int wm   = wid >> 2;
    const int wn   = wid & 3;

#pragma unroll
    for (int mi = 0; mi < 2; mi++) {
#pragma unroll
        for (int hh = 0; hh < 2; hh++) {
            const int m = m0 + wm * 32 + mi * 16 + grp + hh * 8;
            const int tt = m >> 6, bb = m & 63;
            const float ms = mask[tt * BATCH + bb];
            float* orow = out + PRED_OFF + ((size_t)bb * TSTEPS + tt) * VOC;
#pragma unroll
            for (int ni = 0; ni < 4; ni++) {
                const int n = n0 + wn * 32 + ni * 8 + tg * 2;
                if (n + 1 < VOC) {
                    orow[n]     = (c[mi][ni][hh * 2]     + b_fc[n])     * ms;
                    orow[n + 1] = (c[mi][ni][hh * 2 + 1] + b_fc[n + 1]) * ms;
                } else if (n < VOC) {
                    orow[n] = (c[mi][ni][hh * 2] + b_fc[n]) * ms;
                }
            }
        }
    }
}

// ---------------- tiled transpose: src fp32 [K][N] -> dst fp16 [N][ldd] ----------
__global__ void transpose_f2h_kernel(const float* __restrict__ src, __half* __restrict__ dst,
                                     int K, int N, int ldd)
{
    __shared__ float tile[32][33];
    const int kb = blockIdx.y * 32, nb = blockIdx.x * 32;
    const int tx = threadIdx.x & 31, ty = threadIdx.x >> 5;
#pragma unroll
    for (int i = 0; i < 32; i += 8) {
        const int k = kb + ty + i, n = nb + tx;
        tile[ty + i][tx] = (k < K && n < N) ? src[(size_t)k * N + n] : 0.f;
    }
    __syncthreads();
#pragma unroll
    for (int i = 0; i < 32; i += 8) {
        const int n = nb + ty + i, k = kb + tx;
        if (n < N && k < K)
            dst[(size_t)n * ldd + k] = __float2half_rn(tile[tx][ty + i]);
    }
}

// ---------------- init: enc fp16, pads, mask, int outputs ----------------
__global__ void init_kernel(const float* __restrict__ enc,
                            const int* __restrict__ captions, const int* __restrict__ cap_len,
                            float* __restrict__ out)
{
    int idx = blockIdx.x * blockDim.x + threadIdx.x;
    int stride = gridDim.x * blockDim.x;
    for (int i = idx; i < BATCH * PIX * ENC; i += stride)
        g_enc_h[i] = __float2half_rn(enc[i]);
    for (int i = idx; i < 8 * ENC; i += stride)
        g_enc_h[BATCH * PIX * ENC + i] = __ushort_as_half(0);
    for (int i = idx; i < (NPAD - VOC) * DEC; i += stride)
        g_WfcT[(size_t)VOC * DEC + i] = __ushort_as_half(0);
    if (idx < TSTEPS * BATCH) {
        int t = idx / BATCH, b = idx - t * BATCH;
        g_mask[idx] = (t < cap_len[b] - 1) ? 1.f : 0.f;
    }
    if (idx < BATCH * MAXLEN) out[CAP_OFF + idx] = (float)captions[idx];
    if (idx < BATCH)          out[LEN_OFF + idx] = (float)(cap_len[idx] - 1);
}

__global__ void mean_kernel(const float* __restrict__ enc)
{
    int b = blockIdx.y;
    int d = blockIdx.x * 256 + threadIdx.x;
    const float* ep = enc + (size_t)b * PIX * ENC + d;
    float s = 0.f;
    for (int p = 0; p < PIX; p++) s += ep[(size_t)p * ENC];
    g_mean16[b * ENC + d] = __float2half_rn(s * (1.f / (float)PIX));
}

// ---------------- host launcher ----------------
extern "C" void kernel_launch(void* const* d_in, const int* in_sizes, int n_in,
                              void* d_out, int out_size)
{
    const float* enc        = (const float*)d_in[0];
    const int*   captions   = (const int*)  d_in[1];
    const int*   cap_len    = (const int*)  d_in[2];
    const float* emb        = (const float*)d_in[3];
    const float* W_enc_att  = (const float*)d_in[4];
    const float* b_enc_att  = (const float*)d_in[5];
    const float* W_dec_att  = (const float*)d_in[6];
    const float* b_dec_att  = (const float*)d_in[7];
    const float* W_full_att = (const float*)d_in[8];
    const float* b_full_att = (const float*)d_in[9];
    const float* W_init_h   = (const float*)d_in[10];
    const float* b_init_h   = (const float*)d_in[11];
    const float* W_init_c   = (const float*)d_in[12];
    const float* b_init_c   = (const float*)d_in[13];
    const float* W_fbeta    = (const float*)d_in[14];
    const float* b_fbeta    = (const float*)d_in[15];
    const float* W_ih       = (const float*)d_in[16];
    const float* W_hh       = (const float*)d_in[17];
    const float* b_ih       = (const float*)d_in[18];
    const float* b_hh       = (const float*)d_in[19];
    const float* W_fc       = (const float*)d_in[20];
    const float* b_fc       = (const float*)d_in[21];
    float* out = (float*)d_out;
    (void)in_sizes; (void)n_in; (void)out_size;

    float* pmask;
    unsigned* pbar;
    __half *pWhcatT, *pWihT, *pWencT, *pWfcT, *pWinitT;
    cudaGetSymbolAddress((void**)&pmask,   g_mask);
    cudaGetSymbolAddress((void**)&pbar,    g_barcnt);
    cudaGetSymbolAddress((void**)&pWhcatT, g_WhcatT);
    cudaGetSymbolAddress((void**)&pWihT,   g_WihT);
    cudaGetSymbolAddress((void**)&pWencT,  g_WencT);
    cudaGetSymbolAddress((void**)&pWfcT,   g_WfcT);
    cudaGetSymbolAddress((void**)&pWinitT, g_WinitT);

    cudaMemsetAsync(pbar, 0, sizeof(unsigned));

    // coalesced tiled transposes (fp32 -> fp16, [K][N] -> [N][ldd])
    transpose_f2h_kernel<<<dim3(512 / 32, 512 / 32), 256>>>(W_dec_att, pWhcatT, 512, 512, 512);
    transpose_f2h_kernel<<<dim3(2048 / 32, 512 / 32), 256>>>(W_fbeta, pWhcatT + 512 * 512, 512, 2048, 512);
    transpose_f2h_kernel<<<dim3(2048 / 32, 2560 / 32), 256>>>(W_ih, pWihT, 2560, 2048, XDIM2);
    transpose_f2h_kernel<<<dim3(2048 / 32, 512 / 32), 256>>>(W_hh, pWihT + 2560, 512, 2048, XDIM2);
    transpose_f2h_kernel<<<dim3(512 / 32, 2048 / 32), 256>>>(W_enc_att, pWencT, 2048, 512, 2048);
    transpose_f2h_kernel<<<dim3((VOC + 31) / 32, 512 / 32), 256>>>(W_fc, pWfcT, 512, VOC, 512);
    transpose_f2h_kernel<<<dim3(512 / 32, 2048 / 32), 256>>>(W_init_h, pWinitT, 2048, 512, 2048);
    transpose_f2h_kernel<<<dim3(512 / 32, 2048 / 32), 256>>>(W_init_c, pWinitT + 512 * 2048, 2048, 512, 2048);

    init_kernel<<<4096, 256>>>(enc, captions, cap_len, out);
    mean_kernel<<<dim3(ENC / 256, BATCH), 256>>>(enc);
    attenc_mma_kernel<<<dim3(ATT / 128, (BATCH * PIX) / 64), 256>>>(b_enc_att);

    // persistent decode loop with resident weight tiles (dynamic smem ~80KB)
    const int dyn_smem = (5120 + 2 * SWT) * (int)sizeof(__half);
    cudaFuncSetAttribute(decode_loop_kernel,
                         cudaFuncAttributeMaxDynamicSharedMemorySize, dyn_smem);
    decode_loop_kernel<<<NBLK, 256, dyn_smem>>>(b_dec_att, W_full_att, b_full_att, b_fbeta,
                                                emb, captions, cap_len,
                                                b_ih, b_hh, b_init_h, b_init_c, out);

    preds_mma_kernel<<<dim3(NPAD / 128, MTOT / 64), 256>>>(b_fc, pmask, out);
}

// round 14
// speedup vs baseline: 2.0227x; 1.0751x over previous
#include <cuda_runtime.h>
#include <cuda_fp16.h>
#include <math.h>
#include <stdint.h>

// Problem constants
#define BATCH   64
#define PIX     196
#define ENC     2048
#define DEC     512
#define ATT     512
#define EMBD    512
#define VOC     10000
#define MAXLEN  52
#define TSTEPS  51
#define HCAT2   2560     // 512 dec_att | 2048 fbeta
#define XDIM2   3072     // emb 512 | awe 2048 | h 512
#define GDIM    2048     // 4*DEC

// Output layout (flattened tuple, float32)
#define PRED_OFF   0
#define CAP_OFF    32640000
#define LEN_OFF    32643328
#define ALPHA_OFF  32643392

#define HSPLIT  4
#define GSPLITA 8
#define GSPLITB 16
#define ISPLIT  8

#define MTOT  (TSTEPS * BATCH)   // 3264
#define NPAD  10112              // 79*128 >= VOC
#define NBLK  296                // persistent grid: 2 blocks/SM

#define SWS   136                // persistent weight tile row stride (halfs)
#define SWT   (128 * SWS)

// ---------------- scratch ----------------
__device__ __align__(16) __half g_WhcatT[HCAT2 * DEC];
__device__ __align__(16) __half g_WihT[GDIM * XDIM2];
__device__ __align__(16) __half g_WencT[ATT * ENC];
__device__ __align__(16) __half g_WfcT[NPAD * DEC];
__device__ __align__(16) __half g_WinitT[1024 * ENC];
__device__ __align__(16) __half g_enc_h[(BATCH * PIX + 8) * ENC];
__device__ __align__(16) __half g_mean16[BATCH * ENC];
__device__ __align__(16) __half g_h16cur[BATCH * DEC];
__device__ __align__(16) __half g_h16[MTOT * DEC];
__device__ __align__(16) __half g_x16[BATCH * XDIM2];
__device__ __align__(16) __half g_att_enc16[BATCH * PIX * ATT];
__device__ float  g_mask[TSTEPS * BATCH];
__device__ float  g_c[BATCH * DEC];
__device__ float  g_hpart[HSPLIT * BATCH * HCAT2];
__device__ float  g_gpartA[GSPLITA * BATCH * GDIM];
__device__ float  g_gpartB[GSPLITB * BATCH * GDIM];
__device__ float  g_ipart[ISPLIT * BATCH * 1024];
__device__ float  g_e[BATCH * PIX];

__device__ unsigned g_barcnt;

__device__ __forceinline__ float sigmoidf_(float x) { return 1.f / (1.f + __expf(-x)); }
__device__ __forceinline__ float tanh_fast(float x) {
    float y; asm("tanh.approx.f32 %0, %1;" : "=f"(y) : "f"(x)); return y;
}

// monotonic grid barrier
__device__ __forceinline__ void gbar(unsigned& nbar) {
    nbar += NBLK;
    __syncthreads();
    if (threadIdx.x == 0) {
        asm volatile("red.release.gpu.global.add.u32 [%0], 1;" :: "l"(&g_barcnt) : "memory");
        unsigned v;
        do {
            asm volatile("ld.acquire.gpu.u32 %0, [%1];" : "=r"(v) : "l"(&g_barcnt) : "memory");
        } while ((int)(v - nbar) < 0);
    }
    __syncthreads();
}

#define MMA_OP(c, a, b0, b1) \
    asm volatile("mma.sync.aligned.m16n8k16.row.col.f32.f16.f16.f32 " \
        "{%0,%1,%2,%3}, {%4,%5,%6,%7}, {%8,%9}, {%0,%1,%2,%3};" \
        : "+f"((c)[0]), "+f"((c)[1]), "+f"((c)[2]), "+f"((c)[3]) \
        : "r"((a)[0]), "r"((a)[1]), "r"((a)[2]), "r"((a)[3]), "r"(b0), "r"(b1))

// ---------------- HMMA 64x128 core: A+B streamed from global ----
__device__ __forceinline__ void hmma_core(
    const __half* __restrict__ Ag, int lda,
    const __half* __restrict__ Bg, int ldb,
    int n0, int koff, int nsteps,
    __half* sAh, __half* sBh, int tid,
    float (&c)[2][4][4])
{
    const int wid  = tid >> 5;
    const int lane = tid & 31;
    const int grp  = lane >> 2;
    const int tg   = lane & 3;
    const int wm   = wid >> 2;
    const int wn   = wid & 3;
    const int arow = tid >> 2;
    const int aseg = (tid & 3) * 8;

    const __half* Ap = Ag + (size_t)arow * lda + koff + aseg;
    const __half* Bp = Bg + (size_t)(n0 + arow) * ldb + koff + aseg;
    const size_t boff = (size_t)64 * ldb;

#pragma unroll
    for (int i = 0; i < 2; i++)
#pragma unroll
        for (int j = 0; j < 4; j++)
#pragma unroll
            for (int q = 0; q < 4; q++) c[i][j][q] = 0.f;

    uint4 ra  = *(const uint4*)Ap;
    uint4 rb0 = *(const uint4*)Bp;
    uint4 rb1 = *(const uint4*)(Bp + boff);
    *(uint4*)&sAh[arow * 40 + aseg]        = ra;
    *(uint4*)&sBh[arow * 40 + aseg]        = rb0;
    *(uint4*)&sBh[(arow + 64) * 40 + aseg] = rb1;
    __syncthreads();

    for (int kt = 0; kt < nsteps; kt++) {
        const int cur = kt & 1;
        const __half* cA = sAh + cur * (64 * 40);
        const __half* cB = sBh + cur * (128 * 40);

        if (kt + 1 < nsteps) {
            const int kb = (kt + 1) * 32;
            ra  = *(const uint4*)(Ap + kb);
            rb0 = *(const uint4*)(Bp + kb);
            rb1 = *(const uint4*)(Bp + boff + kb);
        }

#pragma unroll
        for (int ks = 0; ks < 2; ks++) {
            const int k0 = ks * 16;
            uint32_t a[2][4];
#pragma unroll
            for (int mi = 0; mi < 2; mi++) {
                const int r = wm * 32 + mi * 16 + grp;
                a[mi][0] = *(const uint32_t*)&cA[(r    ) * 40 + k0 + tg * 2];
                a[mi][1] = *(const uint32_t*)&cA[(r + 8) * 40 + k0 + tg * 2];
                a[mi][2] = *(const uint32_t*)&cA[(r    ) * 40 + k0 + tg * 2 + 8];
                a[mi][3] = *(const uint32_t*)&cA[(r + 8) * 40 + k0 + tg * 2 + 8];
            }
#pragma unroll
            for (int ni = 0; ni < 4; ni++) {
                const int nr = wn * 32 + ni * 8 + grp;
                uint32_t b0 = *(const uint32_t*)&cB[nr * 40 + k0 + tg * 2];
                uint32_t b1 = *(const uint32_t*)&cB[nr * 40 + k0 + tg * 2 + 8];
#pragma unroll
                for (int mi = 0; mi < 2; mi++) MMA_OP(c[mi][ni], a[mi], b0, b1);
            }
        }

        if (kt + 1 < nsteps) {
            const int nxt = cur ^ 1;
            __half* nA = sAh + nxt * (64 * 40);
            __half* nB = sBh + nxt * (128 * 40);
            *(uint4*)&nA[arow * 40 + aseg]        = ra;
            *(uint4*)&nB[arow * 40 + aseg]        = rb0;
            *(uint4*)&nB[(arow + 64) * 40 + aseg] = rb1;
            __syncthreads();
        }
    }
}

__device__ __forceinline__ void hmma_store(
    float (&c)[2][4][4], float* __restrict__ Cg, int ldc, int n0,
    const float* __restrict__ bias, int tid)
{
    const int wid  = tid >> 5;
    const int lane = tid & 31;
    const int grp  = lane >> 2;
    const int tg   = lane & 3;
    const int wm   = wid >> 2;
    const int wn   = wid & 3;
#pragma unroll
    for (int mi = 0; mi < 2; mi++) {
#pragma unroll
        for (int hh = 0; hh < 2; hh++) {
            const int row = wm * 32 + mi * 16 + grp + hh * 8;
            float* crow = Cg + (size_t)row * ldc;
#pragma unroll
            for (int ni = 0; ni < 4; ni++) {
                const int col = n0 + wn * 32 + ni * 8 + tg * 2;
                float v0 = c[mi][ni][hh * 2];
                float v1 = c[mi][ni][hh * 2 + 1];
                if (bias) { v0 += bias[col]; v1 += bias[col + 1]; }
                crow[col]     = v0;
                crow[col + 1] = v1;
            }
        }
    }
}

__device__ __forceinline__ void hmma_tile(
    const __half* __restrict__ Ag, int lda,
    const __half* __restrict__ Bg, int ldb,
    float* __restrict__ Cg, int ldc,
    int n0, int koff, int nsteps,
    const float* __restrict__ bias,
    __half* sAh, __half* sBh, int tid)
{
    float c[2][4][4];
    hmma_core(Ag, lda, Bg, ldb, n0, koff, nsteps, sAh, sBh, tid, c);
    hmma_store(c, Cg, ldc, n0, bias, tid);
}

// ---------------- HMMA 64x128, B resident in smem (K=128 fixed) ------
__device__ __forceinline__ void hmma_smemB(
    const __half* __restrict__ Ag, int lda, int koff,
    const __half* __restrict__ sW,
    float* __restrict__ Cg, int ldc, int n0,
    __half* sAh, int tid)
{
    const int wid  = tid >> 5;
    const int lane = tid & 31;
    const int grp  = lane >> 2;
    const int tg   = lane & 3;
    const int wm   = wid >> 2;
    const int wn   = wid & 3;
    const int arow = tid >> 2;
    const int aseg = (tid & 3) * 8;

    const __half* Ap = Ag + (size_t)arow * lda + koff + aseg;

    float c[2][4][4];
#pragma unroll
    for (int i = 0; i < 2; i++)
#pragma unroll
        for (int j = 0; j < 4; j++)
#pragma unroll
            for (int q = 0; q < 4; q++) c[i][j][q] = 0.f;

    uint4 ra = *(const uint4*)Ap;
    *(uint4*)&sAh[arow * 40 + aseg] = ra;
    __syncthreads();

#pragma unroll
    for (int kt = 0; kt < 4; kt++) {
        const int cur = kt & 1;
        const __half* cA = sAh + cur * (64 * 40);
        if (kt < 3) ra = *(const uint4*)(Ap + (kt + 1) * 32);

#pragma unroll
        for (int ks = 0; ks < 2; ks++) {
            const int k0 = ks * 16;
            const int kW = kt * 32 + k0;
            uint32_t a[2][4];
#pragma unroll
            for (int mi = 0; mi < 2; mi++) {
                const int r = wm * 32 + mi * 16 + grp;
                a[mi][0] = *(const uint32_t*)&cA[(r    ) * 40 + k0 + tg * 2];
                a[mi][1] = *(const uint32_t*)&cA[(r + 8) * 40 + k0 + tg * 2];
                a[mi][2] = *(const uint32_t*)&cA[(r    ) * 40 + k0 + tg * 2 + 8];
                a[mi][3] = *(const uint32_t*)&cA[(r + 8) * 40 + k0 + tg * 2 + 8];
            }
#pragma unroll
            for (int ni = 0; ni < 4; ni++) {
                const int nr = wn * 32 + ni * 8 + grp;
                uint32_t b0 = *(const uint32_t*)&sW[nr * SWS + kW + tg * 2];
                uint32_t b1 = *(const uint32_t*)&sW[nr * SWS + kW + tg * 2 + 8];
#pragma unroll
                for (int mi = 0; mi < 2; mi++) MMA_OP(c[mi][ni], a[mi], b0, b1);
            }
        }

        if (kt < 3) {
            const int nxt = cur ^ 1;
            *(uint4*)&sAh[nxt * (64 * 40) + arow * 40 + aseg] = ra;
            __syncthreads();
        }
    }

    hmma_store(c, Cg, ldc, n0, nullptr, tid);
}

__device__ __forceinline__ void load_wtile(const __half* __restrict__ src, int lds,
                                           __half* dst, int tid)
{
#pragma unroll
    for (int j = 0; j < 8; j++) {
        const int u = tid + j * 256;
        const int r = u >> 4, seg = (u & 15) * 8;
        *(uint4*)&dst[r * SWS + seg] = *(const uint4*)&src[(size_t)r * lds + seg];
    }
}

// ============ persistent decode-loop kernel ============
__global__ void __launch_bounds__(256, 2)
decode_loop_kernel(const float* __restrict__ b_dec_att, const float* __restrict__ Wf,
                   const float* __restrict__ bf, const float* __restrict__ b_fbeta,
                   const float* __restrict__ emb, const int* __restrict__ captions,
                   const int* __restrict__ cap_len,
                   const float* __restrict__ b_ih, const float* __restrict__ b_hh,
                   const float* __restrict__ b_init_h, const float* __restrict__ b_init_c,
                   float* __restrict__ out)
{
    extern __shared__ __half dyn[];
    __half* sAh  = dyn;                  // 2*64*40 halfs
    __half* sWp1 = dyn + 5120;
    __half* sWp4 = sWp1 + SWT;
    __shared__ float sdec[ATT];
    __shared__ float swf[ATT];
    __shared__ float sred[256];
    __shared__ float salpha[256];

    const int bid = blockIdx.x;
    const int tid = threadIdx.x;
    unsigned nbar = 0;

    // ---- pre-phase A: h0/c0 partials (64 blocks); sWp1 as B scratch ----
    if (bid < 64) {
        const int nt = bid & 7, z = bid >> 3;
        hmma_tile(g_mean16, ENC, g_WinitT, ENC,
                  g_ipart + (size_t)z * 64 * 1024, 1024,
                  nt * 128, z * 256, 8, nullptr, sAh, sWp1, tid);
    }
    gbar(nbar);

    // ---- pre-phase B: resident weight tiles; reduce h0/c0; emb t=0 ----
    if (bid < 80) {
        const int nt = bid / HSPLIT, z = bid - (bid / HSPLIT) * HSPLIT;
        load_wtile(g_WhcatT + (size_t)(nt * 128) * DEC + z * 128, DEC, sWp1, tid);
    } else if (bid < 208) {
        const int idx = bid - 80, nt = idx & 15, cc = idx >> 4;
        const int koff = (cc < 4) ? cc * 128 : (EMBD + ENC) + (cc - 4) * 128;
        load_wtile(g_WihT + (size_t)(nt * 128) * XDIM2 + koff, XDIM2, sWp1, tid);
    }
    if (bid < 256) {
        const int nt = bid & 15, z = bid >> 4;
        load_wtile(g_WihT + (size_t)(nt * 128) * XDIM2 + EMBD + z * 128, XDIM2, sWp4, tid);
    }
    if (bid < 64) {
        const int b = bid;
#pragma unroll
        for (int jj = 0; jj < 4; jj++) {
            const int col = tid + jj * 256;
            float v = 0.f;
#pragma unroll
            for (int z = 0; z < ISPLIT; z++) v += g_ipart[(size_t)(z * BATCH + b) * 1024 + col];
            if (col < DEC) {
                __half hv = __float2half_rn(v + b_init_h[col]);
                g_h16cur[b * DEC + col] = hv;
                g_x16[b * XDIM2 + EMBD + ENC + col] = hv;
            } else {
                g_c[b * DEC + (col - DEC)] = v + b_init_c[col - DEC];
            }
        }
        const int tok = captions[b * MAXLEN + 0];
        float2 v = *(const float2*)&emb[(size_t)tok * EMBD + tid * 2];
        *(__half2*)&g_x16[b * XDIM2 + tid * 2] = __floats2half2_rn(v.x, v.y);
    }
    gbar(nbar);

    for (int t = 0; t < TSTEPS; t++) {
        // ---- phase 1: hproj (80 blocks) + gates part-A (128 blocks); B resident ----
        if (bid < 80) {
            const int nt = bid / HSPLIT, z = bid - (bid / HSPLIT) * HSPLIT;
            hmma_smemB(g_h16cur, DEC, z * 128, sWp1,
                       g_hpart + (size_t)z * 64 * HCAT2, HCAT2, nt * 128, sAh, tid);
        } else if (bid < 208) {
            const int idx = bid - 80, nt = idx & 15, cc = idx >> 4;
            const int koff = (cc < 4) ? cc * 128 : (EMBD + ENC) + (cc - 4) * 128;
            hmma_smemB(g_x16, XDIM2, koff, sWp1,
                       g_gpartA + (size_t)cc * 64 * GDIM, GDIM, nt * 128, sAh, tid);
        }
        gbar(nbar);

        // ---- phase 2: attention scores (4 blocks per b, skip finished b) ----
        if (bid < 256) {
            const int b = bid >> 2, q = bid & 3;
            if (t < cap_len[b] - 1) {
                for (int k = tid; k < ATT; k += 256) {
                    float s = b_dec_att[k];
#pragma unroll
                    for (int z = 0; z < HSPLIT; z++)
                        s += g_hpart[(size_t)(z * BATCH + b) * HCAT2 + k];
                    sdec[k] = s;
                    swf[k] = Wf[k];
                }
                __syncthreads();
                const int warp = tid >> 5, lane = tid & 31;
                const float bf0 = bf[0];
                const int pbase = q * 49;
                for (int p = pbase + warp; p < pbase + 49; p += 8) {
                    const __half2* ae = (const __half2*)(g_att_enc16 + (size_t)(b * PIX + p) * ATT);
                    float acc = 0.f;
#pragma unroll
                    for (int kk = 0; kk < 8; kk++) {
                        const int idx = lane + kk * 32;
                        __half2 a2 = ae[idx];
                        const int k0 = idx * 2;
                        acc += tanh_fast(__low2float(a2)  + sdec[k0])     * swf[k0];
                        acc += tanh_fast(__high2float(a2) + sdec[k0 + 1]) * swf[k0 + 1];
                    }
#pragma unroll
                    for (int o = 16; o; o >>= 1) acc += __shfl_down_sync(0xffffffffu, acc, o);
                    if (lane == 0) g_e[b * PIX + p] = acc + bf0;
                }
            }
        }
        gbar(nbar);

        // ---- phase 3: softmax + awe + x16 awe-slot (4 blocks per b, skip finished) ----
        if (bid < 256) {
            const int b = bid >> 2, chunk = bid & 3;
            if (t >= cap_len[b] - 1) {
                // finished: output alphas are exactly zero for this step
                if (chunk == 0 && tid < PIX)
                    out[ALPHA_OFF + (size_t)b * TSTEPS * PIX + (size_t)t * PIX + tid] = 0.f;
            } else {
                float v = (tid < PIX) ? g_e[b * PIX + tid] : -1e30f;
                sred[tid] = v; __syncthreads();
                for (int s = 128; s; s >>= 1) { if (tid < s) sred[tid] = fmaxf(sred[tid], sred[tid+s]); __syncthreads(); }
                const float mx = sred[0]; __syncthreads();
                const float ex = (tid < PIX) ? __expf(v - mx) : 0.f;
                sred[tid] = ex; __syncthreads();
                for (int s = 128; s; s >>= 1) { if (tid < s) sred[tid] += sred[tid+s]; __syncthreads(); }
                const float inv = 1.f / sred[0];
                const float a = ex * inv;
                salpha[tid] = a;
                if (chunk == 0 && tid < PIX)
                    out[ALPHA_OFF + (size_t)b * TSTEPS * PIX + (size_t)t * PIX + tid] = a;
                __syncthreads();

                const int d = chunk * 512 + tid * 2;
                float ax = 0.f, ay = 0.f;
                const __half* ep = g_enc_h + (size_t)b * PIX * ENC + d;
#pragma unroll 16
                for (int p = 0; p < 200; p++) {
                    const float al = salpha[p];
                    __half2 h2 = *(const __half2*)(ep + (size_t)p * ENC);
                    ax = fmaf(al, __low2float(h2),  ax);
                    ay = fmaf(al, __high2float(h2), ay);
                }
                float gx = b_fbeta[d], gy = b_fbeta[d + 1];
#pragma unroll
                for (int z = 0; z < HSPLIT; z++) {
                    float2 p2 = *(const float2*)&g_hpart[(size_t)(z * BATCH + b) * HCAT2 + DEC + d];
                    gx += p2.x; gy += p2.y;
                }
                gx = sigmoidf_(gx); gy = sigmoidf_(gy);
                *(__half2*)&g_x16[b * XDIM2 + EMBD + d] = __floats2half2_rn(ax * gx, ay * gy);
            }
        }
        gbar(nbar);

        // ---- phase 4: gates part-B over awe (256 blocks, B resident) ----
        if (bid < 256) {
            const int nt = bid & 15, z = bid >> 4;
            hmma_smemB(g_x16, XDIM2, EMBD + z * 128, sWp4,
                       g_gpartB + (size_t)z * 64 * GDIM, GDIM, nt * 128, sAh, tid);
        }
        gbar(nbar);

        // ---- phase 5: LSTM update (128 blocks; 2 per b) + emb prefetch t+1 ----
        if (bid < 128) {
            const int b = bid >> 1, half = bid & 1;
            const int j = half * 256 + tid;
            float h = __half2float(g_h16cur[b * DEC + j]);
            if (t < cap_len[b] - 1) {
                float gv[4];
#pragma unroll
                for (int s = 0; s < 4; s++) {
                    const int col = s * DEC + j;
                    float v = b_ih[col] + b_hh[col];
#pragma unroll
                    for (int z = 0; z < GSPLITA; z++)
                        v += g_gpartA[(size_t)(z * BATCH + b) * GDIM + col];
#pragma unroll
                    for (int z = 0; z < GSPLITB; z++)
                        v += g_gpartB[(size_t)(z * BATCH + b) * GDIM + col];
                    gv[s] = v;
                }
                const float c_old = g_c[b * DEC + j];
                const float cn = sigmoidf_(gv[1]) * c_old + sigmoidf_(gv[0]) * tanhf(gv[2]);
                g_c[b * DEC + j] = cn;
                h = sigmoidf_(gv[3]) * tanhf(cn);
                __half hv = __float2half_rn(h);
                g_h16cur[b * DEC + j] = hv;
                g_x16[b * XDIM2 + EMBD + ENC + j] = hv;
            }
            g_h16[((size_t)t * BATCH + b) * DEC + j] = __float2half_rn(h);

            if (half == 1 && t + 1 < TSTEPS) {
                const int tok = captions[b * MAXLEN + t + 1];
                float2 v = *(const float2*)&emb[(size_t)tok * EMBD + tid * 2];
                *(__half2*)&g_x16[b * XDIM2 + tid * 2] = __floats2half2_rn(v.x, v.y);
            }
        }
        gbar(nbar);
    }
}

// ============ prologue att_enc GEMM via HMMA -> fp16 output ============
__global__ void __launch_bounds__(256)
attenc_mma_kernel(const float* __restrict__ b_enc_att)
{
    __shared__ __half sAh[2 * 64 * 40];
    __shared__ __half sBh[2 * 128 * 40];
    const int tid = threadIdx.x;
    const int m0 = blockIdx.y * 64;
    const int n0 = blockIdx.x * 128;

    float c[2][4][4];
    hmma_core(g_enc_h + (size_t)m0 * ENC, ENC, g_WencT, ENC,
              n0, 0, ENC / 32, sAh, sBh, tid, c);

    const int wid  = tid >> 5;
    const int lane = tid & 31;
    const int grp  = lane >> 2;
    const int tg   = lane & 3;
    const int wm   = wid >> 2;
    const int wn   = wid & 3;

#pragma unroll
    for (int mi = 0; mi < 2; mi++) {
#pragma unroll
        for (int hh = 0; hh < 2; hh++) {
            const int row = wm * 32 + mi * 16 + grp + hh * 8;
            __half* crow = g_att_enc16 + (size_t)(m0 + row) * ATT;
#pragma unroll
            for (int ni = 0; ni < 4; ni++) {
                const int col = n0 + wn * 32 + ni * 8 + tg * 2;
                float v0 = c[mi][ni][hh * 2]     + b_enc_att[col];
                float v1 = c[mi][ni][hh * 2 + 1] + b_enc_att[col + 1];
                *(__half2*)&crow[col] = __floats2half2_rn(v0, v1);
            }
        }
    }
}

// ============ batched predictions via HMMA ============
__global__ void __launch_bounds__(256)
preds_mma_kernel(const float* __restrict__ b_fc, const float* __restrict__ mask,
                 float* __restrict__ out)
{
    __shared__ __half sAh[2 * 64 * 40];
    __shared__ __half sBh[2 * 128 * 40];

    const int tid = threadIdx.x;
    const int m0 = blockIdx.y * 64;
    const int n0 = blockIdx.x * 128;

    float c[2][4][4];
    hmma_core(g_h16 + (size_t)m0 * DEC, DEC, g_WfcT, DEC,
              n0, 0, DEC / 32, sAh, sBh, tid, c);

    const int wid  = tid >> 5;
    const int lane = tid & 31;
    const int grp  = lane >> 2;
    const int tg   = lane & 3;
    const int wm   = wid >> 2;
    const int wn   = wid & 3;

#pragma unroll
    for (int mi = 0; mi < 2; mi++) {
#pragma unroll
        for (int hh = 0; hh < 2; hh++) {
            const int m = m0 + wm * 32 + mi * 16 + grp + hh * 8;
            const int tt = m >> 6, bb = m & 63;
            const float ms = mask[tt * BATCH + bb];
            float* orow = out + PRED_OFF + ((size_t)bb * TSTEPS + tt) * VOC;
#pragma unroll
            for (int ni = 0; ni < 4; ni++) {
                const int n = n0 + wn * 32 + ni * 8 + tg * 2;
                if (n + 1 < VOC) {
                    orow[n]     = (c[mi][ni][hh * 2]     + b_fc[n])     * ms;
                    orow[n + 1] = (c[mi][ni][hh * 2 + 1] + b_fc[n + 1]) * ms;
                } else if (n < VOC) {
                    orow[n] = (c[mi][ni][hh * 2] + b_fc[n]) * ms;
                }
            }
        }
    }
}

// ---------------- tiled transpose: src fp32 [K][N] -> dst fp16 [N][ldd] ----------
__global__ void transpose_f2h_kernel(const float* __restrict__ src, __half* __restrict__ dst,
                                     int K, int N, int ldd)
{
    __shared__ float tile[32][33];
    const int kb = blockIdx.y * 32, nb = blockIdx.x * 32;
    const int tx = threadIdx.x & 31, ty = threadIdx.x >> 5;
#pragma unroll
    for (int i = 0; i < 32; i += 8) {
        const int k = kb + ty + i, n = nb + tx;
        tile[ty + i][tx] = (k < K && n < N) ? src[(size_t)k * N + n] : 0.f;
    }
    __syncthreads();
#pragma unroll
    for (int i = 0; i < 32; i += 8) {
        const int n = nb + ty + i, k = kb + tx;
        if (n < N && k < K)
            dst[(size_t)n * ldd + k] = __float2half_rn(tile[tx][ty + i]);
    }
}

// ---------------- init: enc fp16, pads, mask, int outputs ----------------
__global__ void init_kernel(const float* __restrict__ enc,
                            const int* __restrict__ captions, const int* __restrict__ cap_len,
                            float* __restrict__ out)
{
    int idx = blockIdx.x * blockDim.x + threadIdx.x;
    int stride = gridDim.x * blockDim.x;
    for (int i = idx; i < BATCH * PIX * ENC; i += stride)
        g_enc_h[i] = __float2half_rn(enc[i]);
    for (int i = idx; i < 8 * ENC; i += stride)
        g_enc_h[BATCH * PIX * ENC + i] = __ushort_as_half(0);
    for (int i = idx; i < (NPAD - VOC) * DEC; i += stride)
        g_WfcT[(size_t)VOC * DEC + i] = __ushort_as_half(0);
    if (idx < TSTEPS * BATCH) {
        int t = idx / BATCH, b = idx - t * BATCH;
        g_mask[idx] = (t < cap_len[b] - 1) ? 1.f : 0.f;
    }
    if (idx < BATCH * MAXLEN) out[CAP_OFF + idx] = (float)captions[idx];
    if (idx < BATCH)          out[LEN_OFF + idx] = (float)(cap_len[idx] - 1);
}

__global__ void mean_kernel(const float* __restrict__ enc)
{
    int b = blockIdx.y;
    int d = blockIdx.x * 256 + threadIdx.x;
    const float* ep = enc + (size_t)b * PIX * ENC + d;
    float s = 0.f;
    for (int p = 0; p < PIX; p++) s += ep[(size_t)p * ENC];
    g_mean16[b * ENC + d] = __float2half_rn(s * (1.f / (float)PIX));
}

// ---------------- host launcher ----------------
extern "C" void kernel_launch(void* const* d_in, const int* in_sizes, int n_in,
                              void* d_out, int out_size)
{
    const float* enc        = (const float*)d_in[0];
    const int*   captions   = (const int*)  d_in[1];
    const int*   cap_len    = (const int*)  d_in[2];
    const float* emb        = (const float*)d_in[3];
    const float* W_enc_att  = (const float*)d_in[4];
    const float* b_enc_att  = (const float*)d_in[5];
    const float* W_dec_att  = (const float*)d_in[6];
    const float* b_dec_att  = (const float*)d_in[7];
    const float* W_full_att = (const float*)d_in[8];
    const float* b_full_att = (const float*)d_in[9];
    const float* W_init_h   = (const float*)d_in[10];
    const float* b_init_h   = (const float*)d_in[11];
    const float* W_init_c   = (const float*)d_in[12];
    const float* b_init_c   = (const float*)d_in[13];
    const float* W_fbeta    = (const float*)d_in[14];
    const float* b_fbeta    = (const float*)d_in[15];
    const float* W_ih       = (const float*)d_in[16];
    const float* W_hh       = (const float*)d_in[17];
    const float* b_ih       = (const float*)d_in[18];
    const float* b_hh       = (const float*)d_in[19];
    const float* W_fc       = (const float*)d_in[20];
    const float* b_fc       = (const float*)d_in[21];
    float* out = (float*)d_out;
    (void)in_sizes; (void)n_in; (void)out_size;

    float* pmask;
    unsigned* pbar;
    __half *pWhcatT, *pWihT, *pWencT, *pWfcT, *pWinitT;
    cudaGetSymbolAddress((void**)&pmask,   g_mask);
    cudaGetSymbolAddress((void**)&pbar,    g_barcnt);
    cudaGetSymbolAddress((void**)&pWhcatT, g_WhcatT);
    cudaGetSymbolAddress((void**)&pWihT,   g_WihT);
    cudaGetSymbolAddress((void**)&pWencT,  g_WencT);
    cudaGetSymbolAddress((void**)&pWfcT,   g_WfcT);
    cudaGetSymbolAddress((void**)&pWinitT, g_WinitT);

    static cudaStream_t s2 = nullptr;
    static cudaEvent_t evFork = nullptr, evJoin = nullptr;
    if (!s2) {
        cudaStreamCreateWithFlags(&s2, cudaStreamNonBlocking);
        cudaEventCreateWithFlags(&evFork, cudaEventDisableTiming);
        cudaEventCreateWithFlags(&evJoin, cudaEventDisableTiming);
    }

    cudaMemsetAsync(pbar, 0, sizeof(unsigned));

    // fork side stream for half the transposes
    cudaEventRecord(evFork, 0);
    cudaStreamWaitEvent(s2, evFork, 0);
    transpose_f2h_kernel<<<dim3(512 / 32, 2048 / 32), 256, 0, s2>>>(W_enc_att, pWencT, 2048, 512, 2048);
    transpose_f2h_kernel<<<dim3((VOC + 31) / 32, 512 / 32), 256, 0, s2>>>(W_fc, pWfcT, 512, VOC, 512);
    transpose_f2h_kernel<<<dim3(512 / 32, 2048 / 32), 256, 0, s2>>>(W_init_h, pWinitT, 2048, 512, 2048);
    transpose_f2h_kernel<<<dim3(512 / 32, 2048 / 32), 256, 0, s2>>>(W_init_c, pWinitT + 512 * 2048, 2048, 512, 2048);
    cudaEventRecord(evJoin, s2);

    // main stream
    transpose_f2h_kernel<<<dim3(512 / 32, 512 / 32), 256>>>(W_dec_att, pWhcatT, 512, 512, 512);
    transpose_f2h_kernel<<<dim3(2048 / 32, 512 / 32), 256>>>(W_fbeta, pWhcatT + 512 * 512, 512, 2048, 512);
    transpose_f2h_kernel<<<dim3(2048 / 32, 2560 / 32), 256>>>(W_ih, pWihT, 2560, 2048, XDIM2);
    transpose_f2h_kernel<<<dim3(2048 / 32, 512 / 32), 256>>>(W_hh, pWihT + 2560, 512, 2048, XDIM2);
    init_kernel<<<4096, 256>>>(enc, captions, cap_len, out);
    mean_kernel<<<dim3(ENC / 256, BATCH), 256>>>(enc);

    cudaStreamWaitEvent(0, evJoin, 0);
    attenc_mma_kernel<<<dim3(ATT / 128, (BATCH * PIX) / 64), 256>>>(b_enc_att);

    const int dyn_smem = (5120 + 2 * SWT) * (int)sizeof(__half);
    cudaFuncSetAttribute(decode_loop_kernel,
                         cudaFuncAttributeMaxDynamicSharedMemorySize, dyn_smem);
    decode_loop_kernel<<<NBLK, 256, dyn_smem>>>(b_dec_att, W_full_att, b_full_att, b_fbeta,
                                                emb, captions, cap_len,
                                                b_ih, b_hh, b_init_h, b_init_c, out);

    preds_mma_kernel<<<dim3(NPAD / 128, MTOT / 64), 256>>>(b_fc, pmask, out);
}

// round 15
// speedup vs baseline: 2.0840x; 1.0303x over previous
#include <cuda_runtime.h>
#include <cuda_fp16.h>
#include <math.h>
#include <stdint.h>

// Problem constants
#define BATCH   64
#define PIX     196
#define ENC     2048
#define DEC     512
#define ATT     512
#define EMBD    512
#define VOC     10000
#define MAXLEN  52
#define TSTEPS  51
#define HCAT2   2560     // 512 dec_att | 2048 fbeta
#define XDIM2   3072     // emb 512 | awe 2048 | h 512
#define GDIM    2048     // 4*DEC

// Output layout (flattened tuple, float32)
#define PRED_OFF   0
#define CAP_OFF    32640000
#define LEN_OFF    32643328
#define ALPHA_OFF  32643392

#define HSPLIT  4
#define GSPLITA 8
#define GSPLITB 16
#define ISPLIT  8

#define MTOT  (TSTEPS * BATCH)   // 3264
#define NPAD  10112              // 79*128 >= VOC
#define NBLK  256                // persistent grid: every block has work

#define SWS   136                // persistent weight tile row stride (halfs)
#define SWT   (128 * SWS)

// ---------------- scratch ----------------
__device__ __align__(16) __half g_WhcatT[HCAT2 * DEC];
__device__ __align__(16) __half g_WihT[GDIM * XDIM2];
__device__ __align__(16) __half g_WencT[ATT * ENC];
__device__ __align__(16) __half g_WfcT[NPAD * DEC];
__device__ __align__(16) __half g_WinitT[1024 * ENC];
__device__ __align__(16) __half g_enc_h[(BATCH * PIX + 8) * ENC];
__device__ __align__(16) __half g_mean16[BATCH * ENC];
__device__ __align__(16) __half g_h16cur[BATCH * DEC];
__device__ __align__(16) __half g_h16[MTOT * DEC];
__device__ __align__(16) __half g_x16[BATCH * XDIM2];
__device__ __align__(16) __half g_att_enc16[BATCH * PIX * ATT];
__device__ float  g_mask[TSTEPS * BATCH];
__device__ float  g_c[BATCH * DEC];
__device__ float  g_hpart[HSPLIT * BATCH * HCAT2];
__device__ float  g_gpartA[GSPLITA * BATCH * GDIM];
__device__ float  g_gpartB[GSPLITB * BATCH * GDIM];
__device__ float  g_ipart[ISPLIT * BATCH * 1024];
__device__ float  g_e[BATCH * PIX];

__device__ unsigned g_barcnt;

__device__ __forceinline__ float sigmoidf_(float x) { return 1.f / (1.f + __expf(-x)); }
__device__ __forceinline__ float tanh_fast(float x) {
    float y; asm("tanh.approx.f32 %0, %1;" : "=f"(y) : "f"(x)); return y;
}

// monotonic grid barrier
__device__ __forceinline__ void gbar(unsigned& nbar) {
    nbar += NBLK;
    __syncthreads();
    if (threadIdx.x == 0) {
        asm volatile("red.release.gpu.global.add.u32 [%0], 1;" :: "l"(&g_barcnt) : "memory");
        unsigned v;
        do {
            asm volatile("ld.acquire.gpu.u32 %0, [%1];" : "=r"(v) : "l"(&g_barcnt) : "memory");
        } while ((int)(v - nbar) < 0);
    }
    __syncthreads();
}

#define MMA_OP(c, a, b0, b1) \
    asm volatile("mma.sync.aligned.m16n8k16.row.col.f32.f16.f16.f32 " \
        "{%0,%1,%2,%3}, {%4,%5,%6,%7}, {%8,%9}, {%0,%1,%2,%3};" \
        : "+f"((c)[0]), "+f"((c)[1]), "+f"((c)[2]), "+f"((c)[3]) \
        : "r"((a)[0]), "r"((a)[1]), "r"((a)[2]), "r"((a)[3]), "r"(b0), "r"(b1))

// ---------------- HMMA 64x128 core: A+B streamed from global ----
__device__ __forceinline__ void hmma_core(
    const __half* __restrict__ Ag, int lda,
    const __half* __restrict__ Bg, int ldb,
    int n0, int koff, int nsteps,
    __half* sAh, __half* sBh, int tid,
    float (&c)[2][4][4])
{
    const int wid  = tid >> 5;
    const int lane = tid & 31;
    const int grp  = lane >> 2;
    const int tg   = lane & 3;
    const int wm   = wid >> 2;
    const int wn   = wid & 3;
    const int arow = tid >> 2;
    const int aseg = (tid & 3) * 8;

    const __half* Ap = Ag + (size_t)arow * lda + koff + aseg;
    const __half* Bp = Bg + (size_t)(n0 + arow) * ldb + koff + aseg;
    const size_t boff = (size_t)64 * ldb;

#pragma unroll
    for (int i = 0; i < 2; i++)
#pragma unroll
        for (int j = 0; j < 4; j++)
#pragma unroll
            for (int q = 0; q < 4; q++) c[i][j][q] = 0.f;

    uint4 ra  = *(const uint4*)Ap;
    uint4 rb0 = *(const uint4*)Bp;
    uint4 rb1 = *(const uint4*)(Bp + boff);
    *(uint4*)&sAh[arow * 40 + aseg]        = ra;
    *(uint4*)&sBh[arow * 40 + aseg]        = rb0;
    *(uint4*)&sBh[(arow + 64) * 40 + aseg] = rb1;
    __syncthreads();

    for (int kt = 0; kt < nsteps; kt++) {
        const int cur = kt & 1;
        const __half* cA = sAh + cur * (64 * 40);
        const __half* cB = sBh + cur * (128 * 40);

        if (kt + 1 < nsteps) {
            const int kb = (kt + 1) * 32;
            ra  = *(const uint4*)(Ap + kb);
            rb0 = *(const uint4*)(Bp + kb);
            rb1 = *(const uint4*)(Bp + boff + kb);
        }

#pragma unroll
        for (int ks = 0; ks < 2; ks++) {
            const int k0 = ks * 16;
            uint32_t a[2][4];
#pragma unroll
            for (int mi = 0; mi < 2; mi++) {
                const int r = wm * 32 + mi * 16 + grp;
                a[mi][0] = *(const uint32_t*)&cA[(r    ) * 40 + k0 + tg * 2];
                a[mi][1] = *(const uint32_t*)&cA[(r + 8) * 40 + k0 + tg * 2];
                a[mi][2] = *(const uint32_t*)&cA[(r    ) * 40 + k0 + tg * 2 + 8];
                a[mi][3] = *(const uint32_t*)&cA[(r + 8) * 40 + k0 + tg * 2 + 8];
            }
#pragma unroll
            for (int ni = 0; ni < 4; ni++) {
                const int nr = wn * 32 + ni * 8 + grp;
                uint32_t b0 = *(const uint32_t*)&cB[nr * 40 + k0 + tg * 2];
                uint32_t b1 = *(const uint32_t*)&cB[nr * 40 + k0 + tg * 2 + 8];
#pragma unroll
                for (int mi = 0; mi < 2; mi++) MMA_OP(c[mi][ni], a[mi], b0, b1);
            }
        }

        if (kt + 1 < nsteps) {
            const int nxt = cur ^ 1;
            __half* nA = sAh + nxt * (64 * 40);
            __half* nB = sBh + nxt * (128 * 40);
            *(uint4*)&nA[arow * 40 + aseg]        = ra;
            *(uint4*)&nB[arow * 40 + aseg]        = rb0;
            *(uint4*)&nB[(arow + 64) * 40 + aseg] = rb1;
            __syncthreads();
        }
    }
}

__device__ __forceinline__ void hmma_store(
    float (&c)[2][4][4], float* __restrict__ Cg, int ldc, int n0,
    const float* __restrict__ bias, int tid)
{
    const int wid  = tid >> 5;
    const int lane = tid & 31;
    const int grp  = lane >> 2;
    const int tg   = lane & 3;
    const int wm   = wid >> 2;
    const int wn   = wid & 3;
#pragma unroll
    for (int mi = 0; mi < 2; mi++) {
#pragma unroll
        for (int hh = 0; hh < 2; hh++) {
            const int row = wm * 32 + mi * 16 + grp + hh * 8;
            float* crow = Cg + (size_t)row * ldc;
#pragma unroll
            for (int ni = 0; ni < 4; ni++) {
                const int col = n0 + wn * 32 + ni * 8 + tg * 2;
                float v0 = c[mi][ni][hh * 2];
                float v1 = c[mi][ni][hh * 2 + 1];
                if (bias) { v0 += bias[col]; v1 += bias[col + 1]; }
                crow[col]     = v0;
                crow[col + 1] = v1;
            }
        }
    }
}

__device__ __forceinline__ void hmma_tile(
    const __half* __restrict__ Ag, int lda,
    const __half* __restrict__ Bg, int ldb,
    float* __restrict__ Cg, int ldc,
    int n0, int koff, int nsteps,
    const float* __restrict__ bias,
    __half* sAh, __half* sBh, int tid)
{
    float c[2][4][4];
    hmma_core(Ag, lda, Bg, ldb, n0, koff, nsteps, sAh, sBh, tid, c);
    hmma_store(c, Cg, ldc, n0, bias, tid);
}

// ---------------- HMMA 64x128, B resident in smem (K=128 fixed) ------
__device__ __forceinline__ void hmma_smemB(
    const __half* __restrict__ Ag, int lda, int koff,
    const __half* __restrict__ sW,
    float* __restrict__ Cg, int ldc, int n0,
    __half* sAh, int tid)
{
    const int wid  = tid >> 5;
    const int lane = tid & 31;
    const int grp  = lane >> 2;
    const int tg   = lane & 3;
    const int wm   = wid >> 2;
    const int wn   = wid & 3;
    const int arow = tid >> 2;
    const int aseg = (tid & 3) * 8;

    const __half* Ap = Ag + (size_t)arow * lda + koff + aseg;

    float c[2][4][4];
#pragma unroll
    for (int i = 0; i < 2; i++)
#pragma unroll
        for (int j = 0; j < 4; j++)
#pragma unroll
            for (int q = 0; q < 4; q++) c[i][j][q] = 0.f;

    uint4 ra = *(const uint4*)Ap;
    *(uint4*)&sAh[arow * 40 + aseg] = ra;
    __syncthreads();

#pragma unroll
    for (int kt = 0; kt < 4; kt++) {
        const int cur = kt & 1;
        const __half* cA = sAh + cur * (64 * 40);
        if (kt < 3) ra = *(const uint4*)(Ap + (kt + 1) * 32);

#pragma unroll
        for (int ks = 0; ks < 2; ks++) {
            const int k0 = ks * 16;
            const int kW = kt * 32 + k0;
            uint32_t a[2][4];
#pragma unroll
            for (int mi = 0; mi < 2; mi++) {
                const int r = wm * 32 + mi * 16 + grp;
                a[mi][0] = *(const uint32_t*)&cA[(r    ) * 40 + k0 + tg * 2];
                a[mi][1] = *(const uint32_t*)&cA[(r + 8) * 40 + k0 + tg * 2];
                a[mi][2] = *(const uint32_t*)&cA[(r    ) * 40 + k0 + tg * 2 + 8];
                a[mi][3] = *(const uint32_t*)&cA[(r + 8) * 40 + k0 + tg * 2 + 8];
            }
#pragma unroll
            for (int ni = 0; ni < 4; ni++) {
                const int nr = wn * 32 + ni * 8 + grp;
                uint32_t b0 = *(const uint32_t*)&sW[nr * SWS + kW + tg * 2];
                uint32_t b1 = *(const uint32_t*)&sW[nr * SWS + kW + tg * 2 + 8];
#pragma unroll
                for (int mi = 0; mi < 2; mi++) MMA_OP(c[mi][ni], a[mi], b0, b1);
            }
        }

        if (kt < 3) {
            const int nxt = cur ^ 1;
            *(uint4*)&sAh[nxt * (64 * 40) + arow * 40 + aseg] = ra;
            __syncthreads();
        }
    }

    hmma_store(c, Cg, ldc, n0, nullptr, tid);
}

__device__ __forceinline__ void load_wtile(const __half* __restrict__ src, int lds,
                                           __half* dst, int tid)
{
#pragma unroll
    for (int j = 0; j < 8; j++) {
        const int u = tid + j * 256;
        const int r = u >> 4, seg = (u & 15) * 8;
        *(uint4*)&dst[r * SWS + seg] = *(const uint4*)&src[(size_t)r * lds + seg];
    }
}

// ============ persistent decode-loop kernel (256 blocks, 2/SM) ============
__global__ void __launch_bounds__(256, 2)
decode_loop_kernel(const float* __restrict__ b_dec_att, const float* __restrict__ Wf,
                   const float* __restrict__ bf, const float* __restrict__ b_fbeta,
                   const float* __restrict__ emb, const int* __restrict__ captions,
                   const int* __restrict__ cap_len,
                   const float* __restrict__ b_ih, const float* __restrict__ b_hh,
                   float* __restrict__ out)
{
    extern __shared__ __half dyn[];
    __half* sAh  = dyn;                  // 2*64*40 halfs
    __half* sWp1 = dyn + 5120;
    __half* sWp4 = sWp1 + SWT;
    __shared__ float sdec[ATT];
    __shared__ float swf[ATT];
    __shared__ float sred[256];
    __shared__ float salpha[256];

    const int bid = blockIdx.x;
    const int tid = threadIdx.x;
    unsigned nbar = 0;

    // ---- block-local: load resident weight tiles (no grid barrier needed) ----
    if (bid < 80) {
        const int nt = bid / HSPLIT, z = bid - (bid / HSPLIT) * HSPLIT;
        load_wtile(g_WhcatT + (size_t)(nt * 128) * DEC + z * 128, DEC, sWp1, tid);
    } else if (bid < 208) {
        const int idx = bid - 80, nt = idx & 15, cc = idx >> 4;
        const int koff = (cc < 4) ? cc * 128 : (EMBD + ENC) + (cc - 4) * 128;
        load_wtile(g_WihT + (size_t)(nt * 128) * XDIM2 + koff, XDIM2, sWp1, tid);
    }
    {
        const int nt = bid & 15, z = bid >> 4;
        load_wtile(g_WihT + (size_t)(nt * 128) * XDIM2 + EMBD + z * 128, XDIM2, sWp4, tid);
    }
    __syncthreads();

    for (int t = 0; t < TSTEPS; t++) {
        // ---- phase 1: hproj (80 blocks) + gates part-A (128 blocks); B resident ----
        if (bid < 80) {
            const int nt = bid / HSPLIT, z = bid - (bid / HSPLIT) * HSPLIT;
            hmma_smemB(g_h16cur, DEC, z * 128, sWp1,
                       g_hpart + (size_t)z * 64 * HCAT2, HCAT2, nt * 128, sAh, tid);
        } else if (bid < 208) {
            const int idx = bid - 80, nt = idx & 15, cc = idx >> 4;
            const int koff = (cc < 4) ? cc * 128 : (EMBD + ENC) + (cc - 4) * 128;
            hmma_smemB(g_x16, XDIM2, koff, sWp1,
                       g_gpartA + (size_t)cc * 64 * GDIM, GDIM, nt * 128, sAh, tid);
        }
        gbar(nbar);

        // ---- phase 2: attention scores (4 blocks per b, skip finished b) ----
        {
            const int b = bid >> 2, q = bid & 3;
            if (t < cap_len[b] - 1) {
                for (int k = tid; k < ATT; k += 256) {
                    float s = b_dec_att[k];
#pragma unroll
                    for (int z = 0; z < HSPLIT; z++)
                        s += g_hpart[(size_t)(z * BATCH + b) * HCAT2 + k];
                    sdec[k] = s;
                    swf[k] = Wf[k];
                }
                __syncthreads();
                const int warp = tid >> 5, lane = tid & 31;
                const float bf0 = bf[0];
                const int pbase = q * 49;
                for (int p = pbase + warp; p < pbase + 49; p += 8) {
                    const __half2* ae = (const __half2*)(g_att_enc16 + (size_t)(b * PIX + p) * ATT);
                    float acc = 0.f;
#pragma unroll
                    for (int kk = 0; kk < 8; kk++) {
                        const int idx = lane + kk * 32;
                        __half2 a2 = ae[idx];
                        const int k0 = idx * 2;
                        acc += tanh_fast(__low2float(a2)  + sdec[k0])     * swf[k0];
                        acc += tanh_fast(__high2float(a2) + sdec[k0 + 1]) * swf[k0 + 1];
                    }
#pragma unroll
                    for (int o = 16; o; o >>= 1) acc += __shfl_down_sync(0xffffffffu, acc, o);
                    if (lane == 0) g_e[b * PIX + p] = acc + bf0;
                }
            }
        }
        gbar(nbar);

        // ---- phase 3: softmax + awe + x16 awe-slot (4 blocks per b, skip finished) ----
        {
            const int b = bid >> 2, chunk = bid & 3;
            if (t >= cap_len[b] - 1) {
                if (chunk == 0 && tid < PIX)
                    out[ALPHA_OFF + (size_t)b * TSTEPS * PIX + (size_t)t * PIX + tid] = 0.f;
            } else {
                float v = (tid < PIX) ? g_e[b * PIX + tid] : -1e30f;
                sred[tid] = v; __syncthreads();
                for (int s = 128; s; s >>= 1) { if (tid < s) sred[tid] = fmaxf(sred[tid], sred[tid+s]); __syncthreads(); }
                const float mx = sred[0]; __syncthreads();
                const float ex = (tid < PIX) ? __expf(v - mx) : 0.f;
                sred[tid] = ex; __syncthreads();
                for (int s = 128; s; s >>= 1) { if (tid < s) sred[tid] += sred[tid+s]; __syncthreads(); }
                const float inv = 1.f / sred[0];
                const float a = ex * inv;
                salpha[tid] = a;
                if (chunk == 0 && tid < PIX)
                    out[ALPHA_OFF + (size_t)b * TSTEPS * PIX + (size_t)t * PIX + tid] = a;
                __syncthreads();

                const int d = chunk * 512 + tid * 2;
                float ax = 0.f, ay = 0.f;
                const __half* ep = g_enc_h + (size_t)b * PIX * ENC + d;
#pragma unroll 16
                for (int p = 0; p < 200; p++) {
                    const float al = salpha[p];
                    __half2 h2 = *(const __half2*)(ep + (size_t)p * ENC);
                    ax = fmaf(al, __low2float(h2),  ax);
                    ay = fmaf(al, __high2float(h2), ay);
                }
                float gx = b_fbeta[d], gy = b_fbeta[d + 1];
#pragma unroll
                for (int z = 0; z < HSPLIT; z++) {
                    float2 p2 = *(const float2*)&g_hpart[(size_t)(z * BATCH + b) * HCAT2 + DEC + d];
                    gx += p2.x; gy += p2.y;
                }
                gx = sigmoidf_(gx); gy = sigmoidf_(gy);
                *(__half2*)&g_x16[b * XDIM2 + EMBD + d] = __floats2half2_rn(ax * gx, ay * gy);
            }
        }
        gbar(nbar);

        // ---- phase 4: gates part-B over awe (256 blocks, B resident) ----
        {
            const int nt = bid & 15, z = bid >> 4;
            hmma_smemB(g_x16, XDIM2, EMBD + z * 128, sWp4,
                       g_gpartB + (size_t)z * 64 * GDIM, GDIM, nt * 128, sAh, tid);
        }
        gbar(nbar);

        // ---- phase 5: LSTM update (128 blocks; 2 per b) + emb prefetch t+1 ----
        if (bid < 128) {
            const int b = bid >> 1, half = bid & 1;
            const int j = half * 256 + tid;
            float h = __half2float(g_h16cur[b * DEC + j]);
            if (t < cap_len[b] - 1) {
                float gv[4];
#pragma unroll
                for (int s = 0; s < 4; s++) {
                    const int col = s * DEC + j;
                    float v = b_ih[col] + b_hh[col];
#pragma unroll
                    for (int z = 0; z < GSPLITA; z++)
                        v += g_gpartA[(size_t)(z * BATCH + b) * GDIM + col];
#pragma unroll
                    for (int z = 0; z < GSPLITB; z++)
                        v += g_gpartB[(size_t)(z * BATCH + b) * GDIM + col];
                    gv[s] = v;
                }
                const float c_old = g_c[b * DEC + j];
                const float cn = sigmoidf_(gv[1]) * c_old + sigmoidf_(gv[0]) * tanhf(gv[2]);
                g_c[b * DEC + j] = cn;
                h = sigmoidf_(gv[3]) * tanhf(cn);
                __half hv = __float2half_rn(h);
                g_h16cur[b * DEC + j] = hv;
                g_x16[b * XDIM2 + EMBD + ENC + j] = hv;
            }
            g_h16[((size_t)t * BATCH + b) * DEC + j] = __float2half_rn(h);

            if (half == 1 && t + 1 < TSTEPS) {
                const int tok = captions[b * MAXLEN + t + 1];
                float2 v = *(const float2*)&emb[(size_t)tok * EMBD + tid * 2];
                *(__half2*)&g_x16[b * XDIM2 + tid * 2] = __floats2half2_rn(v.x, v.y);
            }
        }
        gbar(nbar);
    }
}

// ============ prologue h0/c0 partials via HMMA (64 blocks) ============
__global__ void __launch_bounds__(256)
h0c0_mma_kernel()
{
    __shared__ __half sAh[2 * 64 * 40];
    __shared__ __half sBh[2 * 128 * 40];
    const int nt = blockIdx.x & 7, z = blockIdx.x >> 3;
    hmma_tile(g_mean16, ENC, g_WinitT, ENC,
              g_ipart + (size_t)z * 64 * 1024, 1024,
              nt * 128, z * 256, 8, nullptr, sAh, sBh, threadIdx.x);
}

// ============ prologue reduce -> h0/c0, x16 init, emb t=0 ============
__global__ void __launch_bounds__(256)
ireduce_kernel(const float* __restrict__ b_init_h, const float* __restrict__ b_init_c,
               const float* __restrict__ emb, const int* __restrict__ captions)
{
    const int b = blockIdx.x;
    const int tid = threadIdx.x;
#pragma unroll
    for (int jj = 0; jj < 4; jj++) {
        const int col = tid + jj * 256;
        float v = 0.f;
#pragma unroll
        for (int z = 0; z < ISPLIT; z++) v += g_ipart[(size_t)(z * BATCH + b) * 1024 + col];
        if (col < DEC) {
            __half hv = __float2half_rn(v + b_init_h[col]);
            g_h16cur[b * DEC + col] = hv;
            g_x16[b * XDIM2 + EMBD + ENC + col] = hv;
        } else {
            g_c[b * DEC + (col - DEC)] = v + b_init_c[col - DEC];
        }
    }
    const int tok = captions[b * MAXLEN + 0];
    float2 v = *(const float2*)&emb[(size_t)tok * EMBD + tid * 2];
    *(__half2*)&g_x16[b * XDIM2 + tid * 2] = __floats2half2_rn(v.x, v.y);
}

// ============ prologue att_enc GEMM via HMMA -> fp16 output ============
__global__ void __launch_bounds__(256)
attenc_mma_kernel(const float* __restrict__ b_enc_att)
{
    __shared__ __half sAh[2 * 64 * 40];
    __shared__ __half sBh[2 * 128 * 40];
    const int tid = threadIdx.x;
    const int m0 = blockIdx.y * 64;
    const int n0 = blockIdx.x * 128;

    float c[2][4][4];
    hmma_core(g_enc_h + (size_t)m0 * ENC, ENC, g_WencT, ENC,
              n0, 0, ENC / 32, sAh, sBh, tid, c);

    const int wid  = tid >> 5;
    const int lane = tid & 31;
    const int grp  = lane >> 2;
    const int tg   = lane & 3;
    const int wm   = wid >> 2;
    const int wn   = wid & 3;

#pragma unroll
    for (int mi = 0; mi < 2; mi++) {
#pragma unroll
        for (int hh = 0; hh < 2; hh++) {
            const int row = wm * 32 + mi * 16 + grp + hh * 8;
            __half* crow = g_att_enc16 + (size_t)(m0 + row) * ATT;
#pragma unroll
            for (int ni = 0; ni < 4; ni++) {
                const int col = n0 + wn * 32 + ni * 8 + tg * 2;
                float v0 = c[mi][ni][hh * 2]     + b_enc_att[col];
                float v1 = c[mi][ni][hh * 2 + 1] + b_enc_att[col + 1];
                *(__half2*)&crow[col] = __floats2half2_rn(v0, v1);
            }
        }
    }
}

// ============ batched predictions via HMMA ============
__global__ void __launch_bounds__(256)
preds_mma_kernel(const float* __restrict__ b_fc, const float* __restrict__ mask,
                 float* __restrict__ out)
{
    __shared__ __half sAh[2 * 64 * 40];
    __shared__ __half sBh[2 * 128 * 40];

    const int tid = threadIdx.x;
    const int m0 = blockIdx.y * 64;
    const int n0 = blockIdx.x * 128;

    float c[2][4][4];
    hmma_core(g_h16 + (size_t)m0 * DEC, DEC, g_WfcT, DEC,
              n0, 0, DEC / 32, sAh, sBh, tid, c);

    const int wid  = tid >> 5;
    const int lane = tid & 31;
    const int grp  = lane >> 2;
    const int tg   = lane & 3;
    const int wm   = wid >> 2;
    const int wn   = wid & 3;

#pragma unroll
    for (int mi = 0; mi < 2; mi++) {
#pragma unroll
        for (int hh = 0; hh < 2; hh++) {
            const int m = m0 + wm * 32 + mi * 16 + grp + hh * 8;
            const int tt = m >> 6, bb = m & 63;
            const float ms = mask[tt * BATCH + bb];
            float* orow = out + PRED_OFF + ((size_t)bb * TSTEPS + tt) * VOC;
#pragma unroll
            for (int ni = 0; ni < 4; ni++) {
                const int n = n0 + wn * 32 + ni * 8 + tg * 2;
                if (n + 1 < VOC) {
                    orow[n]     = (c[mi][ni][hh * 2]     + b_fc[n])     * ms;
                    orow[n + 1] = (c[mi][ni][hh * 2 + 1] + b_fc[n + 1]) * ms;
                } else if (n < VOC) {
                    orow[n] = (c[mi][ni][hh * 2] + b_fc[n]) * ms;
                }
            }
        }
    }
}

// ---------------- tiled transpose: src fp32 [K][N] -> dst fp16 [N][ldd] ----------
__global__ void transpose_f2h_kernel(const float* __restrict__ src, __half* __restrict__ dst,
                                     int K, int N, int ldd)
{
    __shared__ float tile[32][33];
    const int kb = blockIdx.y * 32, nb = blockIdx.x * 32;
    const int tx = threadIdx.x & 31, ty = threadIdx.x >> 5;
#pragma unroll
    for (int i = 0; i < 32; i += 8) {
        const int k = kb + ty + i, n = nb + tx;
        tile[ty + i][tx] = (k < K && n < N) ? src[(size_t)k * N + n] : 0.f;
    }
    __syncthreads();
#pragma unroll
    for (int i = 0; i < 32; i += 8) {
        const int n = nb + ty + i, k = kb + tx;
        if (n < N && k < K)
            dst[(size_t)n * ldd + k] = __float2half_rn(tile[tx][ty + i]);
    }
}

// ---------------- init: enc fp16, pads, mask, int outputs ----------------
__global__ void init_kernel(const float* __restrict__ enc,
                            const int* __restrict__ captions, const int* __restrict__ cap_len,
                            float* __restrict__ out)
{
    int idx = blockIdx.x * blockDim.x + threadIdx.x;
    int stride = gridDim.x * blockDim.x;
    for (int i = idx; i < BATCH * PIX * ENC; i += stride)
        g_enc_h[i] = __float2half_rn(enc[i]);
    for (int i = idx; i < 8 * ENC; i += stride)
        g_enc_h[BATCH * PIX * ENC + i] = __ushort_as_half(0);
    for (int i = idx; i < (NPAD - VOC) * DEC; i += stride)
        g_WfcT[(size_t)VOC * DEC + i] = __ushort_as_half(0);
    if (idx < TSTEPS * BATCH) {
        int t = idx / BATCH, b = idx - t * BATCH;
        g_mask[idx] = (t < cap_len[b] - 1) ? 1.f : 0.f;
    }
    if (idx < BATCH * MAXLEN) out[CAP_OFF + idx] = (float)captions[idx];
    if (idx < BATCH)          out[LEN_OFF + idx] = (float)(cap_len[idx] - 1);
}

__global__ void mean_kernel(const float* __restrict__ enc)
{
    int b = blockIdx.y;
    int d = blockIdx.x * 256 + threadIdx.x;
    const float* ep = enc + (size_t)b * PIX * ENC + d;
    float s = 0.f;
    for (int p = 0; p < PIX; p++) s += ep[(size_t)p * ENC];
    g_mean16[b * ENC + d] = __float2half_rn(s * (1.f / (float)PIX));
}

// ---------------- host launcher ----------------
extern "C" void kernel_launch(void* const* d_in, const int* in_sizes, int n_in,
                              void* d_out, int out_size)
{
    const float* enc        = (const float*)d_in[0];
    const int*   captions   = (const int*)  d_in[1];
    const int*   cap_len    = (const int*)  d_in[2];
    const float* emb        = (const float*)d_in[3];
    const float* W_enc_att  = (const float*)d_in[4];
    const float* b_enc_att  = (const float*)d_in[5];
    const float* W_dec_att  = (const float*)d_in[6];
    const float* b_dec_att  = (const float*)d_in[7];
    const float* W_full_att = (const float*)d_in[8];
    const float* b_full_att = (const float*)d_in[9];
    const float* W_init_h   = (const float*)d_in[10];
    const float* b_init_h   = (const float*)d_in[11];
    const float* W_init_c   = (const float*)d_in[12];
    const float* b_init_c   = (const float*)d_in[13];
    const float* W_fbeta    = (const float*)d_in[14];
    const float* b_fbeta    = (const float*)d_in[15];
    const float* W_ih       = (const float*)d_in[16];
    const float* W_hh       = (const float*)d_in[17];
    const float* b_ih       = (const float*)d_in[18];
    const float* b_hh       = (const float*)d_in[19];
    const float* W_fc       = (const float*)d_in[20];
    const float* b_fc       = (const float*)d_in[21];
    float* out = (float*)d_out;
    (void)in_sizes; (void)n_in; (void)out_size;

    float* pmask;
    unsigned* pbar;
    __half *pWhcatT, *pWihT, *pWencT, *pWfcT, *pWinitT;
    cudaGetSymbolAddress((void**)&pmask,   g_mask);
    cudaGetSymbolAddress((void**)&pbar,    g_barcnt);
    cudaGetSymbolAddress((void**)&pWhcatT, g_WhcatT);
    cudaGetSymbolAddress((void**)&pWihT,   g_WihT);
    cudaGetSymbolAddress((void**)&pWencT,  g_WencT);
    cudaGetSymbolAddress((void**)&pWfcT,   g_WfcT);
    cudaGetSymbolAddress((void**)&pWinitT, g_WinitT);

    static cudaStream_t s2 = nullptr;
    static cudaEvent_t evMean = nullptr, evEnc = nullptr, evJoin = nullptr, evFork = nullptr;
    if (!s2) {
        cudaStreamCreateWithFlags(&s2, cudaStreamNonBlocking);
        cudaEventCreateWithFlags(&evMean, cudaEventDisableTiming);
        cudaEventCreateWithFlags(&evEnc,  cudaEventDisableTiming);
        cudaEventCreateWithFlags(&evJoin, cudaEventDisableTiming);
        cudaEventCreateWithFlags(&evFork, cudaEventDisableTiming);
    }

    cudaMemsetAsync(pbar, 0, sizeof(unsigned));

    // side stream: WencT/WfcT/WinitT transposes, then h0/c0 (after mean)
    cudaEventRecord(evFork, 0);
    cudaStreamWaitEvent(s2, evFork, 0);
    transpose_f2h_kernel<<<dim3(512 / 32, 2048 / 32), 256, 0, s2>>>(W_enc_att, pWencT, 2048, 512, 2048);
    cudaEventRecord(evEnc, s2);
    transpose_f2h_kernel<<<dim3((VOC + 31) / 32, 512 / 32), 256, 0, s2>>>(W_fc, pWfcT, 512, VOC, 512);
    transpose_f2h_kernel<<<dim3(512 / 32, 2048 / 32), 256, 0, s2>>>(W_init_h, pWinitT, 2048, 512, 2048);
    transpose_f2h_kernel<<<dim3(512 / 32, 2048 / 32), 256, 0, s2>>>(W_init_c, pWinitT + 512 * 2048, 2048, 512, 2048);

    // main stream: loop-critical transposes + init + mean
    transpose_f2h_kernel<<<dim3(512 / 32, 512 / 32), 256>>>(W_dec_att, pWhcatT, 512, 512, 512);
    transpose_f2h_kernel<<<dim3(2048 / 32, 512 / 32), 256>>>(W_fbeta, pWhcatT + 512 * 512, 512, 2048, 512);
    transpose_f2h_kernel<<<dim3(2048 / 32, 2560 / 32), 256>>>(W_ih, pWihT, 2560, 2048, XDIM2);
    transpose_f2h_kernel<<<dim3(2048 / 32, 512 / 32), 256>>>(W_hh, pWihT + 2560, 512, 2048, XDIM2);
    init_kernel<<<4096, 256>>>(enc, captions, cap_len, out);
    mean_kernel<<<dim3(ENC / 256, BATCH), 256>>>(enc);
    cudaEventRecord(evMean, 0);

    // side: h0/c0 (needs mean16 + WinitT) overlapped with main's attenc
    cudaStreamWaitEvent(s2, evMean, 0);
    h0c0_mma_kernel<<<64, 256, 0, s2>>>();
    ireduce_kernel<<<BATCH, 256, 0, s2>>>(b_init_h, b_init_c, emb, captions);
    cudaEventRecord(evJoin, s2);

    // main: attenc (needs WencT from side + enc_h/init from main)
    cudaStreamWaitEvent(0, evEnc, 0);
    attenc_mma_kernel<<<dim3(ATT / 128, (BATCH * PIX) / 64), 256>>>(b_enc_att);

    // join, then persistent decode loop
    cudaStreamWaitEvent(0, evJoin, 0);
    const int dyn_smem = (5120 + 2 * SWT) * (int)sizeof(__half);
    cudaFuncSetAttribute(decode_loop_kernel,
                         cudaFuncAttributeMaxDynamicSharedMemorySize, dyn_smem);
    decode_loop_kernel<<<NBLK, 256, dyn_smem>>>(b_dec_att, W_full_att, b_full_att, b_fbeta,
                                                emb, captions, cap_len,
                                                b_ih, b_hh, out);

    preds_mma_kernel<<<dim3(NPAD / 128, MTOT / 64), 256>>>(b_fc, pmask, out);
}